// round 4
// baseline (speedup 1.0000x reference)
#include <cuda_runtime.h>

#define NB   512
#define GH   30
#define GW   30
#define NN   900
#define HID  128
#define OUTD 64
#define LROWS 64
#define LNT   15   // ceil(900/64)
#define ONT   15

typedef unsigned long long ull;

// Ping-pong activation buffers (scratch; __device__ globals per allocation rules)
__device__ float g_X0[(size_t)NB * NN * HID];
__device__ float g_X1[(size_t)NB * NN * HID];

__device__ __forceinline__ float dinv_rc(int rp, int cp) {
    int d = 1 + (rp > 0) + (rp < GH - 1) + (cp > 0) + (cp < GW - 1);
    return rsqrtf((float)d);
}
__device__ __forceinline__ float f4get(const float4& v, int i) {
    return i == 0 ? v.x : i == 1 ? v.y : i == 2 ? v.z : v.w;
}
// Broadcast one float into both lanes of an f32x2 package.
__device__ __forceinline__ ull pack2(float a) {
    ull r; asm("mov.b64 %0, {%1, %1};" : "=l"(r) : "f"(a)); return r;
}
// d = a * b + d on packed f32x2 (Blackwell FFMA2; 2 FMA per instruction)
__device__ __forceinline__ void fma2(ull& d, ull a, ull b) {
    asm("fma.rn.f32x2 %0, %1, %2, %0;" : "+l"(d) : "l"(a), "l"(b));
}
__device__ __forceinline__ float2 unpack2(ull v) {
    float x, y; asm("mov.b64 {%0, %1}, %2;" : "=f"(x), "=f"(y) : "l"(v));
    return make_float2(x, y);
}

// ---------------------------------------------------------------------------
// x0 = relu(onehot(color)@Win + pr*Win[10] + pc*Win[11] + bin), Win in smem
// ---------------------------------------------------------------------------
__global__ __launch_bounds__(256) void encode_kernel(
    const int* __restrict__ grids, const float* __restrict__ Win,
    const float* __restrict__ bin)
{
    __shared__ float4 sW[12 * 32];
    __shared__ float4 sB[32];
    const int tid = threadIdx.x;
    for (int i = tid; i < 384; i += 256) sW[i] = ((const float4*)Win)[i];
    if (tid < 32) sB[tid] = ((const float4*)bin)[tid];
    __syncthreads();

    long long idx = (long long)blockIdx.x * 256 + tid;
    int cg = (int)(idx & 31);
    long long bn = idx >> 5;
    int n = (int)(bn % NN);
    int color = grids[bn];
    float pr = (float)(n / GW) * (1.0f / (GH - 1));
    float pc = (float)(n % GW) * (1.0f / (GW - 1));
    float4 wc = sW[color * 32 + cg];
    float4 wr = sW[10 * 32 + cg];
    float4 wp = sW[11 * 32 + cg];
    float4 bb = sB[cg];
    float4 o;
    o.x = fmaxf(fmaf(pc, wp.x, fmaf(pr, wr.x, wc.x + bb.x)), 0.0f);
    o.y = fmaxf(fmaf(pc, wp.y, fmaf(pr, wr.y, wc.y + bb.y)), 0.0f);
    o.z = fmaxf(fmaf(pc, wp.z, fmaf(pr, wr.z, wc.z + bb.z)), 0.0f);
    o.w = fmaxf(fmaf(pc, wp.w, fmaf(pr, wr.w, wc.w + bb.w)), 0.0f);
    ((float4*)g_X0)[idx] = o;
}

// ---------------------------------------------------------------------------
// One GCN layer, fused:  y = A_hat@x (stencil) -> z = y@Wg + bg
//                        x_new = relu(LN(z)*gamma+beta) + x
// CTA = (batch, 64-node tile), 128 threads, 8x8 register tiles, f32x2 FMA.
// Thread layout: tr = tid>>4 (8 row-groups of 8), tc = tid&15 (16 col-groups
// of 8). Lanes 0-15 of a warp share the row group -> Y loads broadcast;
// lanes 16-31 duplicate cols -> W loads dedup. smem: Ws 64KB + Ys 32KB.
// ---------------------------------------------------------------------------
__global__ __launch_bounds__(128, 2) void layer_kernel(
    int flip,
    const float* __restrict__ Wg, const float* __restrict__ bg,
    const float* __restrict__ gamma, const float* __restrict__ beta)
{
    extern __shared__ float sm[];
    float* Ws = sm;                 // [128][128]  (k-major, as in Wg)
    float* Ys = sm + HID * HID;     // [64][128]

    const float* Xin  = flip ? g_X1 : g_X0;
    float*       Xout = flip ? g_X0 : g_X1;

    const int tid  = threadIdx.x;
    const int b    = blockIdx.x / LNT;
    const int tile = blockIdx.x % LNT;
    const int base = tile * LROWS;
    const int nrows = min(LROWS, NN - base);
    const float* Xb  = Xin + (size_t)b * NN * HID;
    float*       Xob = Xout + (size_t)b * NN * HID;

    // --- stage Wg in smem (coalesced float4; 32 per thread) ---
    {
        const float4* src = (const float4*)Wg;
        float4* dst = (float4*)Ws;
        #pragma unroll
        for (int i = 0; i < 32; i++) dst[tid + 128 * i] = src[tid + 128 * i];
    }

    // --- stencil: Ys[r][:] = sum_u coef(u,v) * x[u][:]  (zero-fill tail) ---
    #pragma unroll 4
    for (int s = 0; s < 16; s++) {
        int idx = tid + 128 * s;          // r*32 + cg
        int r = idx >> 5;
        int cg = idx & 31;
        if (r < nrows) {
            int v = base + r;
            int rp = v / GW;
            int cp = v - rp * GW;
            const float4* X4 = (const float4*)Xb;
            float cv = dinv_rc(rp, cp);
            float4 xs = X4[(size_t)v * 32 + cg];
            float ax = cv * xs.x, ay = cv * xs.y, az = cv * xs.z, aw = cv * xs.w;
            if (rp > 0) {
                float cu = dinv_rc(rp - 1, cp);
                float4 t = X4[(size_t)(v - GW) * 32 + cg];
                ax = fmaf(cu, t.x, ax); ay = fmaf(cu, t.y, ay);
                az = fmaf(cu, t.z, az); aw = fmaf(cu, t.w, aw);
            }
            if (rp < GH - 1) {
                float cu = dinv_rc(rp + 1, cp);
                float4 t = X4[(size_t)(v + GW) * 32 + cg];
                ax = fmaf(cu, t.x, ax); ay = fmaf(cu, t.y, ay);
                az = fmaf(cu, t.z, az); aw = fmaf(cu, t.w, aw);
            }
            if (cp > 0) {
                float cu = dinv_rc(rp, cp - 1);
                float4 t = X4[(size_t)(v - 1) * 32 + cg];
                ax = fmaf(cu, t.x, ax); ay = fmaf(cu, t.y, ay);
                az = fmaf(cu, t.z, az); aw = fmaf(cu, t.w, aw);
            }
            if (cp < GW - 1) {
                float cu = dinv_rc(rp, cp + 1);
                float4 t = X4[(size_t)(v + 1) * 32 + cg];
                ax = fmaf(cu, t.x, ax); ay = fmaf(cu, t.y, ay);
                az = fmaf(cu, t.z, az); aw = fmaf(cu, t.w, aw);
            }
            ((float4*)Ys)[idx] = make_float4(cv * ax, cv * ay, cv * az, cv * aw);
        } else {
            ((float4*)Ys)[idx] = make_float4(0.f, 0.f, 0.f, 0.f);
        }
    }
    __syncthreads();

    // --- GEMM: z[64][128] = Ys @ Ws ; thread = 8 rows x 8 cols (4 f32x2) ---
    const int tc = tid & 15;    // cols [tc*8, tc*8+8)
    const int tr = tid >> 4;    // rows [tr*8, tr*8+8)
    ull acc[8][4];
    #pragma unroll
    for (int i = 0; i < 8; i++)
        #pragma unroll
        for (int j = 0; j < 4; j++) acc[i][j] = 0ull;

    const float* Yp = Ys + tr * 8 * HID;
    const float* Wp = Ws + tc * 8;
    #pragma unroll 2
    for (int k0 = 0; k0 < HID; k0 += 4) {
        float4 y[8];
        #pragma unroll
        for (int i = 0; i < 8; i++)
            y[i] = *(const float4*)(Yp + i * HID + k0);
        #pragma unroll
        for (int kk = 0; kk < 4; kk++) {
            const float* wrow = Wp + (k0 + kk) * HID;
            ulonglong2 w0 = *(const ulonglong2*)(wrow);
            ulonglong2 w1 = *(const ulonglong2*)(wrow + 4);
            #pragma unroll
            for (int i = 0; i < 8; i++) {
                ull yy = pack2(f4get(y[i], kk));
                fma2(acc[i][0], yy, w0.x);
                fma2(acc[i][1], yy, w0.y);
                fma2(acc[i][2], yy, w1.x);
                fma2(acc[i][3], yy, w1.y);
            }
        }
    }
    __syncthreads();   // all reads of Ys done before overwrite

    // --- z + bias -> Ys ---
    {
        float4 b0 = *(const float4*)(bg + tc * 8);
        float4 b1 = *(const float4*)(bg + tc * 8 + 4);
        #pragma unroll
        for (int i = 0; i < 8; i++) {
            float2 p0 = unpack2(acc[i][0]);
            float2 p1 = unpack2(acc[i][1]);
            float2 p2 = unpack2(acc[i][2]);
            float2 p3 = unpack2(acc[i][3]);
            float* zr = Ys + (tr * 8 + i) * HID + tc * 8;
            *(float4*)zr       = make_float4(p0.x + b0.x, p0.y + b0.y, p1.x + b0.z, p1.y + b0.w);
            *(float4*)(zr + 4) = make_float4(p2.x + b1.x, p2.y + b1.y, p3.x + b1.z, p3.y + b1.w);
        }
    }
    __syncthreads();

    // --- LayerNorm + relu + residual: warp w handles rows w*16..w*16+15 ---
    const int lane = tid & 31;
    const int warp = tid >> 5;
    float gm0 = gamma[lane], gm1 = gamma[lane + 32], gm2 = gamma[lane + 64], gm3 = gamma[lane + 96];
    float bt0 = beta[lane],  bt1 = beta[lane + 32],  bt2 = beta[lane + 64],  bt3 = beta[lane + 96];
    #pragma unroll 2
    for (int i = 0; i < 16; i++) {
        int r = warp * 16 + i;
        if (r < nrows) {  // warp-uniform
            const float* zr = Ys + r * HID;
            float v0 = zr[lane], v1 = zr[lane + 32], v2 = zr[lane + 64], v3 = zr[lane + 96];
            float s = v0 + v1 + v2 + v3;
            float q = fmaf(v0, v0, fmaf(v1, v1, fmaf(v2, v2, v3 * v3)));
            #pragma unroll
            for (int o = 16; o > 0; o >>= 1) {
                s += __shfl_xor_sync(0xffffffffu, s, o);
                q += __shfl_xor_sync(0xffffffffu, q, o);
            }
            float mean = s * (1.0f / HID);
            float var  = q * (1.0f / HID) - mean * mean;
            float rstd = rsqrtf(var + 1e-5f);
            int v = base + r;
            const float* xr = Xb + (size_t)v * HID;
            float* xo = Xob + (size_t)v * HID;
            xo[lane]      = fmaxf((v0 - mean) * rstd * gm0 + bt0, 0.0f) + xr[lane];
            xo[lane + 32] = fmaxf((v1 - mean) * rstd * gm1 + bt1, 0.0f) + xr[lane + 32];
            xo[lane + 64] = fmaxf((v2 - mean) * rstd * gm2 + bt2, 0.0f) + xr[lane + 64];
            xo[lane + 96] = fmaxf((v3 - mean) * rstd * gm3 + bt3, 0.0f) + xr[lane + 96];
        }
    }
}

// ---------------------------------------------------------------------------
// out = x @ Wout + bout  (x in g_X0 after 4 layers)
// CTA = (batch, 64-node tile), 256 threads, 4x4 register tiles, f32x2 FMA.
// ---------------------------------------------------------------------------
__global__ __launch_bounds__(256) void out_kernel(
    const float* __restrict__ Wout, const float* __restrict__ bout,
    float* __restrict__ out)
{
    extern __shared__ float sm[];
    float* Ws = sm;                   // [128][64]
    float* Xs = sm + HID * OUTD;      // [64][128]
    const int tid  = threadIdx.x;
    const int b    = blockIdx.x / ONT;
    const int tile = blockIdx.x % ONT;
    const int base = tile * LROWS;
    const int nrows = min(LROWS, NN - base);
    const float* Xb = g_X0 + (size_t)b * NN * HID;

    {
        const float4* src = (const float4*)Wout;
        float4* dst = (float4*)Ws;
        #pragma unroll
        for (int i = 0; i < 8; i++) dst[tid + 256 * i] = src[tid + 256 * i];
    }
    #pragma unroll
    for (int s = 0; s < 8; s++) {
        int idx = tid + 256 * s;
        int r = idx >> 5, cg = idx & 31;
        if (r < nrows)
            ((float4*)Xs)[idx] = ((const float4*)Xb)[(size_t)(base + r) * 32 + cg];
        else
            ((float4*)Xs)[idx] = make_float4(0.f, 0.f, 0.f, 0.f);
    }
    __syncthreads();

    const int cg = tid & 15;
    const int rg = tid >> 4;
    ull acc[4][2];
    #pragma unroll
    for (int i = 0; i < 4; i++) { acc[i][0] = 0ull; acc[i][1] = 0ull; }

    const float* Xp = Xs + rg * 4 * HID;
    #pragma unroll 2
    for (int k0 = 0; k0 < HID; k0 += 4) {
        float4 x[4];
        #pragma unroll
        for (int i = 0; i < 4; i++)
            x[i] = *(const float4*)(Xp + i * HID + k0);
        #pragma unroll
        for (int kk = 0; kk < 4; kk++) {
            ulonglong2 w = *(const ulonglong2*)(Ws + (k0 + kk) * OUTD + cg * 4);
            #pragma unroll
            for (int i = 0; i < 4; i++) {
                ull xx = pack2(f4get(x[i], kk));
                fma2(acc[i][0], xx, w.x);
                fma2(acc[i][1], xx, w.y);
            }
        }
    }

    float4 bo = ((const float4*)bout)[cg];
    #pragma unroll
    for (int i = 0; i < 4; i++) {
        int r = rg * 4 + i;
        if (r < nrows) {
            float2 lo = unpack2(acc[i][0]);
            float2 hi = unpack2(acc[i][1]);
            float4 v = make_float4(lo.x + bo.x, lo.y + bo.y, hi.x + bo.z, hi.y + bo.w);
            *(float4*)(out + ((size_t)b * NN + base + r) * OUTD + cg * 4) = v;
        }
    }
}

// ---------------------------------------------------------------------------
extern "C" void kernel_launch(void* const* d_in, const int* in_sizes, int n_in,
                              void* d_out, int out_size) {
    const int*   grids = (const int*)d_in[0];
    // d_in[1] = edge_index: fixed 30x30 4-connected grid; computed analytically.
    const float* Win   = (const float*)d_in[2];
    const float* bin   = (const float*)d_in[3];
    const float* Wg    = (const float*)d_in[4];
    const float* bg    = (const float*)d_in[5];
    const float* gamma = (const float*)d_in[6];
    const float* beta  = (const float*)d_in[7];
    const float* Wout  = (const float*)d_in[8];
    const float* bout  = (const float*)d_in[9];
    float* out = (float*)d_out;
    (void)in_sizes; (void)n_in; (void)out_size;

    const int layer_smem = (HID * HID + LROWS * HID) * 4;   // 98304
    const int out_smem   = (HID * OUTD + LROWS * HID) * 4;  // 65536
    cudaFuncSetAttribute((const void*)layer_kernel,
                         cudaFuncAttributeMaxDynamicSharedMemorySize, layer_smem);
    cudaFuncSetAttribute((const void*)out_kernel,
                         cudaFuncAttributeMaxDynamicSharedMemorySize, out_smem);

    encode_kernel<<<(NB * NN * 32) / 256, 256>>>(grids, Win, bin);
    for (int i = 0; i < 4; i++) {
        layer_kernel<<<NB * LNT, 128, layer_smem>>>(
            i & 1, Wg + (size_t)i * HID * HID, bg + i * HID,
            gamma + i * HID, beta + i * HID);
    }
    out_kernel<<<NB * ONT, 256, out_smem>>>(Wout, bout, out);
}

// round 5
// speedup vs baseline: 1.2674x; 1.2674x over previous
#include <cuda_runtime.h>
#include <cuda_bf16.h>
#include <cstdint>

#define NB   512
#define GH   30
#define GW   30
#define NN   900
#define HID  128
#define OUTD 64
#define LROWS 64
#define ONT   15

typedef unsigned long long ull;

// Ping-pong activation buffers (scratch; __device__ globals per allocation rules)
__device__ float g_X0[(size_t)NB * NN * HID];
__device__ float g_X1[(size_t)NB * NN * HID];

// smem byte offsets for layer_mma_kernel (bf16 matrices, 136-elem = 272B rows)
#define PITCHB 272
#define OFF_BHI 0
#define OFF_BLO 34816
#define OFF_AHI 69632
#define OFF_ALO 104448
#define OFF_PAR 139264
#define SMEM_MMA 140800

__device__ __forceinline__ uint32_t smem_u32(const void* p) {
    uint32_t a;
    asm("{ .reg .u64 t; cvta.to.shared.u64 t, %1; cvt.u32.u64 %0, t; }" : "=r"(a) : "l"(p));
    return a;
}
__device__ __forceinline__ float dinv_rc(int rp, int cp) {
    int d = 1 + (rp > 0) + (rp < GH - 1) + (cp > 0) + (cp < GW - 1);
    return rsqrtf((float)d);
}
__device__ __forceinline__ float f4get(const float4& v, int i) {
    return i == 0 ? v.x : i == 1 ? v.y : i == 2 ? v.z : v.w;
}
// f32x2 helpers (out_kernel)
__device__ __forceinline__ ull pack2(float a) {
    ull r; asm("mov.b64 %0, {%1, %1};" : "=l"(r) : "f"(a)); return r;
}
__device__ __forceinline__ void fma2(ull& d, ull a, ull b) {
    asm("fma.rn.f32x2 %0, %1, %2, %0;" : "+l"(d) : "l"(a), "l"(b));
}
__device__ __forceinline__ float2 unpack2(ull v) {
    float x, y; asm("mov.b64 {%0, %1}, %2;" : "=f"(x), "=f"(y) : "l"(v));
    return make_float2(x, y);
}
// bf16 hi/lo split of two floats packed into two b32 words (elem c in low half)
__device__ __forceinline__ void split2(float a, float b, uint32_t& hi, uint32_t& lo) {
    __nv_bfloat16 ha = __float2bfloat16_rn(a), hb = __float2bfloat16_rn(b);
    __nv_bfloat16 la = __float2bfloat16_rn(a - __bfloat162float(ha));
    __nv_bfloat16 lb = __float2bfloat16_rn(b - __bfloat162float(hb));
    hi = (uint32_t)*(uint16_t*)&ha | ((uint32_t)*(uint16_t*)&hb << 16);
    lo = (uint32_t)*(uint16_t*)&la | ((uint32_t)*(uint16_t*)&lb << 16);
}
__device__ __forceinline__ void ldsm4(uint32_t addr, uint32_t& r0, uint32_t& r1,
                                      uint32_t& r2, uint32_t& r3) {
    asm volatile("ldmatrix.sync.aligned.m8n8.x4.shared.b16 {%0,%1,%2,%3}, [%4];"
                 : "=r"(r0), "=r"(r1), "=r"(r2), "=r"(r3) : "r"(addr));
}
__device__ __forceinline__ void mma_bf16(float* d, const uint32_t* a, const uint32_t* b) {
    asm volatile("mma.sync.aligned.m16n8k16.row.col.f32.bf16.bf16.f32 "
                 "{%0,%1,%2,%3}, {%4,%5,%6,%7}, {%8,%9}, {%0,%1,%2,%3};"
                 : "+f"(d[0]), "+f"(d[1]), "+f"(d[2]), "+f"(d[3])
                 : "r"(a[0]), "r"(a[1]), "r"(a[2]), "r"(a[3]), "r"(b[0]), "r"(b[1]));
}

// ---------------------------------------------------------------------------
// x0 = relu(onehot(color)@Win + pr*Win[10] + pc*Win[11] + bin)
// ---------------------------------------------------------------------------
__global__ __launch_bounds__(256) void encode_kernel(
    const int* __restrict__ grids, const float* __restrict__ Win,
    const float* __restrict__ bin)
{
    __shared__ float4 sW[12 * 32];
    __shared__ float4 sB[32];
    const int tid = threadIdx.x;
    for (int i = tid; i < 384; i += 256) sW[i] = ((const float4*)Win)[i];
    if (tid < 32) sB[tid] = ((const float4*)bin)[tid];
    __syncthreads();

    long long idx = (long long)blockIdx.x * 256 + tid;
    int cg = (int)(idx & 31);
    long long bn = idx >> 5;
    int n = (int)(bn % NN);
    int color = grids[bn];
    float pr = (float)(n / GW) * (1.0f / (GH - 1));
    float pc = (float)(n % GW) * (1.0f / (GW - 1));
    float4 wc = sW[color * 32 + cg];
    float4 wr = sW[10 * 32 + cg];
    float4 wp = sW[11 * 32 + cg];
    float4 bb = sB[cg];
    float4 o;
    o.x = fmaxf(fmaf(pc, wp.x, fmaf(pr, wr.x, wc.x + bb.x)), 0.0f);
    o.y = fmaxf(fmaf(pc, wp.y, fmaf(pr, wr.y, wc.y + bb.y)), 0.0f);
    o.z = fmaxf(fmaf(pc, wp.z, fmaf(pr, wr.z, wc.z + bb.z)), 0.0f);
    o.w = fmaxf(fmaf(pc, wp.w, fmaf(pr, wr.w, wc.w + bb.w)), 0.0f);
    ((float4*)g_X0)[idx] = o;
}

// ---------------------------------------------------------------------------
// Tensor-core (HMMA) GCN layer with bf16 hi/lo split (3 passes).
// CTA = (batch, half), 256 threads; loops 4 tiles of M=128 rows.
// Warp w owns rows [w*16, w*16+16) x all 128 cols -> LN fully in registers.
// ---------------------------------------------------------------------------
__global__ __launch_bounds__(256, 1) void layer_mma_kernel(
    int flip,
    const float* __restrict__ Wg, const float* __restrict__ bg,
    const float* __restrict__ gamma, const float* __restrict__ beta)
{
    extern __shared__ char smem[];
    const uint32_t sb = smem_u32(smem);
    float* sPar = (float*)(smem + OFF_PAR);   // bg[128], gamma[128], beta[128]

    const int tid = threadIdx.x, warp = tid >> 5, lane = tid & 31;
    const int b = blockIdx.x >> 1, half = blockIdx.x & 1;

    const float* Xin  = flip ? g_X1 : g_X0;
    float*       Xout = flip ? g_X0 : g_X1;
    const float* Xb  = Xin  + (size_t)b * NN * HID;
    float*       Xob = Xout + (size_t)b * NN * HID;

    // --- stage LN params ---
    if (tid < 128) {
        sPar[tid]       = bg[tid];
        sPar[128 + tid] = gamma[tid];
        sPar[256 + tid] = beta[tid];
    }

    // --- stage W transposed + bf16-split: Bhi/Blo[n][k], 272B rows ---
    {
        const float4* W4 = (const float4*)Wg;
        #pragma unroll
        for (int i = 0; i < 16; i++) {
            int j = tid + 256 * i;          // float4 index over [128k][32]
            int k = j >> 5, n4 = (j & 31) * 4;
            float4 v = W4[j];
            #pragma unroll
            for (int u = 0; u < 4; u++) {
                float f = f4get(v, u);
                __nv_bfloat16 h = __float2bfloat16_rn(f);
                __nv_bfloat16 l = __float2bfloat16_rn(f - __bfloat162float(h));
                uint32_t o = (uint32_t)(n4 + u) * PITCHB + (uint32_t)k * 2;
                *(__nv_bfloat16*)(smem + OFF_BHI + o) = h;
                *(__nv_bfloat16*)(smem + OFF_BLO + o) = l;
            }
        }
    }
    __syncthreads();

    // lane-dependent ldmatrix base offsets
    const int m0 = warp * 16;
    const uint32_t aRow = (uint32_t)(m0 + (lane & 15)) * PITCHB + ((lane >> 4) & 1) * 16;
    const uint32_t aHiB = sb + OFF_AHI + aRow;
    const uint32_t aLoB = sb + OFF_ALO + aRow;
    uint32_t bOff[8];
    #pragma unroll
    for (int p = 0; p < 8; p++) {
        int n = p * 16 + (lane & 7) + ((lane >> 4) & 1) * 8;
        bOff[p] = (uint32_t)n * PITCHB + ((lane >> 3) & 1) * 16;
    }
    const int g = lane >> 2, tig = lane & 3;

    for (int t4 = 0; t4 < 4; t4++) {
        const int tile = half * 4 + t4;
        const int base = tile * 128;
        const int nrows = min(128, NN - base);

        // --- stencil + bf16 split -> A_hi/A_lo (zero-fill tail rows) ---
        #pragma unroll 4
        for (int s = 0; s < 16; s++) {
            int idx = tid + 256 * s;
            int r = idx >> 5, cg = idx & 31;
            uint32_t off = (uint32_t)r * PITCHB + (uint32_t)cg * 8;
            if (r < nrows) {
                int v = base + r;
                int rp = v / GW;
                int cp = v - rp * GW;
                const float4* X4 = (const float4*)Xb;
                float cv = dinv_rc(rp, cp);
                float4 xs = X4[(size_t)v * 32 + cg];
                float ax = cv * xs.x, ay = cv * xs.y, az = cv * xs.z, aw = cv * xs.w;
                if (rp > 0) {
                    float cu = dinv_rc(rp - 1, cp);
                    float4 t = X4[(size_t)(v - GW) * 32 + cg];
                    ax = fmaf(cu, t.x, ax); ay = fmaf(cu, t.y, ay);
                    az = fmaf(cu, t.z, az); aw = fmaf(cu, t.w, aw);
                }
                if (rp < GH - 1) {
                    float cu = dinv_rc(rp + 1, cp);
                    float4 t = X4[(size_t)(v + GW) * 32 + cg];
                    ax = fmaf(cu, t.x, ax); ay = fmaf(cu, t.y, ay);
                    az = fmaf(cu, t.z, az); aw = fmaf(cu, t.w, aw);
                }
                if (cp > 0) {
                    float cu = dinv_rc(rp, cp - 1);
                    float4 t = X4[(size_t)(v - 1) * 32 + cg];
                    ax = fmaf(cu, t.x, ax); ay = fmaf(cu, t.y, ay);
                    az = fmaf(cu, t.z, az); aw = fmaf(cu, t.w, aw);
                }
                if (cp < GW - 1) {
                    float cu = dinv_rc(rp, cp + 1);
                    float4 t = X4[(size_t)(v + 1) * 32 + cg];
                    ax = fmaf(cu, t.x, ax); ay = fmaf(cu, t.y, ay);
                    az = fmaf(cu, t.z, az); aw = fmaf(cu, t.w, aw);
                }
                ax *= cv; ay *= cv; az *= cv; aw *= cv;
                uint32_t h01, l01, h23, l23;
                split2(ax, ay, h01, l01);
                split2(az, aw, h23, l23);
                *(uint2*)(smem + OFF_AHI + off) = make_uint2(h01, h23);
                *(uint2*)(smem + OFF_ALO + off) = make_uint2(l01, l23);
            } else {
                *(uint2*)(smem + OFF_AHI + off) = make_uint2(0u, 0u);
                *(uint2*)(smem + OFF_ALO + off) = make_uint2(0u, 0u);
            }
        }
        __syncthreads();

        // --- MMA mainloop: D = Ahi@Bhi' + Alo@Bhi' + Ahi@Blo' ---
        float acc[16][4];
        #pragma unroll
        for (int nb = 0; nb < 16; nb++)
            #pragma unroll
            for (int j = 0; j < 4; j++) acc[nb][j] = 0.0f;

        #pragma unroll
        for (int ks = 0; ks < 8; ks++) {
            const uint32_t kb = (uint32_t)ks * 32;
            uint32_t ahi[4], alo[4];
            ldsm4(aHiB + kb, ahi[0], ahi[1], ahi[2], ahi[3]);
            ldsm4(aLoB + kb, alo[0], alo[1], alo[2], alo[3]);
            uint32_t bh[16][2], bl[16][2];
            #pragma unroll
            for (int p = 0; p < 8; p++) {
                ldsm4(sb + OFF_BHI + bOff[p] + kb,
                      bh[2*p][0], bh[2*p][1], bh[2*p+1][0], bh[2*p+1][1]);
                ldsm4(sb + OFF_BLO + bOff[p] + kb,
                      bl[2*p][0], bl[2*p][1], bl[2*p+1][0], bl[2*p+1][1]);
            }
            #pragma unroll
            for (int nb = 0; nb < 16; nb++) {
                mma_bf16(acc[nb], ahi, bh[nb]);
                mma_bf16(acc[nb], alo, bh[nb]);
                mma_bf16(acc[nb], ahi, bl[nb]);
            }
        }
        __syncthreads();   // A/B reads done before next tile overwrites A

        // --- epilogue: bias + LN + relu + residual (in registers) ---
        #pragma unroll
        for (int h = 0; h < 2; h++) {
            int row = m0 + g + 8 * h;
            bool ok = (row < nrows);   // quad-uniform
            float vv[16][2];
            float s = 0.0f, q = 0.0f;
            #pragma unroll
            for (int nb = 0; nb < 16; nb++) {
                float2 bb = *(float2*)(sPar + nb * 8 + tig * 2);
                float v0 = acc[nb][2 * h]     + bb.x;
                float v1 = acc[nb][2 * h + 1] + bb.y;
                vv[nb][0] = v0; vv[nb][1] = v1;
                s += v0 + v1;
                q = fmaf(v0, v0, fmaf(v1, v1, q));
            }
            s += __shfl_xor_sync(0xffffffffu, s, 1);
            s += __shfl_xor_sync(0xffffffffu, s, 2);
            q += __shfl_xor_sync(0xffffffffu, q, 1);
            q += __shfl_xor_sync(0xffffffffu, q, 2);
            float mean = s * (1.0f / HID);
            float var  = q * (1.0f / HID) - mean * mean;
            float rstd = rsqrtf(var + 1e-5f);
            if (ok) {
                int v = base + row;
                const float* xr = Xb + (size_t)v * HID;
                float*       xo = Xob + (size_t)v * HID;
                #pragma unroll
                for (int nb = 0; nb < 16; nb++) {
                    int c = nb * 8 + tig * 2;
                    float2 gm = *(float2*)(sPar + 128 + c);
                    float2 bt = *(float2*)(sPar + 256 + c);
                    float2 xv = *(const float2*)(xr + c);
                    float o0 = fmaxf((vv[nb][0] - mean) * rstd * gm.x + bt.x, 0.0f) + xv.x;
                    float o1 = fmaxf((vv[nb][1] - mean) * rstd * gm.y + bt.y, 0.0f) + xv.y;
                    *(float2*)(xo + c) = make_float2(o0, o1);
                }
            }
        }
        __syncthreads();
    }
}

// ---------------------------------------------------------------------------
// out = x @ Wout + bout  (x in g_X0 after 4 layers); f32x2 CUDA-core GEMM
// ---------------------------------------------------------------------------
__global__ __launch_bounds__(256) void out_kernel(
    const float* __restrict__ Wout, const float* __restrict__ bout,
    float* __restrict__ out)
{
    extern __shared__ float sm[];
    float* Ws = sm;                   // [128][64]
    float* Xs = sm + HID * OUTD;      // [64][128]
    const int tid  = threadIdx.x;
    const int b    = blockIdx.x / ONT;
    const int tile = blockIdx.x % ONT;
    const int base = tile * LROWS;
    const int nrows = min(LROWS, NN - base);
    const float* Xb = g_X0 + (size_t)b * NN * HID;

    {
        const float4* src = (const float4*)Wout;
        float4* dst = (float4*)Ws;
        #pragma unroll
        for (int i = 0; i < 8; i++) dst[tid + 256 * i] = src[tid + 256 * i];
    }
    #pragma unroll
    for (int s = 0; s < 8; s++) {
        int idx = tid + 256 * s;
        int r = idx >> 5, cg = idx & 31;
        if (r < nrows)
            ((float4*)Xs)[idx] = ((const float4*)Xb)[(size_t)(base + r) * 32 + cg];
        else
            ((float4*)Xs)[idx] = make_float4(0.f, 0.f, 0.f, 0.f);
    }
    __syncthreads();

    const int cg = tid & 15;
    const int rg = tid >> 4;
    ull acc[4][2];
    #pragma unroll
    for (int i = 0; i < 4; i++) { acc[i][0] = 0ull; acc[i][1] = 0ull; }

    const float* Xp = Xs + rg * 4 * HID;
    #pragma unroll 2
    for (int k0 = 0; k0 < HID; k0 += 4) {
        float4 x[4];
        #pragma unroll
        for (int i = 0; i < 4; i++)
            x[i] = *(const float4*)(Xp + i * HID + k0);
        #pragma unroll
        for (int kk = 0; kk < 4; kk++) {
            ulonglong2 w = *(const ulonglong2*)(Ws + (k0 + kk) * OUTD + cg * 4);
            #pragma unroll
            for (int i = 0; i < 4; i++) {
                ull xx = pack2(f4get(x[i], kk));
                fma2(acc[i][0], xx, w.x);
                fma2(acc[i][1], xx, w.y);
            }
        }
    }

    float4 bo = ((const float4*)bout)[cg];
    #pragma unroll
    for (int i = 0; i < 4; i++) {
        int r = rg * 4 + i;
        if (r < nrows) {
            float2 lo = unpack2(acc[i][0]);
            float2 hi = unpack2(acc[i][1]);
            float4 v = make_float4(lo.x + bo.x, lo.y + bo.y, hi.x + bo.z, hi.y + bo.w);
            *(float4*)(out + ((size_t)b * NN + base + r) * OUTD + cg * 4) = v;
        }
    }
}

// ---------------------------------------------------------------------------
extern "C" void kernel_launch(void* const* d_in, const int* in_sizes, int n_in,
                              void* d_out, int out_size) {
    const int*   grids = (const int*)d_in[0];
    // d_in[1] = edge_index: fixed 30x30 4-connected grid; computed analytically.
    const float* Win   = (const float*)d_in[2];
    const float* bin   = (const float*)d_in[3];
    const float* Wg    = (const float*)d_in[4];
    const float* bg    = (const float*)d_in[5];
    const float* gamma = (const float*)d_in[6];
    const float* beta  = (const float*)d_in[7];
    const float* Wout  = (const float*)d_in[8];
    const float* bout  = (const float*)d_in[9];
    float* out = (float*)d_out;
    (void)in_sizes; (void)n_in; (void)out_size;

    const int out_smem = (HID * OUTD + LROWS * HID) * 4;  // 65536
    cudaFuncSetAttribute((const void*)layer_mma_kernel,
                         cudaFuncAttributeMaxDynamicSharedMemorySize, SMEM_MMA);
    cudaFuncSetAttribute((const void*)out_kernel,
                         cudaFuncAttributeMaxDynamicSharedMemorySize, out_smem);

    encode_kernel<<<(NB * NN * 32) / 256, 256>>>(grids, Win, bin);
    for (int i = 0; i < 4; i++) {
        layer_mma_kernel<<<NB * 2, 256, SMEM_MMA>>>(
            i & 1, Wg + (size_t)i * HID * HID, bg + i * HID,
            gamma + i * HID, beta + i * HID);
    }
    out_kernel<<<NB * ONT, 256, out_smem>>>(Wout, bout, out);
}

// round 6
// speedup vs baseline: 1.7186x; 1.3561x over previous
#include <cuda_runtime.h>
#include <cuda_bf16.h>
#include <cstdint>

#define NB   512
#define GH   30
#define GW   30
#define NN   900
#define HID  128
#define OUTD 64
#define LROWS 64
#define ONT   15

typedef unsigned long long ull;

// Ping-pong activation buffers (scratch; __device__ globals per allocation rules)
__device__ float g_X0[(size_t)NB * NN * HID];
__device__ float g_X1[(size_t)NB * NN * HID];

// smem byte offsets for layer_mma_kernel (bf16 matrices, 136-elem = 272B rows)
#define PITCHB 272
#define OFF_BHI 0
#define OFF_BLO 34816
#define OFF_AHI 69632
#define OFF_ALO 87040
#define OFF_PAR 104448
#define OFF_RED 105984
#define SMEM_MMA 107008

__device__ __forceinline__ uint32_t smem_u32(const void* p) {
    uint32_t a;
    asm("{ .reg .u64 t; cvta.to.shared.u64 t, %1; cvt.u32.u64 %0, t; }" : "=r"(a) : "l"(p));
    return a;
}
__device__ __forceinline__ float dinv_rc(int rp, int cp) {
    int d = 1 + (rp > 0) + (rp < GH - 1) + (cp > 0) + (cp < GW - 1);
    return rsqrtf((float)d);
}
__device__ __forceinline__ float f4get(const float4& v, int i) {
    return i == 0 ? v.x : i == 1 ? v.y : i == 2 ? v.z : v.w;
}
// f32x2 helpers (out_kernel)
__device__ __forceinline__ ull pack2(float a) {
    ull r; asm("mov.b64 %0, {%1, %1};" : "=l"(r) : "f"(a)); return r;
}
__device__ __forceinline__ void fma2(ull& d, ull a, ull b) {
    asm("fma.rn.f32x2 %0, %1, %2, %0;" : "+l"(d) : "l"(a), "l"(b));
}
__device__ __forceinline__ float2 unpack2(ull v) {
    float x, y; asm("mov.b64 {%0, %1}, %2;" : "=f"(x), "=f"(y) : "l"(v));
    return make_float2(x, y);
}
// bf16 hi/lo split of two floats packed into two b32 words (elem a in low half)
__device__ __forceinline__ void split2(float a, float b, uint32_t& hi, uint32_t& lo) {
    __nv_bfloat16 ha = __float2bfloat16_rn(a), hb = __float2bfloat16_rn(b);
    __nv_bfloat16 la = __float2bfloat16_rn(a - __bfloat162float(ha));
    __nv_bfloat16 lb = __float2bfloat16_rn(b - __bfloat162float(hb));
    hi = (uint32_t)*(uint16_t*)&ha | ((uint32_t)*(uint16_t*)&hb << 16);
    lo = (uint32_t)*(uint16_t*)&la | ((uint32_t)*(uint16_t*)&lb << 16);
}
__device__ __forceinline__ void ldsm4(uint32_t addr, uint32_t& r0, uint32_t& r1,
                                      uint32_t& r2, uint32_t& r3) {
    asm volatile("ldmatrix.sync.aligned.m8n8.x4.shared.b16 {%0,%1,%2,%3}, [%4];"
                 : "=r"(r0), "=r"(r1), "=r"(r2), "=r"(r3) : "r"(addr));
}
__device__ __forceinline__ void mma_bf16(float* d, const uint32_t* a, const uint32_t* b) {
    asm volatile("mma.sync.aligned.m16n8k16.row.col.f32.bf16.bf16.f32 "
                 "{%0,%1,%2,%3}, {%4,%5,%6,%7}, {%8,%9}, {%0,%1,%2,%3};"
                 : "+f"(d[0]), "+f"(d[1]), "+f"(d[2]), "+f"(d[3])
                 : "r"(a[0]), "r"(a[1]), "r"(a[2]), "r"(a[3]), "r"(b[0]), "r"(b[1]));
}

// ---------------------------------------------------------------------------
// x0 = relu(onehot(color)@Win + pr*Win[10] + pc*Win[11] + bin)
// ---------------------------------------------------------------------------
__global__ __launch_bounds__(256) void encode_kernel(
    const int* __restrict__ grids, const float* __restrict__ Win,
    const float* __restrict__ bin)
{
    __shared__ float4 sW[12 * 32];
    __shared__ float4 sB[32];
    const int tid = threadIdx.x;
    for (int i = tid; i < 384; i += 256) sW[i] = ((const float4*)Win)[i];
    if (tid < 32) sB[tid] = ((const float4*)bin)[tid];
    __syncthreads();

    long long idx = (long long)blockIdx.x * 256 + tid;
    int cg = (int)(idx & 31);
    long long bn = idx >> 5;
    int n = (int)(bn % NN);
    int color = grids[bn];
    float pr = (float)(n / GW) * (1.0f / (GH - 1));
    float pc = (float)(n % GW) * (1.0f / (GW - 1));
    float4 wc = sW[color * 32 + cg];
    float4 wr = sW[10 * 32 + cg];
    float4 wp = sW[11 * 32 + cg];
    float4 bb = sB[cg];
    float4 o;
    o.x = fmaxf(fmaf(pc, wp.x, fmaf(pr, wr.x, wc.x + bb.x)), 0.0f);
    o.y = fmaxf(fmaf(pc, wp.y, fmaf(pr, wr.y, wc.y + bb.y)), 0.0f);
    o.z = fmaxf(fmaf(pc, wp.z, fmaf(pr, wr.z, wc.z + bb.z)), 0.0f);
    o.w = fmaxf(fmaf(pc, wp.w, fmaf(pr, wr.w, wc.w + bb.w)), 0.0f);
    ((float4*)g_X0)[idx] = o;
}

// ---------------------------------------------------------------------------
// Tensor-core (HMMA) GCN layer, bf16 hi/lo split (3 passes), M=64 tiles.
// CTA = (batch, half), 256 threads, 2 CTAs/SM; loops 8 tiles of 64 rows.
// Warp (mw,nw): mw=warp>>1 owns rows mw*16+[0,16); nw=warp&1 owns cols
// nw*64+[0,64). LayerNorm partials exchanged across the two N-warps via smem.
// ---------------------------------------------------------------------------
__global__ __launch_bounds__(256, 2) void layer_mma_kernel(
    int flip,
    const float* __restrict__ Wg, const float* __restrict__ bg,
    const float* __restrict__ gamma, const float* __restrict__ beta)
{
    extern __shared__ char smem[];
    const uint32_t sb = smem_u32(smem);
    float* sPar = (float*)(smem + OFF_PAR);   // bg[128], gamma[128], beta[128]
    float* sS   = (float*)(smem + OFF_RED);   // [64][2] sum partials
    float* sQ   = sS + 128;                   // [64][2] sumsq partials

    const int tid = threadIdx.x, warp = tid >> 5, lane = tid & 31;
    const int mw = warp >> 1, nw = warp & 1;
    const int b = blockIdx.x >> 1, half = blockIdx.x & 1;
    const int rowbase0 = half * 450;

    const float* Xin  = flip ? g_X1 : g_X0;
    float*       Xout = flip ? g_X0 : g_X1;
    const float* Xb  = Xin  + (size_t)b * NN * HID;
    float*       Xob = Xout + (size_t)b * NN * HID;

    // --- stage LN params ---
    if (tid < 128) {
        sPar[tid]       = bg[tid];
        sPar[128 + tid] = gamma[tid];
        sPar[256 + tid] = beta[tid];
    }

    // --- stage W transposed + bf16-split: Bhi/Blo[n][k], 272B rows ---
    {
        const float4* W4 = (const float4*)Wg;
        #pragma unroll
        for (int i = 0; i < 16; i++) {
            int j = tid + 256 * i;          // float4 index over [128k][32]
            int k = j >> 5, n4 = (j & 31) * 4;
            float4 v = W4[j];
            #pragma unroll
            for (int u = 0; u < 4; u++) {
                float f = f4get(v, u);
                __nv_bfloat16 h = __float2bfloat16_rn(f);
                __nv_bfloat16 l = __float2bfloat16_rn(f - __bfloat162float(h));
                uint32_t o = (uint32_t)(n4 + u) * PITCHB + (uint32_t)k * 2;
                *(__nv_bfloat16*)(smem + OFF_BHI + o) = h;
                *(__nv_bfloat16*)(smem + OFF_BLO + o) = l;
            }
        }
    }
    __syncthreads();

    // lane-dependent ldmatrix base offsets
    const uint32_t aRow = (uint32_t)(mw * 16 + (lane & 15)) * PITCHB
                        + ((lane >> 4) & 1) * 16;
    const uint32_t aHiB = sb + OFF_AHI + aRow;
    const uint32_t aLoB = sb + OFF_ALO + aRow;
    uint32_t bOff[4];
    #pragma unroll
    for (int p = 0; p < 4; p++) {
        int n = nw * 64 + p * 16 + (lane & 7) + ((lane >> 4) & 1) * 8;
        bOff[p] = (uint32_t)n * PITCHB + ((lane >> 3) & 1) * 16;
    }
    const int g = lane >> 2, tig = lane & 3;

    for (int t = 0; t < 8; t++) {
        const int base = rowbase0 + t * 64;
        const int nrows = min(64, 450 - t * 64);

        // --- stencil + bf16 split -> A_hi/A_lo (zero-fill tail rows) ---
        #pragma unroll 4
        for (int s = 0; s < 8; s++) {
            int idx = tid + 256 * s;
            int r = idx >> 5, cg = idx & 31;
            uint32_t off = (uint32_t)r * PITCHB + (uint32_t)cg * 8;
            if (r < nrows) {
                int v = base + r;
                int rp = v / GW;
                int cp = v - rp * GW;
                const float4* X4 = (const float4*)Xb;
                float cv = dinv_rc(rp, cp);
                float4 xs = X4[(size_t)v * 32 + cg];
                float ax = cv * xs.x, ay = cv * xs.y, az = cv * xs.z, aw = cv * xs.w;
                if (rp > 0) {
                    float cu = dinv_rc(rp - 1, cp);
                    float4 q = X4[(size_t)(v - GW) * 32 + cg];
                    ax = fmaf(cu, q.x, ax); ay = fmaf(cu, q.y, ay);
                    az = fmaf(cu, q.z, az); aw = fmaf(cu, q.w, aw);
                }
                if (rp < GH - 1) {
                    float cu = dinv_rc(rp + 1, cp);
                    float4 q = X4[(size_t)(v + GW) * 32 + cg];
                    ax = fmaf(cu, q.x, ax); ay = fmaf(cu, q.y, ay);
                    az = fmaf(cu, q.z, az); aw = fmaf(cu, q.w, aw);
                }
                if (cp > 0) {
                    float cu = dinv_rc(rp, cp - 1);
                    float4 q = X4[(size_t)(v - 1) * 32 + cg];
                    ax = fmaf(cu, q.x, ax); ay = fmaf(cu, q.y, ay);
                    az = fmaf(cu, q.z, az); aw = fmaf(cu, q.w, aw);
                }
                if (cp < GW - 1) {
                    float cu = dinv_rc(rp, cp + 1);
                    float4 q = X4[(size_t)(v + 1) * 32 + cg];
                    ax = fmaf(cu, q.x, ax); ay = fmaf(cu, q.y, ay);
                    az = fmaf(cu, q.z, az); aw = fmaf(cu, q.w, aw);
                }
                ax *= cv; ay *= cv; az *= cv; aw *= cv;
                uint32_t h01, l01, h23, l23;
                split2(ax, ay, h01, l01);
                split2(az, aw, h23, l23);
                *(uint2*)(smem + OFF_AHI + off) = make_uint2(h01, h23);
                *(uint2*)(smem + OFF_ALO + off) = make_uint2(l01, l23);
            } else {
                *(uint2*)(smem + OFF_AHI + off) = make_uint2(0u, 0u);
                *(uint2*)(smem + OFF_ALO + off) = make_uint2(0u, 0u);
            }
        }
        __syncthreads();

        // --- MMA mainloop: D = Ahi@Bhi' + Alo@Bhi' + Ahi@Blo' ---
        float acc[8][4];
        #pragma unroll
        for (int nb = 0; nb < 8; nb++)
            #pragma unroll
            for (int j = 0; j < 4; j++) acc[nb][j] = 0.0f;

        #pragma unroll
        for (int ks = 0; ks < 8; ks++) {
            const uint32_t kb = (uint32_t)ks * 32;
            uint32_t ahi[4], alo[4];
            ldsm4(aHiB + kb, ahi[0], ahi[1], ahi[2], ahi[3]);
            ldsm4(aLoB + kb, alo[0], alo[1], alo[2], alo[3]);
            uint32_t bh[8][2], bl[8][2];
            #pragma unroll
            for (int p = 0; p < 4; p++) {
                ldsm4(sb + OFF_BHI + bOff[p] + kb,
                      bh[2*p][0], bh[2*p][1], bh[2*p+1][0], bh[2*p+1][1]);
                ldsm4(sb + OFF_BLO + bOff[p] + kb,
                      bl[2*p][0], bl[2*p][1], bl[2*p+1][0], bl[2*p+1][1]);
            }
            #pragma unroll
            for (int nb = 0; nb < 8; nb++) {
                mma_bf16(acc[nb], ahi, bh[nb]);
                mma_bf16(acc[nb], alo, bh[nb]);
                mma_bf16(acc[nb], ahi, bl[nb]);
            }
        }

        // --- epilogue: bias add (in place), LN partials, cross-warp reduce ---
        #pragma unroll
        for (int h = 0; h < 2; h++) {
            int row = mw * 16 + g + 8 * h;
            float s = 0.0f, q = 0.0f;
            #pragma unroll
            for (int nb = 0; nb < 8; nb++) {
                float2 bb = *(float2*)(sPar + nw * 64 + nb * 8 + tig * 2);
                float v0 = acc[nb][2 * h]     + bb.x;
                float v1 = acc[nb][2 * h + 1] + bb.y;
                acc[nb][2 * h] = v0; acc[nb][2 * h + 1] = v1;
                s += v0 + v1;
                q = fmaf(v0, v0, fmaf(v1, v1, q));
            }
            s += __shfl_xor_sync(0xffffffffu, s, 1);
            s += __shfl_xor_sync(0xffffffffu, s, 2);
            q += __shfl_xor_sync(0xffffffffu, q, 1);
            q += __shfl_xor_sync(0xffffffffu, q, 2);
            if (tig == 0) { sS[row * 2 + nw] = s; sQ[row * 2 + nw] = q; }
        }
        __syncthreads();

        #pragma unroll
        for (int h = 0; h < 2; h++) {
            int row = mw * 16 + g + 8 * h;
            float s = sS[row * 2] + sS[row * 2 + 1];
            float q = sQ[row * 2] + sQ[row * 2 + 1];
            float mean = s * (1.0f / HID);
            float var  = q * (1.0f / HID) - mean * mean;
            float rstd = rsqrtf(var + 1e-5f);
            if (row < nrows) {   // quad-uniform
                int v = base + row;
                const float* xr = Xb + (size_t)v * HID;
                float*       xo = Xob + (size_t)v * HID;
                #pragma unroll
                for (int nb = 0; nb < 8; nb++) {
                    int c = nw * 64 + nb * 8 + tig * 2;
                    float2 gm = *(float2*)(sPar + 128 + c);
                    float2 bt = *(float2*)(sPar + 256 + c);
                    float2 xv = *(const float2*)(xr + c);
                    float o0 = fmaxf((acc[nb][2*h]   - mean) * rstd * gm.x + bt.x, 0.0f) + xv.x;
                    float o1 = fmaxf((acc[nb][2*h+1] - mean) * rstd * gm.y + bt.y, 0.0f) + xv.y;
                    *(float2*)(xo + c) = make_float2(o0, o1);
                }
            }
        }
        __syncthreads();
    }
}

// ---------------------------------------------------------------------------
// out = x @ Wout + bout  (x in g_X0 after 4 layers); f32x2 CUDA-core GEMM
// ---------------------------------------------------------------------------
__global__ __launch_bounds__(256) void out_kernel(
    const float* __restrict__ Wout, const float* __restrict__ bout,
    float* __restrict__ out)
{
    extern __shared__ float sm[];
    float* Ws = sm;                   // [128][64]
    float* Xs = sm + HID * OUTD;      // [64][128]
    const int tid  = threadIdx.x;
    const int b    = blockIdx.x / ONT;
    const int tile = blockIdx.x % ONT;
    const int base = tile * LROWS;
    const int nrows = min(LROWS, NN - base);
    const float* Xb = g_X0 + (size_t)b * NN * HID;

    {
        const float4* src = (const float4*)Wout;
        float4* dst = (float4*)Ws;
        #pragma unroll
        for (int i = 0; i < 8; i++) dst[tid + 256 * i] = src[tid + 256 * i];
    }
    #pragma unroll
    for (int s = 0; s < 8; s++) {
        int idx = tid + 256 * s;
        int r = idx >> 5, cg = idx & 31;
        if (r < nrows)
            ((float4*)Xs)[idx] = ((const float4*)Xb)[(size_t)(base + r) * 32 + cg];
        else
            ((float4*)Xs)[idx] = make_float4(0.f, 0.f, 0.f, 0.f);
    }
    __syncthreads();

    const int cg = tid & 15;
    const int rg = tid >> 4;
    ull acc[4][2];
    #pragma unroll
    for (int i = 0; i < 4; i++) { acc[i][0] = 0ull; acc[i][1] = 0ull; }

    const float* Xp = Xs + rg * 4 * HID;
    #pragma unroll 2
    for (int k0 = 0; k0 < HID; k0 += 4) {
        float4 x[4];
        #pragma unroll
        for (int i = 0; i < 4; i++)
            x[i] = *(const float4*)(Xp + i * HID + k0);
        #pragma unroll
        for (int kk = 0; kk < 4; kk++) {
            ulonglong2 w = *(const ulonglong2*)(Ws + (k0 + kk) * OUTD + cg * 4);
            #pragma unroll
            for (int i = 0; i < 4; i++) {
                ull xx = pack2(f4get(x[i], kk));
                fma2(acc[i][0], xx, w.x);
                fma2(acc[i][1], xx, w.y);
            }
        }
    }

    float4 bo = ((const float4*)bout)[cg];
    #pragma unroll
    for (int i = 0; i < 4; i++) {
        int r = rg * 4 + i;
        if (r < nrows) {
            float2 lo = unpack2(acc[i][0]);
            float2 hi = unpack2(acc[i][1]);
            float4 v = make_float4(lo.x + bo.x, lo.y + bo.y, hi.x + bo.z, hi.y + bo.w);
            *(float4*)(out + ((size_t)b * NN + base + r) * OUTD + cg * 4) = v;
        }
    }
}

// ---------------------------------------------------------------------------
extern "C" void kernel_launch(void* const* d_in, const int* in_sizes, int n_in,
                              void* d_out, int out_size) {
    const int*   grids = (const int*)d_in[0];
    // d_in[1] = edge_index: fixed 30x30 4-connected grid; computed analytically.
    const float* Win   = (const float*)d_in[2];
    const float* bin   = (const float*)d_in[3];
    const float* Wg    = (const float*)d_in[4];
    const float* bg    = (const float*)d_in[5];
    const float* gamma = (const float*)d_in[6];
    const float* beta  = (const float*)d_in[7];
    const float* Wout  = (const float*)d_in[8];
    const float* bout  = (const float*)d_in[9];
    float* out = (float*)d_out;
    (void)in_sizes; (void)n_in; (void)out_size;

    const int out_smem = (HID * OUTD + LROWS * HID) * 4;  // 65536
    cudaFuncSetAttribute((const void*)layer_mma_kernel,
                         cudaFuncAttributeMaxDynamicSharedMemorySize, SMEM_MMA);
    cudaFuncSetAttribute((const void*)out_kernel,
                         cudaFuncAttributeMaxDynamicSharedMemorySize, out_smem);

    encode_kernel<<<(NB * NN * 32) / 256, 256>>>(grids, Win, bin);
    for (int i = 0; i < 4; i++) {
        layer_mma_kernel<<<NB * 2, 256, SMEM_MMA>>>(
            i & 1, Wg + (size_t)i * HID * HID, bg + i * HID,
            gamma + i * HID, beta + i * HID);
    }
    out_kernel<<<NB * ONT, 256, out_smem>>>(Wout, bout, out);
}

// round 7
// speedup vs baseline: 1.9795x; 1.1518x over previous
#include <cuda_runtime.h>
#include <cuda_fp16.h>
#include <cstdint>

#define NB   512
#define GH   30
#define GW   30
#define NN   900
#define HID  128
#define OUTD 64
#define LROWS 64
#define ONT   15

typedef unsigned long long ull;

// Ping-pong activation buffers (scratch; __device__ globals per allocation rules)
__device__ float g_X0[(size_t)NB * NN * HID];
__device__ float g_X1[(size_t)NB * NN * HID];

// smem byte offsets for layer_mma_kernel (fp16 matrices, 136-elem = 272B rows)
#define PITCHB 272
#define OFF_B   0
#define OFF_AHI 34816
#define OFF_ALO 52224
#define OFF_PAR 69632
#define OFF_RED 71168
#define SMEM_MMA 72192

__device__ __forceinline__ uint32_t smem_u32(const void* p) {
    uint32_t a;
    asm("{ .reg .u64 t; cvta.to.shared.u64 t, %1; cvt.u32.u64 %0, t; }" : "=r"(a) : "l"(p));
    return a;
}
__device__ __forceinline__ float dinv_rc(int rp, int cp) {
    int d = 1 + (rp > 0) + (rp < GH - 1) + (cp > 0) + (cp < GW - 1);
    return rsqrtf((float)d);
}
__device__ __forceinline__ float f4get(const float4& v, int i) {
    return i == 0 ? v.x : i == 1 ? v.y : i == 2 ? v.z : v.w;
}
// f32x2 helpers (out_kernel)
__device__ __forceinline__ ull pack2(float a) {
    ull r; asm("mov.b64 %0, {%1, %1};" : "=l"(r) : "f"(a)); return r;
}
__device__ __forceinline__ void fma2(ull& d, ull a, ull b) {
    asm("fma.rn.f32x2 %0, %1, %2, %0;" : "+l"(d) : "l"(a), "l"(b));
}
__device__ __forceinline__ float2 unpack2(ull v) {
    float x, y; asm("mov.b64 {%0, %1}, %2;" : "=f"(x), "=f"(y) : "l"(v));
    return make_float2(x, y);
}
// fp16 hi/lo split of two floats packed as half2 words
__device__ __forceinline__ void split2h(float a, float b, uint32_t& hi, uint32_t& lo) {
    __half2 h = __floats2half2_rn(a, b);
    float2 hf = __half22float2(h);
    __half2 l = __floats2half2_rn(a - hf.x, b - hf.y);
    hi = *(uint32_t*)&h; lo = *(uint32_t*)&l;
}
__device__ __forceinline__ void ldsm4(uint32_t addr, uint32_t& r0, uint32_t& r1,
                                      uint32_t& r2, uint32_t& r3) {
    asm volatile("ldmatrix.sync.aligned.m8n8.x4.shared.b16 {%0,%1,%2,%3}, [%4];"
                 : "=r"(r0), "=r"(r1), "=r"(r2), "=r"(r3) : "r"(addr));
}
__device__ __forceinline__ void mma_f16(float* d, const uint32_t* a, const uint32_t* b) {
    asm volatile("mma.sync.aligned.m16n8k16.row.col.f32.f16.f16.f32 "
                 "{%0,%1,%2,%3}, {%4,%5,%6,%7}, {%8,%9}, {%0,%1,%2,%3};"
                 : "+f"(d[0]), "+f"(d[1]), "+f"(d[2]), "+f"(d[3])
                 : "r"(a[0]), "r"(a[1]), "r"(a[2]), "r"(a[3]), "r"(b[0]), "r"(b[1]));
}

// ---------------------------------------------------------------------------
// x0 = relu(onehot(color)@Win + pr*Win[10] + pc*Win[11] + bin)
// ---------------------------------------------------------------------------
__global__ __launch_bounds__(256) void encode_kernel(
    const int* __restrict__ grids, const float* __restrict__ Win,
    const float* __restrict__ bin)
{
    __shared__ float4 sW[12 * 32];
    __shared__ float4 sB[32];
    const int tid = threadIdx.x;
    for (int i = tid; i < 384; i += 256) sW[i] = ((const float4*)Win)[i];
    if (tid < 32) sB[tid] = ((const float4*)bin)[tid];
    __syncthreads();

    long long idx = (long long)blockIdx.x * 256 + tid;
    int cg = (int)(idx & 31);
    long long bn = idx >> 5;
    int n = (int)(bn % NN);
    int color = grids[bn];
    float pr = (float)(n / GW) * (1.0f / (GH - 1));
    float pc = (float)(n % GW) * (1.0f / (GW - 1));
    float4 wc = sW[color * 32 + cg];
    float4 wr = sW[10 * 32 + cg];
    float4 wp = sW[11 * 32 + cg];
    float4 bb = sB[cg];
    float4 o;
    o.x = fmaxf(fmaf(pc, wp.x, fmaf(pr, wr.x, wc.x + bb.x)), 0.0f);
    o.y = fmaxf(fmaf(pc, wp.y, fmaf(pr, wr.y, wc.y + bb.y)), 0.0f);
    o.z = fmaxf(fmaf(pc, wp.z, fmaf(pr, wr.z, wc.z + bb.z)), 0.0f);
    o.w = fmaxf(fmaf(pc, wp.w, fmaf(pr, wr.w, wc.w + bb.w)), 0.0f);
    ((float4*)g_X0)[idx] = o;
}

// ---------------------------------------------------------------------------
// Tensor-core (HMMA) GCN layer, fp16 2-pass: D = Ahi@B + Alo@B, B = fp16(W).
// CTA = (batch, half), 256 threads, 2 CTAs/SM; loops 8 tiles of 64 rows.
// Warp (mw,nw): mw=warp>>1 owns rows mw*16+[0,16); nw=warp&1 owns cols
// nw*64+[0,64). LayerNorm partials exchanged across the two N-warps via smem.
// ---------------------------------------------------------------------------
__global__ __launch_bounds__(256, 2) void layer_mma_kernel(
    int flip,
    const float* __restrict__ Wg, const float* __restrict__ bg,
    const float* __restrict__ gamma, const float* __restrict__ beta)
{
    extern __shared__ char smem[];
    const uint32_t sb = smem_u32(smem);
    float* sPar = (float*)(smem + OFF_PAR);   // bg[128], gamma[128], beta[128]
    float* sS   = (float*)(smem + OFF_RED);   // [64][2] sum partials
    float* sQ   = sS + 128;                   // [64][2] sumsq partials

    const int tid = threadIdx.x, warp = tid >> 5, lane = tid & 31;
    const int mw = warp >> 1, nw = warp & 1;
    const int b = blockIdx.x >> 1, half = blockIdx.x & 1;
    const int rowbase0 = half * 450;

    const float* Xin  = flip ? g_X1 : g_X0;
    float*       Xout = flip ? g_X0 : g_X1;
    const float* Xb  = Xin  + (size_t)b * NN * HID;
    float*       Xob = Xout + (size_t)b * NN * HID;

    // --- stage LN params ---
    if (tid < 128) {
        sPar[tid]       = bg[tid];
        sPar[128 + tid] = gamma[tid];
        sPar[256 + tid] = beta[tid];
    }

    // --- stage W transposed to fp16: B[n][k], 272B rows ---
    {
        const float4* W4 = (const float4*)Wg;
        #pragma unroll
        for (int i = 0; i < 16; i++) {
            int j = tid + 256 * i;          // float4 index over [128k][32]
            int k = j >> 5, n4 = (j & 31) * 4;
            float4 v = W4[j];
            #pragma unroll
            for (int u = 0; u < 4; u++) {
                __half h = __float2half_rn(f4get(v, u));
                *(__half*)(smem + OFF_B + (uint32_t)(n4 + u) * PITCHB
                           + (uint32_t)k * 2) = h;
            }
        }
    }
    __syncthreads();

    // lane-dependent ldmatrix base offsets
    const uint32_t aRow = (uint32_t)(mw * 16 + (lane & 15)) * PITCHB
                        + ((lane >> 4) & 1) * 16;
    const uint32_t aHiB = sb + OFF_AHI + aRow;
    const uint32_t aLoB = sb + OFF_ALO + aRow;
    uint32_t bOff[4];
    #pragma unroll
    for (int p = 0; p < 4; p++) {
        int n = nw * 64 + p * 16 + (lane & 7) + ((lane >> 4) & 1) * 8;
        bOff[p] = sb + OFF_B + (uint32_t)n * PITCHB + ((lane >> 3) & 1) * 16;
    }
    const int g = lane >> 2, tig = lane & 3;

    for (int t = 0; t < 8; t++) {
        const int base = rowbase0 + t * 64;
        const int nrows = min(64, 450 - t * 64);

        // --- stencil + fp16 split -> A_hi/A_lo (zero-fill tail rows) ---
        #pragma unroll 4
        for (int s = 0; s < 8; s++) {
            int idx = tid + 256 * s;
            int r = idx >> 5, cg = idx & 31;
            uint32_t off = (uint32_t)r * PITCHB + (uint32_t)cg * 8;
            if (r < nrows) {
                int v = base + r;
                int rp = v / GW;
                int cp = v - rp * GW;
                const float4* X4 = (const float4*)Xb;
                float cv = dinv_rc(rp, cp);
                float4 xs = X4[(size_t)v * 32 + cg];
                float ax = cv * xs.x, ay = cv * xs.y, az = cv * xs.z, aw = cv * xs.w;
                if (rp > 0) {
                    float cu = dinv_rc(rp - 1, cp);
                    float4 q = X4[(size_t)(v - GW) * 32 + cg];
                    ax = fmaf(cu, q.x, ax); ay = fmaf(cu, q.y, ay);
                    az = fmaf(cu, q.z, az); aw = fmaf(cu, q.w, aw);
                }
                if (rp < GH - 1) {
                    float cu = dinv_rc(rp + 1, cp);
                    float4 q = X4[(size_t)(v + GW) * 32 + cg];
                    ax = fmaf(cu, q.x, ax); ay = fmaf(cu, q.y, ay);
                    az = fmaf(cu, q.z, az); aw = fmaf(cu, q.w, aw);
                }
                if (cp > 0) {
                    float cu = dinv_rc(rp, cp - 1);
                    float4 q = X4[(size_t)(v - 1) * 32 + cg];
                    ax = fmaf(cu, q.x, ax); ay = fmaf(cu, q.y, ay);
                    az = fmaf(cu, q.z, az); aw = fmaf(cu, q.w, aw);
                }
                if (cp < GW - 1) {
                    float cu = dinv_rc(rp, cp + 1);
                    float4 q = X4[(size_t)(v + 1) * 32 + cg];
                    ax = fmaf(cu, q.x, ax); ay = fmaf(cu, q.y, ay);
                    az = fmaf(cu, q.z, az); aw = fmaf(cu, q.w, aw);
                }
                ax *= cv; ay *= cv; az *= cv; aw *= cv;
                uint32_t h01, l01, h23, l23;
                split2h(ax, ay, h01, l01);
                split2h(az, aw, h23, l23);
                *(uint2*)(smem + OFF_AHI + off) = make_uint2(h01, h23);
                *(uint2*)(smem + OFF_ALO + off) = make_uint2(l01, l23);
            } else {
                *(uint2*)(smem + OFF_AHI + off) = make_uint2(0u, 0u);
                *(uint2*)(smem + OFF_ALO + off) = make_uint2(0u, 0u);
            }
        }
        __syncthreads();

        // --- MMA mainloop: D = Ahi@B' + Alo@B' ---
        float acc[8][4];
        #pragma unroll
        for (int nb = 0; nb < 8; nb++)
            #pragma unroll
            for (int j = 0; j < 4; j++) acc[nb][j] = 0.0f;

        #pragma unroll
        for (int ks = 0; ks < 8; ks++) {
            const uint32_t kb = (uint32_t)ks * 32;
            uint32_t ahi[4], alo[4];
            ldsm4(aHiB + kb, ahi[0], ahi[1], ahi[2], ahi[3]);
            ldsm4(aLoB + kb, alo[0], alo[1], alo[2], alo[3]);
            uint32_t bh[8][2];
            #pragma unroll
            for (int p = 0; p < 4; p++) {
                ldsm4(bOff[p] + kb,
                      bh[2*p][0], bh[2*p][1], bh[2*p+1][0], bh[2*p+1][1]);
            }
            #pragma unroll
            for (int nb = 0; nb < 8; nb++) {
                mma_f16(acc[nb], ahi, bh[nb]);
                mma_f16(acc[nb], alo, bh[nb]);
            }
        }

        // --- epilogue: bias add (in place), LN partials, cross-warp reduce ---
        #pragma unroll
        for (int h = 0; h < 2; h++) {
            int row = mw * 16 + g + 8 * h;
            float s = 0.0f, q = 0.0f;
            #pragma unroll
            for (int nb = 0; nb < 8; nb++) {
                float2 bb = *(float2*)(sPar + nw * 64 + nb * 8 + tig * 2);
                float v0 = acc[nb][2 * h]     + bb.x;
                float v1 = acc[nb][2 * h + 1] + bb.y;
                acc[nb][2 * h] = v0; acc[nb][2 * h + 1] = v1;
                s += v0 + v1;
                q = fmaf(v0, v0, fmaf(v1, v1, q));
            }
            s += __shfl_xor_sync(0xffffffffu, s, 1);
            s += __shfl_xor_sync(0xffffffffu, s, 2);
            q += __shfl_xor_sync(0xffffffffu, q, 1);
            q += __shfl_xor_sync(0xffffffffu, q, 2);
            if (tig == 0) { sS[row * 2 + nw] = s; sQ[row * 2 + nw] = q; }
        }
        __syncthreads();

        #pragma unroll
        for (int h = 0; h < 2; h++) {
            int row = mw * 16 + g + 8 * h;
            float s = sS[row * 2] + sS[row * 2 + 1];
            float q = sQ[row * 2] + sQ[row * 2 + 1];
            float mean = s * (1.0f / HID);
            float var  = q * (1.0f / HID) - mean * mean;
            float rstd = rsqrtf(var + 1e-5f);
            if (row < nrows) {   // quad-uniform
                int v = base + row;
                const float* xr = Xb + (size_t)v * HID;
                float*       xo = Xob + (size_t)v * HID;
                #pragma unroll
                for (int nb = 0; nb < 8; nb++) {
                    int c = nw * 64 + nb * 8 + tig * 2;
                    float2 gm = *(float2*)(sPar + 128 + c);
                    float2 bt = *(float2*)(sPar + 256 + c);
                    float2 xv = *(const float2*)(xr + c);
                    float o0 = fmaxf((acc[nb][2*h]   - mean) * rstd * gm.x + bt.x, 0.0f) + xv.x;
                    float o1 = fmaxf((acc[nb][2*h+1] - mean) * rstd * gm.y + bt.y, 0.0f) + xv.y;
                    *(float2*)(xo + c) = make_float2(o0, o1);
                }
            }
        }
        __syncthreads();
    }
}

// ---------------------------------------------------------------------------
// out = x @ Wout + bout  (x in g_X0 after 4 layers); f32x2 CUDA-core GEMM
// ---------------------------------------------------------------------------
__global__ __launch_bounds__(256) void out_kernel(
    const float* __restrict__ Wout, const float* __restrict__ bout,
    float* __restrict__ out)
{
    extern __shared__ float sm[];
    float* Ws = sm;                   // [128][64]
    float* Xs = sm + HID * OUTD;      // [64][128]
    const int tid  = threadIdx.x;
    const int b    = blockIdx.x / ONT;
    const int tile = blockIdx.x % ONT;
    const int base = tile * LROWS;
    const int nrows = min(LROWS, NN - base);
    const float* Xb = g_X0 + (size_t)b * NN * HID;

    {
        const float4* src = (const float4*)Wout;
        float4* dst = (float4*)Ws;
        #pragma unroll
        for (int i = 0; i < 8; i++) dst[tid + 256 * i] = src[tid + 256 * i];
    }
    #pragma unroll
    for (int s = 0; s < 8; s++) {
        int idx = tid + 256 * s;
        int r = idx >> 5, cg = idx & 31;
        if (r < nrows)
            ((float4*)Xs)[idx] = ((const float4*)Xb)[(size_t)(base + r) * 32 + cg];
        else
            ((float4*)Xs)[idx] = make_float4(0.f, 0.f, 0.f, 0.f);
    }
    __syncthreads();

    const int cg = tid & 15;
    const int rg = tid >> 4;
    ull acc[4][2];
    #pragma unroll
    for (int i = 0; i < 4; i++) { acc[i][0] = 0ull; acc[i][1] = 0ull; }

    const float* Xp = Xs + rg * 4 * HID;
    #pragma unroll 2
    for (int k0 = 0; k0 < HID; k0 += 4) {
        float4 x[4];
        #pragma unroll
        for (int i = 0; i < 4; i++)
            x[i] = *(const float4*)(Xp + i * HID + k0);
        #pragma unroll
        for (int kk = 0; kk < 4; kk++) {
            ulonglong2 w = *(const ulonglong2*)(Ws + (k0 + kk) * OUTD + cg * 4);
            #pragma unroll
            for (int i = 0; i < 4; i++) {
                ull xx = pack2(f4get(x[i], kk));
                fma2(acc[i][0], xx, w.x);
                fma2(acc[i][1], xx, w.y);
            }
        }
    }

    float4 bo = ((const float4*)bout)[cg];
    #pragma unroll
    for (int i = 0; i < 4; i++) {
        int r = rg * 4 + i;
        if (r < nrows) {
            float2 lo = unpack2(acc[i][0]);
            float2 hi = unpack2(acc[i][1]);
            float4 v = make_float4(lo.x + bo.x, lo.y + bo.y, hi.x + bo.z, hi.y + bo.w);
            *(float4*)(out + ((size_t)b * NN + base + r) * OUTD + cg * 4) = v;
        }
    }
}

// ---------------------------------------------------------------------------
extern "C" void kernel_launch(void* const* d_in, const int* in_sizes, int n_in,
                              void* d_out, int out_size) {
    const int*   grids = (const int*)d_in[0];
    // d_in[1] = edge_index: fixed 30x30 4-connected grid; computed analytically.
    const float* Win   = (const float*)d_in[2];
    const float* bin   = (const float*)d_in[3];
    const float* Wg    = (const float*)d_in[4];
    const float* bg    = (const float*)d_in[5];
    const float* gamma = (const float*)d_in[6];
    const float* beta  = (const float*)d_in[7];
    const float* Wout  = (const float*)d_in[8];
    const float* bout  = (const float*)d_in[9];
    float* out = (float*)d_out;
    (void)in_sizes; (void)n_in; (void)out_size;

    const int out_smem = (HID * OUTD + LROWS * HID) * 4;  // 65536
    cudaFuncSetAttribute((const void*)layer_mma_kernel,
                         cudaFuncAttributeMaxDynamicSharedMemorySize, SMEM_MMA);
    cudaFuncSetAttribute((const void*)out_kernel,
                         cudaFuncAttributeMaxDynamicSharedMemorySize, out_smem);

    encode_kernel<<<(NB * NN * 32) / 256, 256>>>(grids, Win, bin);
    for (int i = 0; i < 4; i++) {
        layer_mma_kernel<<<NB * 2, 256, SMEM_MMA>>>(
            i & 1, Wg + (size_t)i * HID * HID, bg + i * HID,
            gamma + i * HID, beta + i * HID);
    }
    out_kernel<<<NB * ONT, 256, out_smem>>>(Wout, bout, out);
}

// round 8
// speedup vs baseline: 2.3887x; 1.2067x over previous
#include <cuda_runtime.h>
#include <cuda_fp16.h>
#include <cstdint>

#define NB   512
#define GH   30
#define GW   30
#define NN   900
#define HID  128
#define OUTD 64

typedef unsigned long long ull;

// Ping-pong activation buffers (scratch; __device__ globals per allocation rules)
__device__ float g_X0[(size_t)NB * NN * HID];
__device__ float g_X1[(size_t)NB * NN * HID];
// Precomputed graph tables (fixed 30x30 4-connected grid + self loops)
__device__ float g_coef[NN * 8];   // [v]: self, W, E, N, S, pad...
__device__ int4  g_nidx[NN];       // [v]: clamped W, E, N, S indices

// smem byte offsets for layer_mma_kernel (fp16 matrices, 136-elem = 272B rows)
#define PITCHB 272
#define OFF_B   0
#define OFF_AHI 34816
#define OFF_ALO 52224
#define OFF_PAR 69632
#define OFF_RED 71168
#define SMEM_MMA 72192

// smem offsets for out_mma_kernel
#define OOFF_B   0
#define OOFF_AHI 17408
#define OOFF_ALO 34816
#define OOFF_PAR 52224
#define SMEM_OUT 52480

__device__ __forceinline__ uint32_t smem_u32(const void* p) {
    uint32_t a;
    asm("{ .reg .u64 t; cvta.to.shared.u64 t, %1; cvt.u32.u64 %0, t; }" : "=r"(a) : "l"(p));
    return a;
}
__device__ __forceinline__ float dinv_rc(int rp, int cp) {
    int d = 1 + (rp > 0) + (rp < GH - 1) + (cp > 0) + (cp < GW - 1);
    return rsqrtf((float)d);
}
__device__ __forceinline__ float f4get(const float4& v, int i) {
    return i == 0 ? v.x : i == 1 ? v.y : i == 2 ? v.z : v.w;
}
// fp16 hi/lo split of two floats packed as half2 words
__device__ __forceinline__ void split2h(float a, float b, uint32_t& hi, uint32_t& lo) {
    __half2 h = __floats2half2_rn(a, b);
    float2 hf = __half22float2(h);
    __half2 l = __floats2half2_rn(a - hf.x, b - hf.y);
    hi = *(uint32_t*)&h; lo = *(uint32_t*)&l;
}
__device__ __forceinline__ void ldsm4(uint32_t addr, uint32_t& r0, uint32_t& r1,
                                      uint32_t& r2, uint32_t& r3) {
    asm volatile("ldmatrix.sync.aligned.m8n8.x4.shared.b16 {%0,%1,%2,%3}, [%4];"
                 : "=r"(r0), "=r"(r1), "=r"(r2), "=r"(r3) : "r"(addr));
}
__device__ __forceinline__ void mma_f16(float* d, const uint32_t* a, const uint32_t* b) {
    asm volatile("mma.sync.aligned.m16n8k16.row.col.f32.f16.f16.f32 "
                 "{%0,%1,%2,%3}, {%4,%5,%6,%7}, {%8,%9}, {%0,%1,%2,%3};"
                 : "+f"(d[0]), "+f"(d[1]), "+f"(d[2]), "+f"(d[3])
                 : "r"(a[0]), "r"(a[1]), "r"(a[2]), "r"(a[3]), "r"(b[0]), "r"(b[1]));
}

// ---------------------------------------------------------------------------
// init: precompute normalized stencil coefficients + clamped neighbor indices
// ---------------------------------------------------------------------------
__global__ void init_tables_kernel() {
    int v = threadIdx.x + blockIdx.x * 256;
    if (v < NN) {
        int r = v / GW, c = v - (v / GW) * GW;
        float dv = dinv_rc(r, c);
        float w = (c > 0)      ? dinv_rc(r, c - 1) : 0.0f;
        float e = (c < GW - 1) ? dinv_rc(r, c + 1) : 0.0f;
        float n = (r > 0)      ? dinv_rc(r - 1, c) : 0.0f;
        float s = (r < GH - 1) ? dinv_rc(r + 1, c) : 0.0f;
        float4* cf = (float4*)(g_coef + v * 8);
        cf[0] = make_float4(dv * dv, dv * w, dv * e, dv * n);
        cf[1] = make_float4(dv * s, 0.0f, 0.0f, 0.0f);
        g_nidx[v] = make_int4((c > 0) ? v - 1 : v, (c < GW - 1) ? v + 1 : v,
                              (r > 0) ? v - GW : v, (r < GH - 1) ? v + GW : v);
    }
}

// ---------------------------------------------------------------------------
// x0 = relu(onehot(color)@Win + pr*Win[10] + pc*Win[11] + bin)
// ---------------------------------------------------------------------------
__global__ __launch_bounds__(256) void encode_kernel(
    const int* __restrict__ grids, const float* __restrict__ Win,
    const float* __restrict__ bin)
{
    __shared__ float4 sW[12 * 32];
    __shared__ float4 sB[32];
    const int tid = threadIdx.x;
    for (int i = tid; i < 384; i += 256) sW[i] = ((const float4*)Win)[i];
    if (tid < 32) sB[tid] = ((const float4*)bin)[tid];
    __syncthreads();

    long long idx = (long long)blockIdx.x * 256 + tid;
    int cg = (int)(idx & 31);
    long long bn = idx >> 5;
    int n = (int)(bn % NN);
    int color = grids[bn];
    float pr = (float)(n / GW) * (1.0f / (GH - 1));
    float pc = (float)(n % GW) * (1.0f / (GW - 1));
    float4 wc = sW[color * 32 + cg];
    float4 wr = sW[10 * 32 + cg];
    float4 wp = sW[11 * 32 + cg];
    float4 bb = sB[cg];
    float4 o;
    o.x = fmaxf(fmaf(pc, wp.x, fmaf(pr, wr.x, wc.x + bb.x)), 0.0f);
    o.y = fmaxf(fmaf(pc, wp.y, fmaf(pr, wr.y, wc.y + bb.y)), 0.0f);
    o.z = fmaxf(fmaf(pc, wp.z, fmaf(pr, wr.z, wc.z + bb.z)), 0.0f);
    o.w = fmaxf(fmaf(pc, wp.w, fmaf(pr, wr.w, wc.w + bb.w)), 0.0f);
    ((float4*)g_X0)[idx] = o;
}

// ---------------------------------------------------------------------------
// Tensor-core (HMMA) GCN layer, fp16 2-pass: D = Ahi@B + Alo@B, B = fp16(W).
// CTA = (batch, half), 256 threads, 2 CTAs/SM; loops 8 tiles of 64 rows.
// Stencil uses precomputed coef/nidx tables: no MUFU, no branches.
// ---------------------------------------------------------------------------
__global__ __launch_bounds__(256, 2) void layer_mma_kernel(
    int flip,
    const float* __restrict__ Wg, const float* __restrict__ bg,
    const float* __restrict__ gamma, const float* __restrict__ beta)
{
    extern __shared__ char smem[];
    const uint32_t sb = smem_u32(smem);
    float* sPar = (float*)(smem + OFF_PAR);   // bg[128], gamma[128], beta[128]
    float* sS   = (float*)(smem + OFF_RED);   // [64][2] sum partials
    float* sQ   = sS + 128;                   // [64][2] sumsq partials

    const int tid = threadIdx.x, warp = tid >> 5, lane = tid & 31;
    const int mw = warp >> 1, nw = warp & 1;
    const int b = blockIdx.x >> 1, half = blockIdx.x & 1;
    const int rowbase0 = half * 450;

    const float* Xin  = flip ? g_X1 : g_X0;
    float*       Xout = flip ? g_X0 : g_X1;
    const float* Xb  = Xin  + (size_t)b * NN * HID;
    float*       Xob = Xout + (size_t)b * NN * HID;

    // --- stage LN params ---
    if (tid < 128) {
        sPar[tid]       = bg[tid];
        sPar[128 + tid] = gamma[tid];
        sPar[256 + tid] = beta[tid];
    }

    // --- stage W transposed to fp16: B[n][k], 272B rows ---
    {
        const float4* W4 = (const float4*)Wg;
        #pragma unroll
        for (int i = 0; i < 16; i++) {
            int j = tid + 256 * i;          // float4 index over [128k][32]
            int k = j >> 5, n4 = (j & 31) * 4;
            float4 v = W4[j];
            #pragma unroll
            for (int u = 0; u < 4; u++) {
                __half h = __float2half_rn(f4get(v, u));
                *(__half*)(smem + OFF_B + (uint32_t)(n4 + u) * PITCHB
                           + (uint32_t)k * 2) = h;
            }
        }
    }
    __syncthreads();

    // lane-dependent ldmatrix base offsets
    const uint32_t aRow = (uint32_t)(mw * 16 + (lane & 15)) * PITCHB
                        + ((lane >> 4) & 1) * 16;
    const uint32_t aHiB = sb + OFF_AHI + aRow;
    const uint32_t aLoB = sb + OFF_ALO + aRow;
    uint32_t bOff[4];
    #pragma unroll
    for (int p = 0; p < 4; p++) {
        int n = nw * 64 + p * 16 + (lane & 7) + ((lane >> 4) & 1) * 8;
        bOff[p] = sb + OFF_B + (uint32_t)n * PITCHB + ((lane >> 3) & 1) * 16;
    }
    const int g = lane >> 2, tig = lane & 3;

    for (int t = 0; t < 8; t++) {
        const int base = rowbase0 + t * 64;
        const int nrows = min(64, 450 - t * 64);

        // --- stencil (table-driven) + fp16 split -> A_hi/A_lo ---
        #pragma unroll 4
        for (int s = 0; s < 8; s++) {
            int idx = tid + 256 * s;
            int r = idx >> 5, cg = idx & 31;
            uint32_t off = (uint32_t)r * PITCHB + (uint32_t)cg * 8;
            if (r < nrows) {
                int v = base + r;
                float4 cf = *(const float4*)(g_coef + v * 8);      // self,W,E,N
                float cfs = g_coef[v * 8 + 4];                     // S
                int4 ni = g_nidx[v];
                const float4* X4 = (const float4*)Xb;
                float4 xs = X4[(size_t)v * 32 + cg];
                float4 xw = X4[(size_t)ni.x * 32 + cg];
                float4 xe = X4[(size_t)ni.y * 32 + cg];
                float4 xn = X4[(size_t)ni.z * 32 + cg];
                float4 xo = X4[(size_t)ni.w * 32 + cg];
                float ax = cf.x * xs.x, ay = cf.x * xs.y, az = cf.x * xs.z, aw = cf.x * xs.w;
                ax = fmaf(cf.y, xw.x, ax); ay = fmaf(cf.y, xw.y, ay);
                az = fmaf(cf.y, xw.z, az); aw = fmaf(cf.y, xw.w, aw);
                ax = fmaf(cf.z, xe.x, ax); ay = fmaf(cf.z, xe.y, ay);
                az = fmaf(cf.z, xe.z, az); aw = fmaf(cf.z, xe.w, aw);
                ax = fmaf(cf.w, xn.x, ax); ay = fmaf(cf.w, xn.y, ay);
                az = fmaf(cf.w, xn.z, az); aw = fmaf(cf.w, xn.w, aw);
                ax = fmaf(cfs, xo.x, ax); ay = fmaf(cfs, xo.y, ay);
                az = fmaf(cfs, xo.z, az); aw = fmaf(cfs, xo.w, aw);
                uint32_t h01, l01, h23, l23;
                split2h(ax, ay, h01, l01);
                split2h(az, aw, h23, l23);
                *(uint2*)(smem + OFF_AHI + off) = make_uint2(h01, h23);
                *(uint2*)(smem + OFF_ALO + off) = make_uint2(l01, l23);
            } else {
                *(uint2*)(smem + OFF_AHI + off) = make_uint2(0u, 0u);
                *(uint2*)(smem + OFF_ALO + off) = make_uint2(0u, 0u);
            }
        }
        __syncthreads();

        // --- MMA mainloop: D = Ahi@B' + Alo@B' ---
        float acc[8][4];
        #pragma unroll
        for (int nb = 0; nb < 8; nb++)
            #pragma unroll
            for (int j = 0; j < 4; j++) acc[nb][j] = 0.0f;

        #pragma unroll
        for (int ks = 0; ks < 8; ks++) {
            const uint32_t kb = (uint32_t)ks * 32;
            uint32_t ahi[4], alo[4];
            ldsm4(aHiB + kb, ahi[0], ahi[1], ahi[2], ahi[3]);
            ldsm4(aLoB + kb, alo[0], alo[1], alo[2], alo[3]);
            uint32_t bh[8][2];
            #pragma unroll
            for (int p = 0; p < 4; p++) {
                ldsm4(bOff[p] + kb,
                      bh[2*p][0], bh[2*p][1], bh[2*p+1][0], bh[2*p+1][1]);
            }
            #pragma unroll
            for (int nb = 0; nb < 8; nb++) {
                mma_f16(acc[nb], ahi, bh[nb]);
                mma_f16(acc[nb], alo, bh[nb]);
            }
        }

        // --- epilogue: bias add (in place), LN partials, cross-warp reduce ---
        #pragma unroll
        for (int h = 0; h < 2; h++) {
            int row = mw * 16 + g + 8 * h;
            float s = 0.0f, q = 0.0f;
            #pragma unroll
            for (int nb = 0; nb < 8; nb++) {
                float2 bb = *(float2*)(sPar + nw * 64 + nb * 8 + tig * 2);
                float v0 = acc[nb][2 * h]     + bb.x;
                float v1 = acc[nb][2 * h + 1] + bb.y;
                acc[nb][2 * h] = v0; acc[nb][2 * h + 1] = v1;
                s += v0 + v1;
                q = fmaf(v0, v0, fmaf(v1, v1, q));
            }
            s += __shfl_xor_sync(0xffffffffu, s, 1);
            s += __shfl_xor_sync(0xffffffffu, s, 2);
            q += __shfl_xor_sync(0xffffffffu, q, 1);
            q += __shfl_xor_sync(0xffffffffu, q, 2);
            if (tig == 0) { sS[row * 2 + nw] = s; sQ[row * 2 + nw] = q; }
        }
        __syncthreads();

        #pragma unroll
        for (int h = 0; h < 2; h++) {
            int row = mw * 16 + g + 8 * h;
            float s = sS[row * 2] + sS[row * 2 + 1];
            float q = sQ[row * 2] + sQ[row * 2 + 1];
            float mean = s * (1.0f / HID);
            float var  = q * (1.0f / HID) - mean * mean;
            float rstd = rsqrtf(var + 1e-5f);
            if (row < nrows) {   // quad-uniform
                int v = base + row;
                const float* xr = Xb + (size_t)v * HID;
                float*       xo = Xob + (size_t)v * HID;
                #pragma unroll
                for (int nb = 0; nb < 8; nb++) {
                    int c = nw * 64 + nb * 8 + tig * 2;
                    float2 gm = *(float2*)(sPar + 128 + c);
                    float2 bt = *(float2*)(sPar + 256 + c);
                    float2 xv = *(const float2*)(xr + c);
                    float o0 = fmaxf((acc[nb][2*h]   - mean) * rstd * gm.x + bt.x, 0.0f) + xv.x;
                    float o1 = fmaxf((acc[nb][2*h+1] - mean) * rstd * gm.y + bt.y, 0.0f) + xv.y;
                    *(float2*)(xo + c) = make_float2(o0, o1);
                }
            }
        }
        __syncthreads();
    }
}

// ---------------------------------------------------------------------------
// out = x @ Wout + bout via fp16 2-pass HMMA (x in g_X0 after 4 layers).
// CTA = (batch, half), 256 threads, 4 CTAs/SM; loops 8 tiles of 64 rows.
// Warp (mw,nw): mw=warp>>1 rows mw*16+[0,16); nw=warp&1 cols nw*32+[0,32).
// ---------------------------------------------------------------------------
__global__ __launch_bounds__(256, 4) void out_mma_kernel(
    const float* __restrict__ Wout, const float* __restrict__ bout,
    float* __restrict__ out)
{
    extern __shared__ char smem[];
    const uint32_t sb = smem_u32(smem);
    float* sPar = (float*)(smem + OOFF_PAR);   // bout[64]

    const int tid = threadIdx.x, warp = tid >> 5, lane = tid & 31;
    const int mw = warp >> 1, nw = warp & 1;
    const int b = blockIdx.x >> 1, half = blockIdx.x & 1;
    const int rowbase0 = half * 450;
    const float* Xb = g_X0 + (size_t)b * NN * HID;

    if (tid < 64) sPar[tid] = bout[tid];

    // --- stage Wout transposed to fp16: B[n][k], 272B rows ---
    {
        const float4* W4 = (const float4*)Wout;   // [128k][16]
        #pragma unroll
        for (int i = 0; i < 8; i++) {
            int j = tid + 256 * i;
            int k = j >> 4, n4 = (j & 15) * 4;
            float4 v = W4[j];
            #pragma unroll
            for (int u = 0; u < 4; u++) {
                __half h = __float2half_rn(f4get(v, u));
                *(__half*)(smem + OOFF_B + (uint32_t)(n4 + u) * PITCHB
                           + (uint32_t)k * 2) = h;
            }
        }
    }
    __syncthreads();

    const uint32_t aRow = (uint32_t)(mw * 16 + (lane & 15)) * PITCHB
                        + ((lane >> 4) & 1) * 16;
    const uint32_t aHiB = sb + OOFF_AHI + aRow;
    const uint32_t aLoB = sb + OOFF_ALO + aRow;
    uint32_t bOff[2];
    #pragma unroll
    for (int p = 0; p < 2; p++) {
        int n = nw * 32 + p * 16 + (lane & 7) + ((lane >> 4) & 1) * 8;
        bOff[p] = sb + OOFF_B + (uint32_t)n * PITCHB + ((lane >> 3) & 1) * 16;
    }
    const int g = lane >> 2, tig = lane & 3;

    for (int t = 0; t < 8; t++) {
        const int base = rowbase0 + t * 64;
        const int nrows = min(64, 450 - t * 64);

        // --- A = fp16 split of x rows ---
        #pragma unroll 4
        for (int s = 0; s < 8; s++) {
            int idx = tid + 256 * s;
            int r = idx >> 5, cg = idx & 31;
            uint32_t off = (uint32_t)r * PITCHB + (uint32_t)cg * 8;
            if (r < nrows) {
                float4 x = ((const float4*)Xb)[(size_t)(base + r) * 32 + cg];
                uint32_t h01, l01, h23, l23;
                split2h(x.x, x.y, h01, l01);
                split2h(x.z, x.w, h23, l23);
                *(uint2*)(smem + OOFF_AHI + off) = make_uint2(h01, h23);
                *(uint2*)(smem + OOFF_ALO + off) = make_uint2(l01, l23);
            } else {
                *(uint2*)(smem + OOFF_AHI + off) = make_uint2(0u, 0u);
                *(uint2*)(smem + OOFF_ALO + off) = make_uint2(0u, 0u);
            }
        }
        __syncthreads();

        float acc[4][4];
        #pragma unroll
        for (int nb = 0; nb < 4; nb++)
            #pragma unroll
            for (int j = 0; j < 4; j++) acc[nb][j] = 0.0f;

        #pragma unroll
        for (int ks = 0; ks < 8; ks++) {
            const uint32_t kb = (uint32_t)ks * 32;
            uint32_t ahi[4], alo[4];
            ldsm4(aHiB + kb, ahi[0], ahi[1], ahi[2], ahi[3]);
            ldsm4(aLoB + kb, alo[0], alo[1], alo[2], alo[3]);
            uint32_t bh[4][2];
            #pragma unroll
            for (int p = 0; p < 2; p++) {
                ldsm4(bOff[p] + kb,
                      bh[2*p][0], bh[2*p][1], bh[2*p+1][0], bh[2*p+1][1]);
            }
            #pragma unroll
            for (int nb = 0; nb < 4; nb++) {
                mma_f16(acc[nb], ahi, bh[nb]);
                mma_f16(acc[nb], alo, bh[nb]);
            }
        }

        #pragma unroll
        for (int h = 0; h < 2; h++) {
            int row = mw * 16 + g + 8 * h;
            if (row < nrows) {   // quad-uniform
                float* op = out + ((size_t)b * NN + base + row) * OUTD;
                #pragma unroll
                for (int nb = 0; nb < 4; nb++) {
                    int c = nw * 32 + nb * 8 + tig * 2;
                    float2 bo = *(float2*)(sPar + c);
                    *(float2*)(op + c) = make_float2(acc[nb][2*h]   + bo.x,
                                                     acc[nb][2*h+1] + bo.y);
                }
            }
        }
        __syncthreads();
    }
}

// ---------------------------------------------------------------------------
extern "C" void kernel_launch(void* const* d_in, const int* in_sizes, int n_in,
                              void* d_out, int out_size) {
    const int*   grids = (const int*)d_in[0];
    // d_in[1] = edge_index: fixed 30x30 4-connected grid; precomputed tables.
    const float* Win   = (const float*)d_in[2];
    const float* bin   = (const float*)d_in[3];
    const float* Wg    = (const float*)d_in[4];
    const float* bg    = (const float*)d_in[5];
    const float* gamma = (const float*)d_in[6];
    const float* beta  = (const float*)d_in[7];
    const float* Wout  = (const float*)d_in[8];
    const float* bout  = (const float*)d_in[9];
    float* out = (float*)d_out;
    (void)in_sizes; (void)n_in; (void)out_size;

    cudaFuncSetAttribute((const void*)layer_mma_kernel,
                         cudaFuncAttributeMaxDynamicSharedMemorySize, SMEM_MMA);
    cudaFuncSetAttribute((const void*)out_mma_kernel,
                         cudaFuncAttributeMaxDynamicSharedMemorySize, SMEM_OUT);

    init_tables_kernel<<<4, 256>>>();
    encode_kernel<<<(NB * NN * 32) / 256, 256>>>(grids, Win, bin);
    for (int i = 0; i < 4; i++) {
        layer_mma_kernel<<<NB * 2, 256, SMEM_MMA>>>(
            i & 1, Wg + (size_t)i * HID * HID, bg + i * HID,
            gamma + i * HID, beta + i * HID);
    }
    out_mma_kernel<<<NB * 2, 256, SMEM_OUT>>>(Wout, bout, out);
}

// round 9
// speedup vs baseline: 2.9534x; 1.2364x over previous
#include <cuda_runtime.h>
#include <cuda_fp16.h>
#include <cstdint>

#define NB   512
#define GH   30
#define GW   30
#define NN   900
#define HID  128
#define OUTD 64

typedef unsigned long long ull;

// Ping-pong activation buffers (scratch; __device__ globals per allocation rules)
__device__ float g_X0[(size_t)NB * NN * HID];
__device__ float g_X1[(size_t)NB * NN * HID];
// Precomputed graph tables (fixed 30x30 4-connected grid + self loops)
__device__ float g_coef[NN * 8];   // [v]: self, W, E, N, S, pad...
__device__ int4  g_nidx[NN];       // [v]: clamped W, E, N, S indices

// smem byte offsets for layer_mma_kernel (fp16 matrices, 136-elem = 272B rows)
#define PITCHB 272
#define OFF_B   0
#define OFF_AHI 34816
#define OFF_ALO 52224
#define OFF_PAR 69632
#define OFF_RED 71168
#define SMEM_MMA 72192

// smem offsets for out_mma_kernel
#define OOFF_B   0
#define OOFF_AHI 17408
#define OOFF_ALO 34816
#define OOFF_PAR 52224
#define SMEM_OUT 52480

__device__ __forceinline__ uint32_t smem_u32(const void* p) {
    uint32_t a;
    asm("{ .reg .u64 t; cvta.to.shared.u64 t, %1; cvt.u32.u64 %0, t; }" : "=r"(a) : "l"(p));
    return a;
}
__device__ __forceinline__ float dinv_rc(int rp, int cp) {
    int d = 1 + (rp > 0) + (rp < GH - 1) + (cp > 0) + (cp < GW - 1);
    return rsqrtf((float)d);
}
__device__ __forceinline__ float f4get(const float4& v, int i) {
    return i == 0 ? v.x : i == 1 ? v.y : i == 2 ? v.z : v.w;
}
// fp16 hi/lo split of two floats packed as half2 words
__device__ __forceinline__ void split2h(float a, float b, uint32_t& hi, uint32_t& lo) {
    __half2 h = __floats2half2_rn(a, b);
    float2 hf = __half22float2(h);
    __half2 l = __floats2half2_rn(a - hf.x, b - hf.y);
    hi = *(uint32_t*)&h; lo = *(uint32_t*)&l;
}
__device__ __forceinline__ void ldsm4(uint32_t addr, uint32_t& r0, uint32_t& r1,
                                      uint32_t& r2, uint32_t& r3) {
    asm volatile("ldmatrix.sync.aligned.m8n8.x4.shared.b16 {%0,%1,%2,%3}, [%4];"
                 : "=r"(r0), "=r"(r1), "=r"(r2), "=r"(r3) : "r"(addr));
}
__device__ __forceinline__ void mma_f16(float* d, const uint32_t* a, const uint32_t* b) {
    asm volatile("mma.sync.aligned.m16n8k16.row.col.f32.f16.f16.f32 "
                 "{%0,%1,%2,%3}, {%4,%5,%6,%7}, {%8,%9}, {%0,%1,%2,%3};"
                 : "+f"(d[0]), "+f"(d[1]), "+f"(d[2]), "+f"(d[3])
                 : "r"(a[0]), "r"(a[1]), "r"(a[2]), "r"(a[3]), "r"(b[0]), "r"(b[1]));
}

// ---------------------------------------------------------------------------
// init: precompute normalized stencil coefficients + clamped neighbor indices
// ---------------------------------------------------------------------------
__global__ void init_tables_kernel() {
    int v = threadIdx.x + blockIdx.x * 256;
    if (v < NN) {
        int r = v / GW, c = v - (v / GW) * GW;
        float dv = dinv_rc(r, c);
        float w = (c > 0)      ? dinv_rc(r, c - 1) : 0.0f;
        float e = (c < GW - 1) ? dinv_rc(r, c + 1) : 0.0f;
        float n = (r > 0)      ? dinv_rc(r - 1, c) : 0.0f;
        float s = (r < GH - 1) ? dinv_rc(r + 1, c) : 0.0f;
        float4* cf = (float4*)(g_coef + v * 8);
        cf[0] = make_float4(dv * dv, dv * w, dv * e, dv * n);
        cf[1] = make_float4(dv * s, 0.0f, 0.0f, 0.0f);
        g_nidx[v] = make_int4((c > 0) ? v - 1 : v, (c < GW - 1) ? v + 1 : v,
                              (r > 0) ? v - GW : v, (r < GH - 1) ? v + GW : v);
    }
}

// ---------------------------------------------------------------------------
// x0 = relu(onehot(color)@Win + pr*Win[10] + pc*Win[11] + bin)
// ---------------------------------------------------------------------------
__global__ __launch_bounds__(256) void encode_kernel(
    const int* __restrict__ grids, const float* __restrict__ Win,
    const float* __restrict__ bin)
{
    __shared__ float4 sW[12 * 32];
    __shared__ float4 sB[32];
    const int tid = threadIdx.x;
    for (int i = tid; i < 384; i += 256) sW[i] = ((const float4*)Win)[i];
    if (tid < 32) sB[tid] = ((const float4*)bin)[tid];
    __syncthreads();

    long long idx = (long long)blockIdx.x * 256 + tid;
    int cg = (int)(idx & 31);
    long long bn = idx >> 5;
    int n = (int)(bn % NN);
    int color = grids[bn];
    float pr = (float)(n / GW) * (1.0f / (GH - 1));
    float pc = (float)(n % GW) * (1.0f / (GW - 1));
    float4 wc = sW[color * 32 + cg];
    float4 wr = sW[10 * 32 + cg];
    float4 wp = sW[11 * 32 + cg];
    float4 bb = sB[cg];
    float4 o;
    o.x = fmaxf(fmaf(pc, wp.x, fmaf(pr, wr.x, wc.x + bb.x)), 0.0f);
    o.y = fmaxf(fmaf(pc, wp.y, fmaf(pr, wr.y, wc.y + bb.y)), 0.0f);
    o.z = fmaxf(fmaf(pc, wp.z, fmaf(pr, wr.z, wc.z + bb.z)), 0.0f);
    o.w = fmaxf(fmaf(pc, wp.w, fmaf(pr, wr.w, wc.w + bb.w)), 0.0f);
    ((float4*)g_X0)[idx] = o;
}

// ---------------------------------------------------------------------------
// Tensor-core (HMMA) GCN layer, fp16 2-pass: D = Ahi@B + Alo@B, B = fp16(W).
// CTA = (batch, quarter), 256 threads, 3 CTAs/SM; loops 4 tiles (3x64 + 33).
// Warp (mw,nw): mw=warp>>1 owns rows mw*16+[0,16); nw=warp&1 owns cols
// nw*64+[0,64). LayerNorm partials exchanged across the two N-warps via smem.
// ---------------------------------------------------------------------------
__global__ __launch_bounds__(256, 3) void layer_mma_kernel(
    int flip,
    const float* __restrict__ Wg, const float* __restrict__ bg,
    const float* __restrict__ gamma, const float* __restrict__ beta)
{
    extern __shared__ char smem[];
    const uint32_t sb = smem_u32(smem);
    float* sPar = (float*)(smem + OFF_PAR);   // bg[128], gamma[128], beta[128]
    float* sS   = (float*)(smem + OFF_RED);   // [64][2] sum partials
    float* sQ   = sS + 128;                   // [64][2] sumsq partials

    const int tid = threadIdx.x, warp = tid >> 5, lane = tid & 31;
    const int mw = warp >> 1, nw = warp & 1;
    const int b = blockIdx.x >> 2, quarter = blockIdx.x & 3;
    const int rowbase0 = quarter * 225;

    const float* Xin  = flip ? g_X1 : g_X0;
    float*       Xout = flip ? g_X0 : g_X1;
    const float* Xb  = Xin  + (size_t)b * NN * HID;
    float*       Xob = Xout + (size_t)b * NN * HID;

    // --- stage LN params ---
    if (tid < 128) {
        sPar[tid]       = bg[tid];
        sPar[128 + tid] = gamma[tid];
        sPar[256 + tid] = beta[tid];
    }

    // --- stage W transposed to fp16: B[n][k], 272B rows ---
    {
        const float4* W4 = (const float4*)Wg;
        #pragma unroll
        for (int i = 0; i < 16; i++) {
            int j = tid + 256 * i;          // float4 index over [128k][32]
            int k = j >> 5, n4 = (j & 31) * 4;
            float4 v = W4[j];
            #pragma unroll
            for (int u = 0; u < 4; u++) {
                __half h = __float2half_rn(f4get(v, u));
                *(__half*)(smem + OFF_B + (uint32_t)(n4 + u) * PITCHB
                           + (uint32_t)k * 2) = h;
            }
        }
    }
    __syncthreads();

    // lane-dependent ldmatrix base offsets
    const uint32_t aRow = (uint32_t)(mw * 16 + (lane & 15)) * PITCHB
                        + ((lane >> 4) & 1) * 16;
    const uint32_t aHiB = sb + OFF_AHI + aRow;
    const uint32_t aLoB = sb + OFF_ALO + aRow;
    uint32_t bOff[4];
    #pragma unroll
    for (int p = 0; p < 4; p++) {
        int n = nw * 64 + p * 16 + (lane & 7) + ((lane >> 4) & 1) * 8;
        bOff[p] = sb + OFF_B + (uint32_t)n * PITCHB + ((lane >> 3) & 1) * 16;
    }
    const int g = lane >> 2, tig = lane & 3;

    for (int t = 0; t < 4; t++) {
        const int base = rowbase0 + t * 64;
        const int nrows = min(64, 225 - t * 64);

        // --- stencil (table-driven) + fp16 split -> A_hi/A_lo ---
        #pragma unroll 4
        for (int s = 0; s < 8; s++) {
            int idx = tid + 256 * s;
            int r = idx >> 5, cg = idx & 31;
            uint32_t off = (uint32_t)r * PITCHB + (uint32_t)cg * 8;
            if (r < nrows) {
                int v = base + r;
                float4 cf = *(const float4*)(g_coef + v * 8);      // self,W,E,N
                float cfs = g_coef[v * 8 + 4];                     // S
                int4 ni = g_nidx[v];
                const float4* X4 = (const float4*)Xb;
                float4 xs = X4[(size_t)v * 32 + cg];
                float4 xw = X4[(size_t)ni.x * 32 + cg];
                float4 xe = X4[(size_t)ni.y * 32 + cg];
                float4 xn = X4[(size_t)ni.z * 32 + cg];
                float4 xo = X4[(size_t)ni.w * 32 + cg];
                float ax = cf.x * xs.x, ay = cf.x * xs.y, az = cf.x * xs.z, aw = cf.x * xs.w;
                ax = fmaf(cf.y, xw.x, ax); ay = fmaf(cf.y, xw.y, ay);
                az = fmaf(cf.y, xw.z, az); aw = fmaf(cf.y, xw.w, aw);
                ax = fmaf(cf.z, xe.x, ax); ay = fmaf(cf.z, xe.y, ay);
                az = fmaf(cf.z, xe.z, az); aw = fmaf(cf.z, xe.w, aw);
                ax = fmaf(cf.w, xn.x, ax); ay = fmaf(cf.w, xn.y, ay);
                az = fmaf(cf.w, xn.z, az); aw = fmaf(cf.w, xn.w, aw);
                ax = fmaf(cfs, xo.x, ax); ay = fmaf(cfs, xo.y, ay);
                az = fmaf(cfs, xo.z, az); aw = fmaf(cfs, xo.w, aw);
                uint32_t h01, l01, h23, l23;
                split2h(ax, ay, h01, l01);
                split2h(az, aw, h23, l23);
                *(uint2*)(smem + OFF_AHI + off) = make_uint2(h01, h23);
                *(uint2*)(smem + OFF_ALO + off) = make_uint2(l01, l23);
            } else {
                *(uint2*)(smem + OFF_AHI + off) = make_uint2(0u, 0u);
                *(uint2*)(smem + OFF_ALO + off) = make_uint2(0u, 0u);
            }
        }
        __syncthreads();

        // --- MMA mainloop: D = Ahi@B' + Alo@B' ---
        float acc[8][4];
        #pragma unroll
        for (int nb = 0; nb < 8; nb++)
            #pragma unroll
            for (int j = 0; j < 4; j++) acc[nb][j] = 0.0f;

        #pragma unroll
        for (int ks = 0; ks < 8; ks++) {
            const uint32_t kb = (uint32_t)ks * 32;
            uint32_t ahi[4], alo[4];
            ldsm4(aHiB + kb, ahi[0], ahi[1], ahi[2], ahi[3]);
            ldsm4(aLoB + kb, alo[0], alo[1], alo[2], alo[3]);
            uint32_t bh[8][2];
            #pragma unroll
            for (int p = 0; p < 4; p++) {
                ldsm4(bOff[p] + kb,
                      bh[2*p][0], bh[2*p][1], bh[2*p+1][0], bh[2*p+1][1]);
            }
            #pragma unroll
            for (int nb = 0; nb < 8; nb++) {
                mma_f16(acc[nb], ahi, bh[nb]);
                mma_f16(acc[nb], alo, bh[nb]);
            }
        }

        // --- epilogue: bias add (in place), LN partials, cross-warp reduce ---
        #pragma unroll
        for (int h = 0; h < 2; h++) {
            int row = mw * 16 + g + 8 * h;
            float s = 0.0f, q = 0.0f;
            #pragma unroll
            for (int nb = 0; nb < 8; nb++) {
                float2 bb = *(float2*)(sPar + nw * 64 + nb * 8 + tig * 2);
                float v0 = acc[nb][2 * h]     + bb.x;
                float v1 = acc[nb][2 * h + 1] + bb.y;
                acc[nb][2 * h] = v0; acc[nb][2 * h + 1] = v1;
                s += v0 + v1;
                q = fmaf(v0, v0, fmaf(v1, v1, q));
            }
            s += __shfl_xor_sync(0xffffffffu, s, 1);
            s += __shfl_xor_sync(0xffffffffu, s, 2);
            q += __shfl_xor_sync(0xffffffffu, q, 1);
            q += __shfl_xor_sync(0xffffffffu, q, 2);
            if (tig == 0) { sS[row * 2 + nw] = s; sQ[row * 2 + nw] = q; }
        }
        __syncthreads();

        #pragma unroll
        for (int h = 0; h < 2; h++) {
            int row = mw * 16 + g + 8 * h;
            float s = sS[row * 2] + sS[row * 2 + 1];
            float q = sQ[row * 2] + sQ[row * 2 + 1];
            float mean = s * (1.0f / HID);
            float var  = q * (1.0f / HID) - mean * mean;
            float rstd = rsqrtf(var + 1e-5f);
            if (row < nrows) {   // quad-uniform
                int v = base + row;
                const float* xr = Xb + (size_t)v * HID;
                float*       xo = Xob + (size_t)v * HID;
                #pragma unroll
                for (int nb = 0; nb < 8; nb++) {
                    int c = nw * 64 + nb * 8 + tig * 2;
                    float2 gm = *(float2*)(sPar + 128 + c);
                    float2 bt = *(float2*)(sPar + 256 + c);
                    float2 xv = *(const float2*)(xr + c);
                    float o0 = fmaxf((acc[nb][2*h]   - mean) * rstd * gm.x + bt.x, 0.0f) + xv.x;
                    float o1 = fmaxf((acc[nb][2*h+1] - mean) * rstd * gm.y + bt.y, 0.0f) + xv.y;
                    *(float2*)(xo + c) = make_float2(o0, o1);
                }
            }
        }
        __syncthreads();
    }
}

// ---------------------------------------------------------------------------
// out = x @ Wout + bout via fp16 2-pass HMMA (x in g_X0 after 4 layers).
// CTA = (batch, half), 256 threads, 4 CTAs/SM; loops 8 tiles of 64 rows.
// ---------------------------------------------------------------------------
__global__ __launch_bounds__(256, 4) void out_mma_kernel(
    const float* __restrict__ Wout, const float* __restrict__ bout,
    float* __restrict__ out)
{
    extern __shared__ char smem[];
    const uint32_t sb = smem_u32(smem);
    float* sPar = (float*)(smem + OOFF_PAR);   // bout[64]

    const int tid = threadIdx.x, warp = tid >> 5, lane = tid & 31;
    const int mw = warp >> 1, nw = warp & 1;
    const int b = blockIdx.x >> 1, half = blockIdx.x & 1;
    const int rowbase0 = half * 450;
    const float* Xb = g_X0 + (size_t)b * NN * HID;

    if (tid < 64) sPar[tid] = bout[tid];

    // --- stage Wout transposed to fp16: B[n][k], 272B rows ---
    {
        const float4* W4 = (const float4*)Wout;   // [128k][16]
        #pragma unroll
        for (int i = 0; i < 8; i++) {
            int j = tid + 256 * i;
            int k = j >> 4, n4 = (j & 15) * 4;
            float4 v = W4[j];
            #pragma unroll
            for (int u = 0; u < 4; u++) {
                __half h = __float2half_rn(f4get(v, u));
                *(__half*)(smem + OOFF_B + (uint32_t)(n4 + u) * PITCHB
                           + (uint32_t)k * 2) = h;
            }
        }
    }
    __syncthreads();

    const uint32_t aRow = (uint32_t)(mw * 16 + (lane & 15)) * PITCHB
                        + ((lane >> 4) & 1) * 16;
    const uint32_t aHiB = sb + OOFF_AHI + aRow;
    const uint32_t aLoB = sb + OOFF_ALO + aRow;
    uint32_t bOff[2];
    #pragma unroll
    for (int p = 0; p < 2; p++) {
        int n = nw * 32 + p * 16 + (lane & 7) + ((lane >> 4) & 1) * 8;
        bOff[p] = sb + OOFF_B + (uint32_t)n * PITCHB + ((lane >> 3) & 1) * 16;
    }
    const int g = lane >> 2, tig = lane & 3;

    for (int t = 0; t < 8; t++) {
        const int base = rowbase0 + t * 64;
        const int nrows = min(64, 450 - t * 64);

        // --- A = fp16 split of x rows ---
        #pragma unroll 4
        for (int s = 0; s < 8; s++) {
            int idx = tid + 256 * s;
            int r = idx >> 5, cg = idx & 31;
            uint32_t off = (uint32_t)r * PITCHB + (uint32_t)cg * 8;
            if (r < nrows) {
                float4 x = ((const float4*)Xb)[(size_t)(base + r) * 32 + cg];
                uint32_t h01, l01, h23, l23;
                split2h(x.x, x.y, h01, l01);
                split2h(x.z, x.w, h23, l23);
                *(uint2*)(smem + OOFF_AHI + off) = make_uint2(h01, h23);
                *(uint2*)(smem + OOFF_ALO + off) = make_uint2(l01, l23);
            } else {
                *(uint2*)(smem + OOFF_AHI + off) = make_uint2(0u, 0u);
                *(uint2*)(smem + OOFF_ALO + off) = make_uint2(0u, 0u);
            }
        }
        __syncthreads();

        float acc[4][4];
        #pragma unroll
        for (int nb = 0; nb < 4; nb++)
            #pragma unroll
            for (int j = 0; j < 4; j++) acc[nb][j] = 0.0f;

        #pragma unroll
        for (int ks = 0; ks < 8; ks++) {
            const uint32_t kb = (uint32_t)ks * 32;
            uint32_t ahi[4], alo[4];
            ldsm4(aHiB + kb, ahi[0], ahi[1], ahi[2], ahi[3]);
            ldsm4(aLoB + kb, alo[0], alo[1], alo[2], alo[3]);
            uint32_t bh[4][2];
            #pragma unroll
            for (int p = 0; p < 2; p++) {
                ldsm4(bOff[p] + kb,
                      bh[2*p][0], bh[2*p][1], bh[2*p+1][0], bh[2*p+1][1]);
            }
            #pragma unroll
            for (int nb = 0; nb < 4; nb++) {
                mma_f16(acc[nb], ahi, bh[nb]);
                mma_f16(acc[nb], alo, bh[nb]);
            }
        }

        #pragma unroll
        for (int h = 0; h < 2; h++) {
            int row = mw * 16 + g + 8 * h;
            if (row < nrows) {   // quad-uniform
                float* op = out + ((size_t)b * NN + base + row) * OUTD;
                #pragma unroll
                for (int nb = 0; nb < 4; nb++) {
                    int c = nw * 32 + nb * 8 + tig * 2;
                    float2 bo = *(float2*)(sPar + c);
                    *(float2*)(op + c) = make_float2(acc[nb][2*h]   + bo.x,
                                                     acc[nb][2*h+1] + bo.y);
                }
            }
        }
        __syncthreads();
    }
}

// ---------------------------------------------------------------------------
extern "C" void kernel_launch(void* const* d_in, const int* in_sizes, int n_in,
                              void* d_out, int out_size) {
    const int*   grids = (const int*)d_in[0];
    // d_in[1] = edge_index: fixed 30x30 4-connected grid; precomputed tables.
    const float* Win   = (const float*)d_in[2];
    const float* bin   = (const float*)d_in[3];
    const float* Wg    = (const float*)d_in[4];
    const float* bg    = (const float*)d_in[5];
    const float* gamma = (const float*)d_in[6];
    const float* beta  = (const float*)d_in[7];
    const float* Wout  = (const float*)d_in[8];
    const float* bout  = (const float*)d_in[9];
    float* out = (float*)d_out;
    (void)in_sizes; (void)n_in; (void)out_size;

    cudaFuncSetAttribute((const void*)layer_mma_kernel,
                         cudaFuncAttributeMaxDynamicSharedMemorySize, SMEM_MMA);
    cudaFuncSetAttribute((const void*)out_mma_kernel,
                         cudaFuncAttributeMaxDynamicSharedMemorySize, SMEM_OUT);

    init_tables_kernel<<<4, 256>>>();
    encode_kernel<<<(NB * NN * 32) / 256, 256>>>(grids, Win, bin);
    for (int i = 0; i < 4; i++) {
        layer_mma_kernel<<<NB * 4, 256, SMEM_MMA>>>(
            i & 1, Wg + (size_t)i * HID * HID, bg + i * HID,
            gamma + i * HID, beta + i * HID);
    }
    out_mma_kernel<<<NB * 2, 256, SMEM_OUT>>>(Wout, bout, out);
}

// round 10
// speedup vs baseline: 3.3642x; 1.1391x over previous
#include <cuda_runtime.h>
#include <cuda_fp16.h>
#include <cstdint>

#define NB   512
#define GH   30
#define GW   30
#define NN   900
#define HID  128
#define OUTD 64

// Ping-pong activation buffers (scratch; __device__ globals per allocation rules)
__device__ float g_X0[(size_t)NB * NN * HID];
__device__ float g_X1[(size_t)NB * NN * HID];
// Precomputed graph tables (fixed 30x30 4-connected grid + self loops)
__device__ float g_coef[NN * 8];   // [v]: self, W, E, N, S, pad...
__device__ int4  g_nidx[NN];       // [v]: clamped W, E, N, S indices

// smem byte offsets for layer_mma_kernel (fp16 matrices, 136-elem = 272B rows)
#define PITCHB 272
#define OFF_B   0
#define OFF_A   34816
#define OFF_PAR 52224
#define OFF_RED 53760
#define SMEM_MMA 54784

// smem offsets for out_mma_kernel
#define OOFF_B   0
#define OOFF_A   17408
#define OOFF_PAR 34816
#define SMEM_OUT 35072

__device__ __forceinline__ uint32_t smem_u32(const void* p) {
    uint32_t a;
    asm("{ .reg .u64 t; cvta.to.shared.u64 t, %1; cvt.u32.u64 %0, t; }" : "=r"(a) : "l"(p));
    return a;
}
__device__ __forceinline__ float dinv_rc(int rp, int cp) {
    int d = 1 + (rp > 0) + (rp < GH - 1) + (cp > 0) + (cp < GW - 1);
    return rsqrtf((float)d);
}
__device__ __forceinline__ float f4get(const float4& v, int i) {
    return i == 0 ? v.x : i == 1 ? v.y : i == 2 ? v.z : v.w;
}
__device__ __forceinline__ void ldsm4(uint32_t addr, uint32_t& r0, uint32_t& r1,
                                      uint32_t& r2, uint32_t& r3) {
    asm volatile("ldmatrix.sync.aligned.m8n8.x4.shared.b16 {%0,%1,%2,%3}, [%4];"
                 : "=r"(r0), "=r"(r1), "=r"(r2), "=r"(r3) : "r"(addr));
}
__device__ __forceinline__ void mma_f16(float* d, const uint32_t* a, const uint32_t* b) {
    asm volatile("mma.sync.aligned.m16n8k16.row.col.f32.f16.f16.f32 "
                 "{%0,%1,%2,%3}, {%4,%5,%6,%7}, {%8,%9}, {%0,%1,%2,%3};"
                 : "+f"(d[0]), "+f"(d[1]), "+f"(d[2]), "+f"(d[3])
                 : "r"(a[0]), "r"(a[1]), "r"(a[2]), "r"(a[3]), "r"(b[0]), "r"(b[1]));
}

// ---------------------------------------------------------------------------
// init: precompute normalized stencil coefficients + clamped neighbor indices
// ---------------------------------------------------------------------------
__global__ void init_tables_kernel() {
    int v = threadIdx.x + blockIdx.x * 256;
    if (v < NN) {
        int r = v / GW, c = v - (v / GW) * GW;
        float dv = dinv_rc(r, c);
        float w = (c > 0)      ? dinv_rc(r, c - 1) : 0.0f;
        float e = (c < GW - 1) ? dinv_rc(r, c + 1) : 0.0f;
        float n = (r > 0)      ? dinv_rc(r - 1, c) : 0.0f;
        float s = (r < GH - 1) ? dinv_rc(r + 1, c) : 0.0f;
        float4* cf = (float4*)(g_coef + v * 8);
        cf[0] = make_float4(dv * dv, dv * w, dv * e, dv * n);
        cf[1] = make_float4(dv * s, 0.0f, 0.0f, 0.0f);
        g_nidx[v] = make_int4((c > 0) ? v - 1 : v, (c < GW - 1) ? v + 1 : v,
                              (r > 0) ? v - GW : v, (r < GH - 1) ? v + GW : v);
    }
}

// ---------------------------------------------------------------------------
// x0 = relu(onehot(color)@Win + pr*Win[10] + pc*Win[11] + bin)
// ---------------------------------------------------------------------------
__global__ __launch_bounds__(256) void encode_kernel(
    const int* __restrict__ grids, const float* __restrict__ Win,
    const float* __restrict__ bin)
{
    __shared__ float4 sW[12 * 32];
    __shared__ float4 sB[32];
    const int tid = threadIdx.x;
    for (int i = tid; i < 384; i += 256) sW[i] = ((const float4*)Win)[i];
    if (tid < 32) sB[tid] = ((const float4*)bin)[tid];
    __syncthreads();

    long long idx = (long long)blockIdx.x * 256 + tid;
    int cg = (int)(idx & 31);
    long long bn = idx >> 5;
    int n = (int)(bn % NN);
    int color = grids[bn];
    float pr = (float)(n / GW) * (1.0f / (GH - 1));
    float pc = (float)(n % GW) * (1.0f / (GW - 1));
    float4 wc = sW[color * 32 + cg];
    float4 wr = sW[10 * 32 + cg];
    float4 wp = sW[11 * 32 + cg];
    float4 bb = sB[cg];
    float4 o;
    o.x = fmaxf(fmaf(pc, wp.x, fmaf(pr, wr.x, wc.x + bb.x)), 0.0f);
    o.y = fmaxf(fmaf(pc, wp.y, fmaf(pr, wr.y, wc.y + bb.y)), 0.0f);
    o.z = fmaxf(fmaf(pc, wp.z, fmaf(pr, wr.z, wc.z + bb.z)), 0.0f);
    o.w = fmaxf(fmaf(pc, wp.w, fmaf(pr, wr.w, wc.w + bb.w)), 0.0f);
    ((float4*)g_X0)[idx] = o;
}

// ---------------------------------------------------------------------------
// Tensor-core (HMMA) GCN layer, single-pass fp16: D = fp16(Ahat@x) @ fp16(W).
// CTA = (batch, quarter), 256 threads, 3 CTAs/SM; loops 4 tiles (3x64 + 33).
// B columns are PERMUTED at staging (physical col nb*8+tig*2+e holds logical
// col tig*16+nb*2+e within each 64-block) so each thread's 16 accumulator
// values cover 16 consecutive output columns -> float4-coalesced epilogue.
// ---------------------------------------------------------------------------
__global__ __launch_bounds__(256, 3) void layer_mma_kernel(
    int flip,
    const float* __restrict__ Wg, const float* __restrict__ bg,
    const float* __restrict__ gamma, const float* __restrict__ beta)
{
    extern __shared__ char smem[];
    const uint32_t sb = smem_u32(smem);
    float* sPar = (float*)(smem + OFF_PAR);   // bg[128], gamma[128], beta[128]
    float* sS   = (float*)(smem + OFF_RED);   // [64][2] sum partials
    float* sQ   = sS + 128;                   // [64][2] sumsq partials

    const int tid = threadIdx.x, warp = tid >> 5, lane = tid & 31;
    const int mw = warp >> 1, nw = warp & 1;
    const int b = blockIdx.x >> 2, quarter = blockIdx.x & 3;
    const int rowbase0 = quarter * 225;

    const float* Xin  = flip ? g_X1 : g_X0;
    float*       Xout = flip ? g_X0 : g_X1;
    const float* Xb  = Xin  + (size_t)b * NN * HID;
    float*       Xob = Xout + (size_t)b * NN * HID;

    // --- stage LN params ---
    if (tid < 128) {
        sPar[tid]       = bg[tid];
        sPar[128 + tid] = gamma[tid];
        sPar[256 + tid] = beta[tid];
    }

    // --- stage W transposed+permuted to fp16: B[P(l)][k], 272B rows ---
    {
        const float4* W4 = (const float4*)Wg;
        #pragma unroll
        for (int i = 0; i < 16; i++) {
            int j = tid + 256 * i;          // float4 index over [128k][32]
            int k = j >> 5, n4 = (j & 31) * 4;
            float4 v = W4[j];
            #pragma unroll
            for (int u = 0; u < 4; u++) {
                int l = n4 + u;
                int li = l & 63;
                int P = (l & 64) + ((li & 15) >> 1) * 8 + (li >> 4) * 2 + (l & 1);
                __half h = __float2half_rn(f4get(v, u));
                *(__half*)(smem + OFF_B + (uint32_t)P * PITCHB
                           + (uint32_t)k * 2) = h;
            }
        }
    }
    __syncthreads();

    // lane-dependent ldmatrix base offsets
    const uint32_t aRow = (uint32_t)(mw * 16 + (lane & 15)) * PITCHB
                        + ((lane >> 4) & 1) * 16;
    const uint32_t aB = sb + OFF_A + aRow;
    uint32_t bOff[4];
    #pragma unroll
    for (int p = 0; p < 4; p++) {
        int n = nw * 64 + p * 16 + (lane & 7) + ((lane >> 4) & 1) * 8;
        bOff[p] = sb + OFF_B + (uint32_t)n * PITCHB + ((lane >> 3) & 1) * 16;
    }
    const int g = lane >> 2, tig = lane & 3;

    for (int t = 0; t < 4; t++) {
        const int base = rowbase0 + t * 64;
        const int nrows = min(64, 225 - t * 64);

        // --- stencil (table-driven) -> fp16 A ---
        #pragma unroll 4
        for (int s = 0; s < 8; s++) {
            int idx = tid + 256 * s;
            int r = idx >> 5, cg = idx & 31;
            uint32_t off = (uint32_t)r * PITCHB + (uint32_t)cg * 8;
            if (r < nrows) {
                int v = base + r;
                float4 cf = *(const float4*)(g_coef + v * 8);      // self,W,E,N
                float cfs = g_coef[v * 8 + 4];                     // S
                int4 ni = g_nidx[v];
                const float4* X4 = (const float4*)Xb;
                float4 xs = X4[(size_t)v * 32 + cg];
                float4 xw = X4[(size_t)ni.x * 32 + cg];
                float4 xe = X4[(size_t)ni.y * 32 + cg];
                float4 xn = X4[(size_t)ni.z * 32 + cg];
                float4 xo = X4[(size_t)ni.w * 32 + cg];
                float ax = cf.x * xs.x, ay = cf.x * xs.y, az = cf.x * xs.z, aw = cf.x * xs.w;
                ax = fmaf(cf.y, xw.x, ax); ay = fmaf(cf.y, xw.y, ay);
                az = fmaf(cf.y, xw.z, az); aw = fmaf(cf.y, xw.w, aw);
                ax = fmaf(cf.z, xe.x, ax); ay = fmaf(cf.z, xe.y, ay);
                az = fmaf(cf.z, xe.z, az); aw = fmaf(cf.z, xe.w, aw);
                ax = fmaf(cf.w, xn.x, ax); ay = fmaf(cf.w, xn.y, ay);
                az = fmaf(cf.w, xn.z, az); aw = fmaf(cf.w, xn.w, aw);
                ax = fmaf(cfs, xo.x, ax); ay = fmaf(cfs, xo.y, ay);
                az = fmaf(cfs, xo.z, az); aw = fmaf(cfs, xo.w, aw);
                __half2 h01 = __floats2half2_rn(ax, ay);
                __half2 h23 = __floats2half2_rn(az, aw);
                *(uint2*)(smem + OFF_A + off) =
                    make_uint2(*(uint32_t*)&h01, *(uint32_t*)&h23);
            } else {
                *(uint2*)(smem + OFF_A + off) = make_uint2(0u, 0u);
            }
        }
        __syncthreads();

        // --- MMA mainloop: D = A @ B' (single fp16 pass) ---
        float acc[8][4];
        #pragma unroll
        for (int nb = 0; nb < 8; nb++)
            #pragma unroll
            for (int j = 0; j < 4; j++) acc[nb][j] = 0.0f;

        #pragma unroll
        for (int ks = 0; ks < 8; ks++) {
            const uint32_t kb = (uint32_t)ks * 32;
            uint32_t a[4];
            ldsm4(aB + kb, a[0], a[1], a[2], a[3]);
            uint32_t bh[8][2];
            #pragma unroll
            for (int p = 0; p < 4; p++) {
                ldsm4(bOff[p] + kb,
                      bh[2*p][0], bh[2*p][1], bh[2*p+1][0], bh[2*p+1][1]);
            }
            #pragma unroll
            for (int nb = 0; nb < 8; nb++)
                mma_f16(acc[nb], a, bh[nb]);
        }

        // --- epilogue: bias add, LN partials, cross-warp reduce ---
        #pragma unroll
        for (int h = 0; h < 2; h++) {
            int row = mw * 16 + g + 8 * h;
            float s = 0.0f, q = 0.0f;
            #pragma unroll
            for (int nb = 0; nb < 8; nb++) {
                // logical cols: nw*64 + tig*16 + nb*2 + {0,1}
                float2 bb = *(float2*)(sPar + nw * 64 + tig * 16 + nb * 2);
                float v0 = acc[nb][2 * h]     + bb.x;
                float v1 = acc[nb][2 * h + 1] + bb.y;
                acc[nb][2 * h] = v0; acc[nb][2 * h + 1] = v1;
                s += v0 + v1;
                q = fmaf(v0, v0, fmaf(v1, v1, q));
            }
            s += __shfl_xor_sync(0xffffffffu, s, 1);
            s += __shfl_xor_sync(0xffffffffu, s, 2);
            q += __shfl_xor_sync(0xffffffffu, q, 1);
            q += __shfl_xor_sync(0xffffffffu, q, 2);
            if (tig == 0) { sS[row * 2 + nw] = s; sQ[row * 2 + nw] = q; }
        }
        __syncthreads();

        #pragma unroll
        for (int h = 0; h < 2; h++) {
            int row = mw * 16 + g + 8 * h;
            float s = sS[row * 2] + sS[row * 2 + 1];
            float q = sQ[row * 2] + sQ[row * 2 + 1];
            float mean = s * (1.0f / HID);
            float var  = q * (1.0f / HID) - mean * mean;
            float rstd = rsqrtf(var + 1e-5f);
            if (row < nrows) {   // quad-uniform
                int v = base + row;
                const float* xr = Xb + (size_t)v * HID;
                float*       xo = Xob + (size_t)v * HID;
                #pragma unroll
                for (int j = 0; j < 4; j++) {
                    int C = nw * 64 + tig * 16 + 4 * j;
                    float4 gm = *(float4*)(sPar + 128 + C);
                    float4 bt = *(float4*)(sPar + 256 + C);
                    float4 xv = *(const float4*)(xr + C);
                    float4 o;
                    o.x = fmaxf((acc[2*j][2*h]     - mean) * rstd * gm.x + bt.x, 0.0f) + xv.x;
                    o.y = fmaxf((acc[2*j][2*h+1]   - mean) * rstd * gm.y + bt.y, 0.0f) + xv.y;
                    o.z = fmaxf((acc[2*j+1][2*h]   - mean) * rstd * gm.z + bt.z, 0.0f) + xv.z;
                    o.w = fmaxf((acc[2*j+1][2*h+1] - mean) * rstd * gm.w + bt.w, 0.0f) + xv.w;
                    *(float4*)(xo + C) = o;
                }
            }
        }
        __syncthreads();
    }
}

// ---------------------------------------------------------------------------
// out = x @ Wout + bout via single-pass fp16 HMMA (x in g_X0 after 4 layers).
// CTA = (batch, half), 256 threads, 4+ CTAs/SM; loops 8 tiles of 64 rows.
// Same column permutation trick (logical l = tig*8 + nb*2 + e per 32-block).
// ---------------------------------------------------------------------------
__global__ __launch_bounds__(256, 4) void out_mma_kernel(
    const float* __restrict__ Wout, const float* __restrict__ bout,
    float* __restrict__ out)
{
    extern __shared__ char smem[];
    const uint32_t sb = smem_u32(smem);
    float* sPar = (float*)(smem + OOFF_PAR);   // bout[64]

    const int tid = threadIdx.x, warp = tid >> 5, lane = tid & 31;
    const int mw = warp >> 1, nw = warp & 1;
    const int b = blockIdx.x >> 1, half = blockIdx.x & 1;
    const int rowbase0 = half * 450;
    const float* Xb = g_X0 + (size_t)b * NN * HID;

    if (tid < 64) sPar[tid] = bout[tid];

    // --- stage Wout transposed+permuted to fp16: B[P(l)][k], 272B rows ---
    {
        const float4* W4 = (const float4*)Wout;   // [128k][16]
        #pragma unroll
        for (int i = 0; i < 8; i++) {
            int j = tid + 256 * i;
            int k = j >> 4, n4 = (j & 15) * 4;
            float4 v = W4[j];
            #pragma unroll
            for (int u = 0; u < 4; u++) {
                int l = n4 + u;
                int li = l & 31;
                int P = (l & 32) + ((li & 7) >> 1) * 8 + (li >> 3) * 2 + (l & 1);
                __half h = __float2half_rn(f4get(v, u));
                *(__half*)(smem + OOFF_B + (uint32_t)P * PITCHB
                           + (uint32_t)k * 2) = h;
            }
        }
    }
    __syncthreads();

    const uint32_t aRow = (uint32_t)(mw * 16 + (lane & 15)) * PITCHB
                        + ((lane >> 4) & 1) * 16;
    const uint32_t aB = sb + OOFF_A + aRow;
    uint32_t bOff[2];
    #pragma unroll
    for (int p = 0; p < 2; p++) {
        int n = nw * 32 + p * 16 + (lane & 7) + ((lane >> 4) & 1) * 8;
        bOff[p] = sb + OOFF_B + (uint32_t)n * PITCHB + ((lane >> 3) & 1) * 16;
    }
    const int g = lane >> 2, tig = lane & 3;

    for (int t = 0; t < 8; t++) {
        const int base = rowbase0 + t * 64;
        const int nrows = min(64, 450 - t * 64);

        // --- A = fp16 of x rows ---
        #pragma unroll 4
        for (int s = 0; s < 8; s++) {
            int idx = tid + 256 * s;
            int r = idx >> 5, cg = idx & 31;
            uint32_t off = (uint32_t)r * PITCHB + (uint32_t)cg * 8;
            if (r < nrows) {
                float4 x = ((const float4*)Xb)[(size_t)(base + r) * 32 + cg];
                __half2 h01 = __floats2half2_rn(x.x, x.y);
                __half2 h23 = __floats2half2_rn(x.z, x.w);
                *(uint2*)(smem + OOFF_A + off) =
                    make_uint2(*(uint32_t*)&h01, *(uint32_t*)&h23);
            } else {
                *(uint2*)(smem + OOFF_A + off) = make_uint2(0u, 0u);
            }
        }
        __syncthreads();

        float acc[4][4];
        #pragma unroll
        for (int nb = 0; nb < 4; nb++)
            #pragma unroll
            for (int j = 0; j < 4; j++) acc[nb][j] = 0.0f;

        #pragma unroll
        for (int ks = 0; ks < 8; ks++) {
            const uint32_t kb = (uint32_t)ks * 32;
            uint32_t a[4];
            ldsm4(aB + kb, a[0], a[1], a[2], a[3]);
            uint32_t bh[4][2];
            #pragma unroll
            for (int p = 0; p < 2; p++) {
                ldsm4(bOff[p] + kb,
                      bh[2*p][0], bh[2*p][1], bh[2*p+1][0], bh[2*p+1][1]);
            }
            #pragma unroll
            for (int nb = 0; nb < 4; nb++)
                mma_f16(acc[nb], a, bh[nb]);
        }

        #pragma unroll
        for (int h = 0; h < 2; h++) {
            int row = mw * 16 + g + 8 * h;
            if (row < nrows) {   // quad-uniform
                float* op = out + ((size_t)b * NN + base + row) * OUTD;
                #pragma unroll
                for (int j = 0; j < 2; j++) {
                    int C = nw * 32 + tig * 8 + 4 * j;
                    float4 bo = *(float4*)(sPar + C);
                    float4 o;
                    o.x = acc[2*j][2*h]     + bo.x;
                    o.y = acc[2*j][2*h+1]   + bo.y;
                    o.z = acc[2*j+1][2*h]   + bo.z;
                    o.w = acc[2*j+1][2*h+1] + bo.w;
                    *(float4*)(op + C) = o;
                }
            }
        }
        __syncthreads();
    }
}

// ---------------------------------------------------------------------------
extern "C" void kernel_launch(void* const* d_in, const int* in_sizes, int n_in,
                              void* d_out, int out_size) {
    const int*   grids = (const int*)d_in[0];
    // d_in[1] = edge_index: fixed 30x30 4-connected grid; precomputed tables.
    const float* Win   = (const float*)d_in[2];
    const float* bin   = (const float*)d_in[3];
    const float* Wg    = (const float*)d_in[4];
    const float* bg    = (const float*)d_in[5];
    const float* gamma = (const float*)d_in[6];
    const float* beta  = (const float*)d_in[7];
    const float* Wout  = (const float*)d_in[8];
    const float* bout  = (const float*)d_in[9];
    float* out = (float*)d_out;
    (void)in_sizes; (void)n_in; (void)out_size;

    cudaFuncSetAttribute((const void*)layer_mma_kernel,
                         cudaFuncAttributeMaxDynamicSharedMemorySize, SMEM_MMA);
    cudaFuncSetAttribute((const void*)out_mma_kernel,
                         cudaFuncAttributeMaxDynamicSharedMemorySize, SMEM_OUT);

    init_tables_kernel<<<4, 256>>>();
    encode_kernel<<<(NB * NN * 32) / 256, 256>>>(grids, Win, bin);
    for (int i = 0; i < 4; i++) {
        layer_mma_kernel<<<NB * 4, 256, SMEM_MMA>>>(
            i & 1, Wg + (size_t)i * HID * HID, bg + i * HID,
            gamma + i * HID, beta + i * HID);
    }
    out_mma_kernel<<<NB * 2, 256, SMEM_OUT>>>(Wout, bout, out);
}

// round 11
// speedup vs baseline: 3.5247x; 1.0477x over previous
#include <cuda_runtime.h>
#include <cuda_fp16.h>
#include <cstdint>

#define NB   512
#define GH   30
#define GW   30
#define NN   900
#define HID  128
#define OUTD 64

// Ping-pong activation buffers (scratch; __device__ globals per allocation rules)
__device__ float  g_X0[(size_t)NB * NN * HID];
__device__ float  g_X1[(size_t)NB * NN * HID];
// fp16 shadow copies (stencil / out-GEMM inputs; residual path stays fp32)
__device__ __half g_XH0[(size_t)NB * NN * HID];
__device__ __half g_XH1[(size_t)NB * NN * HID];
// Precomputed graph tables (fixed 30x30 4-connected grid + self loops)
__device__ float g_coef[NN * 8];   // [v]: self, W, E, N, S, pad...
__device__ int4  g_nidx[NN];       // [v]: clamped W, E, N, S indices

// smem byte offsets for layer_mma_kernel (fp16 matrices, 136-elem = 272B rows)
#define PITCHB 272
#define OFF_B   0
#define OFF_A   34816
#define OFF_PAR 52224
#define OFF_RED 53760
#define SMEM_MMA 55808

// smem offsets for out_mma_kernel
#define OOFF_B   0
#define OOFF_A   17408
#define OOFF_PAR 34816
#define SMEM_OUT 35072

__device__ __forceinline__ uint32_t smem_u32(const void* p) {
    uint32_t a;
    asm("{ .reg .u64 t; cvta.to.shared.u64 t, %1; cvt.u32.u64 %0, t; }" : "=r"(a) : "l"(p));
    return a;
}
__device__ __forceinline__ float dinv_rc(int rp, int cp) {
    int d = 1 + (rp > 0) + (rp < GH - 1) + (cp > 0) + (cp < GW - 1);
    return rsqrtf((float)d);
}
__device__ __forceinline__ float f4get(const float4& v, int i) {
    return i == 0 ? v.x : i == 1 ? v.y : i == 2 ? v.z : v.w;
}
__device__ __forceinline__ void ldsm4(uint32_t addr, uint32_t& r0, uint32_t& r1,
                                      uint32_t& r2, uint32_t& r3) {
    asm volatile("ldmatrix.sync.aligned.m8n8.x4.shared.b16 {%0,%1,%2,%3}, [%4];"
                 : "=r"(r0), "=r"(r1), "=r"(r2), "=r"(r3) : "r"(addr));
}
__device__ __forceinline__ void mma_f16(float* d, const uint32_t* a, const uint32_t* b) {
    asm volatile("mma.sync.aligned.m16n8k16.row.col.f32.f16.f16.f32 "
                 "{%0,%1,%2,%3}, {%4,%5,%6,%7}, {%8,%9}, {%0,%1,%2,%3};"
                 : "+f"(d[0]), "+f"(d[1]), "+f"(d[2]), "+f"(d[3])
                 : "r"(a[0]), "r"(a[1]), "r"(a[2]), "r"(a[3]), "r"(b[0]), "r"(b[1]));
}
// fp32x2 from a half2 word
__device__ __forceinline__ float2 h2f2(uint32_t h) {
    return __half22float2(*(__half2*)&h);
}

// ---------------------------------------------------------------------------
// init: precompute normalized stencil coefficients + clamped neighbor indices
// ---------------------------------------------------------------------------
__global__ void init_tables_kernel() {
    int v = threadIdx.x + blockIdx.x * 256;
    if (v < NN) {
        int r = v / GW, c = v - (v / GW) * GW;
        float dv = dinv_rc(r, c);
        float w = (c > 0)      ? dinv_rc(r, c - 1) : 0.0f;
        float e = (c < GW - 1) ? dinv_rc(r, c + 1) : 0.0f;
        float n = (r > 0)      ? dinv_rc(r - 1, c) : 0.0f;
        float s = (r < GH - 1) ? dinv_rc(r + 1, c) : 0.0f;
        float4* cf = (float4*)(g_coef + v * 8);
        cf[0] = make_float4(dv * dv, dv * w, dv * e, dv * n);
        cf[1] = make_float4(dv * s, 0.0f, 0.0f, 0.0f);
        g_nidx[v] = make_int4((c > 0) ? v - 1 : v, (c < GW - 1) ? v + 1 : v,
                              (r > 0) ? v - GW : v, (r < GH - 1) ? v + GW : v);
    }
}

// ---------------------------------------------------------------------------
// x0 = relu(onehot(color)@Win + pr*Win[10] + pc*Win[11] + bin); writes fp32+fp16
// ---------------------------------------------------------------------------
__global__ __launch_bounds__(256) void encode_kernel(
    const int* __restrict__ grids, const float* __restrict__ Win,
    const float* __restrict__ bin)
{
    __shared__ float4 sW[12 * 32];
    __shared__ float4 sB[32];
    const int tid = threadIdx.x;
    for (int i = tid; i < 384; i += 256) sW[i] = ((const float4*)Win)[i];
    if (tid < 32) sB[tid] = ((const float4*)bin)[tid];
    __syncthreads();

    long long idx = (long long)blockIdx.x * 256 + tid;
    int cg = (int)(idx & 31);
    long long bn = idx >> 5;
    int n = (int)(bn % NN);
    int color = grids[bn];
    float pr = (float)(n / GW) * (1.0f / (GH - 1));
    float pc = (float)(n % GW) * (1.0f / (GW - 1));
    float4 wc = sW[color * 32 + cg];
    float4 wr = sW[10 * 32 + cg];
    float4 wp = sW[11 * 32 + cg];
    float4 bb = sB[cg];
    float4 o;
    o.x = fmaxf(fmaf(pc, wp.x, fmaf(pr, wr.x, wc.x + bb.x)), 0.0f);
    o.y = fmaxf(fmaf(pc, wp.y, fmaf(pr, wr.y, wc.y + bb.y)), 0.0f);
    o.z = fmaxf(fmaf(pc, wp.z, fmaf(pr, wr.z, wc.z + bb.z)), 0.0f);
    o.w = fmaxf(fmaf(pc, wp.w, fmaf(pr, wr.w, wc.w + bb.w)), 0.0f);
    ((float4*)g_X0)[idx] = o;
    __half2 h01 = __floats2half2_rn(o.x, o.y);
    __half2 h23 = __floats2half2_rn(o.z, o.w);
    ((uint2*)g_XH0)[idx] = make_uint2(*(uint32_t*)&h01, *(uint32_t*)&h23);
}

// ---------------------------------------------------------------------------
// Tensor-core (HMMA) GCN layer, single-pass fp16: D = fp16(Ahat@x16) @ fp16(W).
// CTA = (batch, quarter), 256 threads, 3 CTAs/SM; loops 4 tiles (3x64 + 33).
// Warp tile 32 rows x 32 cols (mw=warp>>2, nw=warp&3): balanced ldsm (2A+2B).
// B columns permuted so each thread owns 8 consecutive logical cols.
// Stencil reads the fp16 shadow of x; residual path reads/writes fp32 x and
// also emits the fp16 shadow for the next layer.
// ---------------------------------------------------------------------------
__global__ __launch_bounds__(256, 3) void layer_mma_kernel(
    int flip,
    const float* __restrict__ Wg, const float* __restrict__ bg,
    const float* __restrict__ gamma, const float* __restrict__ beta)
{
    extern __shared__ char smem[];
    const uint32_t sb = smem_u32(smem);
    float* sPar = (float*)(smem + OFF_PAR);   // bg[128], gamma[128], beta[128]
    float* sS   = (float*)(smem + OFF_RED);   // [64][4] sum partials
    float* sQ   = sS + 256;                   // [64][4] sumsq partials

    const int tid = threadIdx.x, warp = tid >> 5, lane = tid & 31;
    const int mw = warp >> 2, nw = warp & 3;
    const int b = blockIdx.x >> 2, quarter = blockIdx.x & 3;
    const int rowbase0 = quarter * 225;

    const float*  Xin   = flip ? g_X1 : g_X0;
    float*        Xout  = flip ? g_X0 : g_X1;
    const __half* XinH  = flip ? g_XH1 : g_XH0;
    __half*       XoutH = flip ? g_XH0 : g_XH1;
    const float*  Xb   = Xin   + (size_t)b * NN * HID;
    float*        Xob  = Xout  + (size_t)b * NN * HID;
    const __half* XbH  = XinH  + (size_t)b * NN * HID;
    __half*       XobH = XoutH + (size_t)b * NN * HID;

    // --- stage LN params ---
    if (tid < 128) {
        sPar[tid]       = bg[tid];
        sPar[128 + tid] = gamma[tid];
        sPar[256 + tid] = beta[tid];
    }

    // --- stage W transposed+permuted to fp16: B[P(l)][k], 272B rows ---
    {
        const float4* W4 = (const float4*)Wg;
        #pragma unroll
        for (int i = 0; i < 16; i++) {
            int j = tid + 256 * i;          // float4 index over [128k][32]
            int k = j >> 5, n4 = (j & 31) * 4;
            float4 v = W4[j];
            #pragma unroll
            for (int u = 0; u < 4; u++) {
                int l = n4 + u;
                int li = l & 31;
                int P = (l & 96) + ((li & 7) >> 1) * 8 + (li >> 3) * 2 + (l & 1);
                __half h = __float2half_rn(f4get(v, u));
                *(__half*)(smem + OFF_B + (uint32_t)P * PITCHB
                           + (uint32_t)k * 2) = h;
            }
        }
    }
    __syncthreads();

    // lane-dependent ldmatrix base offsets
    const uint32_t aRow = (uint32_t)(mw * 32 + (lane & 15)) * PITCHB
                        + ((lane >> 4) & 1) * 16;
    const uint32_t aB0 = sb + OFF_A + aRow;
    const uint32_t aB1 = aB0 + 16 * PITCHB;
    uint32_t bOff[2];
    #pragma unroll
    for (int p = 0; p < 2; p++) {
        int n = nw * 32 + p * 16 + (lane & 7) + ((lane >> 4) & 1) * 8;
        bOff[p] = sb + OFF_B + (uint32_t)n * PITCHB + ((lane >> 3) & 1) * 16;
    }
    const int g = lane >> 2, tig = lane & 3;
    const int C0 = nw * 32 + tig * 8;   // this thread's 8 logical cols

    for (int t = 0; t < 4; t++) {
        const int base = rowbase0 + t * 64;
        const int nrows = min(64, 225 - t * 64);

        // --- stencil (table-driven, fp16 input) -> fp16 A ---
        #pragma unroll 4
        for (int s = 0; s < 8; s++) {
            int idx = tid + 256 * s;
            int r = idx >> 5, cg = idx & 31;
            uint32_t off = (uint32_t)r * PITCHB + (uint32_t)cg * 8;
            if (r < nrows) {
                int v = base + r;
                float4 cf = *(const float4*)(g_coef + v * 8);      // self,W,E,N
                float cfs = g_coef[v * 8 + 4];                     // S
                int4 ni = g_nidx[v];
                uint2 hs = *(const uint2*)(XbH + (size_t)v    * HID + cg * 4);
                uint2 hw = *(const uint2*)(XbH + (size_t)ni.x * HID + cg * 4);
                uint2 he = *(const uint2*)(XbH + (size_t)ni.y * HID + cg * 4);
                uint2 hn = *(const uint2*)(XbH + (size_t)ni.z * HID + cg * 4);
                uint2 ho = *(const uint2*)(XbH + (size_t)ni.w * HID + cg * 4);
                float2 s0 = h2f2(hs.x), s1 = h2f2(hs.y);
                float2 w0 = h2f2(hw.x), w1 = h2f2(hw.y);
                float2 e0 = h2f2(he.x), e1 = h2f2(he.y);
                float2 n0 = h2f2(hn.x), n1 = h2f2(hn.y);
                float2 o0 = h2f2(ho.x), o1 = h2f2(ho.y);
                float ax = cf.x * s0.x, ay = cf.x * s0.y;
                float az = cf.x * s1.x, aw = cf.x * s1.y;
                ax = fmaf(cf.y, w0.x, ax); ay = fmaf(cf.y, w0.y, ay);
                az = fmaf(cf.y, w1.x, az); aw = fmaf(cf.y, w1.y, aw);
                ax = fmaf(cf.z, e0.x, ax); ay = fmaf(cf.z, e0.y, ay);
                az = fmaf(cf.z, e1.x, az); aw = fmaf(cf.z, e1.y, aw);
                ax = fmaf(cf.w, n0.x, ax); ay = fmaf(cf.w, n0.y, ay);
                az = fmaf(cf.w, n1.x, az); aw = fmaf(cf.w, n1.y, aw);
                ax = fmaf(cfs, o0.x, ax); ay = fmaf(cfs, o0.y, ay);
                az = fmaf(cfs, o1.x, az); aw = fmaf(cfs, o1.y, aw);
                __half2 h01 = __floats2half2_rn(ax, ay);
                __half2 h23 = __floats2half2_rn(az, aw);
                *(uint2*)(smem + OFF_A + off) =
                    make_uint2(*(uint32_t*)&h01, *(uint32_t*)&h23);
            } else {
                *(uint2*)(smem + OFF_A + off) = make_uint2(0u, 0u);
            }
        }
        __syncthreads();

        // --- MMA mainloop: D = A @ B' (single fp16 pass, 32x32 warp tile) ---
        float acc[2][4][4];
        #pragma unroll
        for (int i = 0; i < 2; i++)
            #pragma unroll
            for (int nb = 0; nb < 4; nb++)
                #pragma unroll
                for (int j = 0; j < 4; j++) acc[i][nb][j] = 0.0f;

        #pragma unroll
        for (int ks = 0; ks < 8; ks++) {
            const uint32_t kb = (uint32_t)ks * 32;
            uint32_t a0[4], a1[4];
            ldsm4(aB0 + kb, a0[0], a0[1], a0[2], a0[3]);
            ldsm4(aB1 + kb, a1[0], a1[1], a1[2], a1[3]);
            uint32_t bh[4][2];
            #pragma unroll
            for (int p = 0; p < 2; p++) {
                ldsm4(bOff[p] + kb,
                      bh[2*p][0], bh[2*p][1], bh[2*p+1][0], bh[2*p+1][1]);
            }
            #pragma unroll
            for (int nb = 0; nb < 4; nb++) {
                mma_f16(acc[0][nb], a0, bh[nb]);
                mma_f16(acc[1][nb], a1, bh[nb]);
            }
        }

        // --- epilogue: bias add, LN partials (32 cols/warp), 4-way reduce ---
        float4 bi0 = *(float4*)(sPar + C0);
        float4 bi1 = *(float4*)(sPar + C0 + 4);
        #pragma unroll
        for (int i = 0; i < 2; i++) {
            #pragma unroll
            for (int h = 0; h < 2; h++) {
                int row = mw * 32 + i * 16 + g + 8 * h;
                float v0 = acc[i][0][2*h]   + bi0.x;
                float v1 = acc[i][0][2*h+1] + bi0.y;
                float v2 = acc[i][1][2*h]   + bi0.z;
                float v3 = acc[i][1][2*h+1] + bi0.w;
                float v4 = acc[i][2][2*h]   + bi1.x;
                float v5 = acc[i][2][2*h+1] + bi1.y;
                float v6 = acc[i][3][2*h]   + bi1.z;
                float v7 = acc[i][3][2*h+1] + bi1.w;
                acc[i][0][2*h] = v0; acc[i][0][2*h+1] = v1;
                acc[i][1][2*h] = v2; acc[i][1][2*h+1] = v3;
                acc[i][2][2*h] = v4; acc[i][2][2*h+1] = v5;
                acc[i][3][2*h] = v6; acc[i][3][2*h+1] = v7;
                float s = v0 + v1 + v2 + v3 + v4 + v5 + v6 + v7;
                float q = fmaf(v0, v0, fmaf(v1, v1, fmaf(v2, v2, v3 * v3)));
                q = fmaf(v4, v4, fmaf(v5, v5, fmaf(v6, v6, fmaf(v7, v7, q))));
                s += __shfl_xor_sync(0xffffffffu, s, 1);
                s += __shfl_xor_sync(0xffffffffu, s, 2);
                q += __shfl_xor_sync(0xffffffffu, q, 1);
                q += __shfl_xor_sync(0xffffffffu, q, 2);
                if (tig == 0) { sS[row * 4 + nw] = s; sQ[row * 4 + nw] = q; }
            }
        }
        __syncthreads();

        #pragma unroll
        for (int i = 0; i < 2; i++) {
            #pragma unroll
            for (int h = 0; h < 2; h++) {
                int row = mw * 32 + i * 16 + g + 8 * h;
                float4 sv = *(float4*)(sS + row * 4);
                float4 qv = *(float4*)(sQ + row * 4);
                float s = (sv.x + sv.y) + (sv.z + sv.w);
                float q = (qv.x + qv.y) + (qv.z + qv.w);
                float mean = s * (1.0f / HID);
                float var  = q * (1.0f / HID) - mean * mean;
                float rstd = rsqrtf(var + 1e-5f);
                if (row < nrows) {   // quad-uniform
                    int v = base + row;
                    const float* xr = Xb + (size_t)v * HID + C0;
                    float*       xo = Xob + (size_t)v * HID + C0;
                    float4 gm0 = *(float4*)(sPar + 128 + C0);
                    float4 gm1 = *(float4*)(sPar + 128 + C0 + 4);
                    float4 bt0 = *(float4*)(sPar + 256 + C0);
                    float4 bt1 = *(float4*)(sPar + 256 + C0 + 4);
                    float4 xv0 = *(const float4*)(xr);
                    float4 xv1 = *(const float4*)(xr + 4);
                    float4 o0, o1;
                    o0.x = fmaxf((acc[i][0][2*h]   - mean) * rstd * gm0.x + bt0.x, 0.0f) + xv0.x;
                    o0.y = fmaxf((acc[i][0][2*h+1] - mean) * rstd * gm0.y + bt0.y, 0.0f) + xv0.y;
                    o0.z = fmaxf((acc[i][1][2*h]   - mean) * rstd * gm0.z + bt0.z, 0.0f) + xv0.z;
                    o0.w = fmaxf((acc[i][1][2*h+1] - mean) * rstd * gm0.w + bt0.w, 0.0f) + xv0.w;
                    o1.x = fmaxf((acc[i][2][2*h]   - mean) * rstd * gm1.x + bt1.x, 0.0f) + xv1.x;
                    o1.y = fmaxf((acc[i][2][2*h+1] - mean) * rstd * gm1.y + bt1.y, 0.0f) + xv1.y;
                    o1.z = fmaxf((acc[i][3][2*h]   - mean) * rstd * gm1.z + bt1.z, 0.0f) + xv1.z;
                    o1.w = fmaxf((acc[i][3][2*h+1] - mean) * rstd * gm1.w + bt1.w, 0.0f) + xv1.w;
                    *(float4*)(xo)     = o0;
                    *(float4*)(xo + 4) = o1;
                    __half2 ha = __floats2half2_rn(o0.x, o0.y);
                    __half2 hb = __floats2half2_rn(o0.z, o0.w);
                    __half2 hc = __floats2half2_rn(o1.x, o1.y);
                    __half2 hd = __floats2half2_rn(o1.z, o1.w);
                    *(uint4*)(XobH + (size_t)v * HID + C0) =
                        make_uint4(*(uint32_t*)&ha, *(uint32_t*)&hb,
                                   *(uint32_t*)&hc, *(uint32_t*)&hd);
                }
            }
        }
        __syncthreads();
    }
}

// ---------------------------------------------------------------------------
// out = x @ Wout + bout via single-pass fp16 HMMA; reads fp16 shadow of x.
// CTA = (batch, half), 256 threads; loops 8 tiles of 64 rows.
// Column permutation: logical l = tig*8 + nb*2 + e per 32-block.
// ---------------------------------------------------------------------------
__global__ __launch_bounds__(256, 4) void out_mma_kernel(
    const float* __restrict__ Wout, const float* __restrict__ bout,
    float* __restrict__ out)
{
    extern __shared__ char smem[];
    const uint32_t sb = smem_u32(smem);
    float* sPar = (float*)(smem + OOFF_PAR);   // bout[64]

    const int tid = threadIdx.x, warp = tid >> 5, lane = tid & 31;
    const int mw = warp >> 1, nw = warp & 1;
    const int b = blockIdx.x >> 1, half = blockIdx.x & 1;
    const int rowbase0 = half * 450;
    const __half* XbH = g_XH0 + (size_t)b * NN * HID;

    if (tid < 64) sPar[tid] = bout[tid];

    // --- stage Wout transposed+permuted to fp16: B[P(l)][k], 272B rows ---
    {
        const float4* W4 = (const float4*)Wout;   // [128k][16]
        #pragma unroll
        for (int i = 0; i < 8; i++) {
            int j = tid + 256 * i;
            int k = j >> 4, n4 = (j & 15) * 4;
            float4 v = W4[j];
            #pragma unroll
            for (int u = 0; u < 4; u++) {
                int l = n4 + u;
                int li = l & 31;
                int P = (l & 32) + ((li & 7) >> 1) * 8 + (li >> 3) * 2 + (l & 1);
                __half h = __float2half_rn(f4get(v, u));
                *(__half*)(smem + OOFF_B + (uint32_t)P * PITCHB
                           + (uint32_t)k * 2) = h;
            }
        }
    }
    __syncthreads();

    const uint32_t aRow = (uint32_t)(mw * 16 + (lane & 15)) * PITCHB
                        + ((lane >> 4) & 1) * 16;
    const uint32_t aB = sb + OOFF_A + aRow;
    uint32_t bOff[2];
    #pragma unroll
    for (int p = 0; p < 2; p++) {
        int n = nw * 32 + p * 16 + (lane & 7) + ((lane >> 4) & 1) * 8;
        bOff[p] = sb + OOFF_B + (uint32_t)n * PITCHB + ((lane >> 3) & 1) * 16;
    }
    const int g = lane >> 2, tig = lane & 3;

    for (int t = 0; t < 8; t++) {
        const int base = rowbase0 + t * 64;
        const int nrows = min(64, 450 - t * 64);

        // --- A = fp16 shadow copy (no conversion needed) ---
        #pragma unroll 4
        for (int s = 0; s < 8; s++) {
            int idx = tid + 256 * s;
            int r = idx >> 5, cg = idx & 31;
            uint32_t off = (uint32_t)r * PITCHB + (uint32_t)cg * 8;
            if (r < nrows) {
                *(uint2*)(smem + OOFF_A + off) =
                    *(const uint2*)(XbH + (size_t)(base + r) * HID + cg * 4);
            } else {
                *(uint2*)(smem + OOFF_A + off) = make_uint2(0u, 0u);
            }
        }
        __syncthreads();

        float acc[4][4];
        #pragma unroll
        for (int nb = 0; nb < 4; nb++)
            #pragma unroll
            for (int j = 0; j < 4; j++) acc[nb][j] = 0.0f;

        #pragma unroll
        for (int ks = 0; ks < 8; ks++) {
            const uint32_t kb = (uint32_t)ks * 32;
            uint32_t a[4];
            ldsm4(aB + kb, a[0], a[1], a[2], a[3]);
            uint32_t bh[4][2];
            #pragma unroll
            for (int p = 0; p < 2; p++) {
                ldsm4(bOff[p] + kb,
                      bh[2*p][0], bh[2*p][1], bh[2*p+1][0], bh[2*p+1][1]);
            }
            #pragma unroll
            for (int nb = 0; nb < 4; nb++)
                mma_f16(acc[nb], a, bh[nb]);
        }

        #pragma unroll
        for (int h = 0; h < 2; h++) {
            int row = mw * 16 + g + 8 * h;
            if (row < nrows) {   // quad-uniform
                float* op = out + ((size_t)b * NN + base + row) * OUTD;
                #pragma unroll
                for (int j = 0; j < 2; j++) {
                    int C = nw * 32 + tig * 8 + 4 * j;
                    float4 bo = *(float4*)(sPar + C);
                    float4 o;
                    o.x = acc[2*j][2*h]     + bo.x;
                    o.y = acc[2*j][2*h+1]   + bo.y;
                    o.z = acc[2*j+1][2*h]   + bo.z;
                    o.w = acc[2*j+1][2*h+1] + bo.w;
                    *(float4*)(op + C) = o;
                }
            }
        }
        __syncthreads();
    }
}

// ---------------------------------------------------------------------------
extern "C" void kernel_launch(void* const* d_in, const int* in_sizes, int n_in,
                              void* d_out, int out_size) {
    const int*   grids = (const int*)d_in[0];
    // d_in[1] = edge_index: fixed 30x30 4-connected grid; precomputed tables.
    const float* Win   = (const float*)d_in[2];
    const float* bin   = (const float*)d_in[3];
    const float* Wg    = (const float*)d_in[4];
    const float* bg    = (const float*)d_in[5];
    const float* gamma = (const float*)d_in[6];
    const float* beta  = (const float*)d_in[7];
    const float* Wout  = (const float*)d_in[8];
    const float* bout  = (const float*)d_in[9];
    float* out = (float*)d_out;
    (void)in_sizes; (void)n_in; (void)out_size;

    cudaFuncSetAttribute((const void*)layer_mma_kernel,
                         cudaFuncAttributeMaxDynamicSharedMemorySize, SMEM_MMA);
    cudaFuncSetAttribute((const void*)out_mma_kernel,
                         cudaFuncAttributeMaxDynamicSharedMemorySize, SMEM_OUT);

    init_tables_kernel<<<4, 256>>>();
    encode_kernel<<<(NB * NN * 32) / 256, 256>>>(grids, Win, bin);
    for (int i = 0; i < 4; i++) {
        layer_mma_kernel<<<NB * 4, 256, SMEM_MMA>>>(
            i & 1, Wg + (size_t)i * HID * HID, bg + i * HID,
            gamma + i * HID, beta + i * HID);
    }
    out_mma_kernel<<<NB * 2, 256, SMEM_OUT>>>(Wout, bout, out);
}

// round 12
// speedup vs baseline: 4.6009x; 1.3053x over previous
#include <cuda_runtime.h>
#include <cuda_fp16.h>
#include <cstdint>

#define NB   512
#define GH   30
#define GW   30
#define NN   900
#define HID  128
#define OUTD 64

// Activations live ONLY in fp16 (ping-pong); residual path fp32 in registers.
__device__ __half g_XH0[(size_t)NB * NN * HID];
__device__ __half g_XH1[(size_t)NB * NN * HID];
// Precomputed graph tables (fixed 30x30 4-connected grid + self loops)
__device__ float g_coef[NN * 8];   // [v]: self, W, E, N, S, pad...
__device__ int4  g_nidx[NN];       // [v]: clamped W, E, N, S indices

// smem byte offsets for layer_mma_kernel (fp16 matrices, 136-elem = 272B rows)
#define PITCHB 272
#define OFF_B   0
#define OFF_A   34816
#define OFF_PAR 52224
#define OFF_RED 53760
#define SMEM_MMA 55808

// smem offsets for out_mma_kernel
#define OOFF_B   0
#define OOFF_A   17408
#define OOFF_PAR 34816
#define SMEM_OUT 35072

__device__ __forceinline__ uint32_t smem_u32(const void* p) {
    uint32_t a;
    asm("{ .reg .u64 t; cvta.to.shared.u64 t, %1; cvt.u32.u64 %0, t; }" : "=r"(a) : "l"(p));
    return a;
}
__device__ __forceinline__ float dinv_rc(int rp, int cp) {
    int d = 1 + (rp > 0) + (rp < GH - 1) + (cp > 0) + (cp < GW - 1);
    return rsqrtf((float)d);
}
__device__ __forceinline__ float f4get(const float4& v, int i) {
    return i == 0 ? v.x : i == 1 ? v.y : i == 2 ? v.z : v.w;
}
__device__ __forceinline__ void ldsm4(uint32_t addr, uint32_t& r0, uint32_t& r1,
                                      uint32_t& r2, uint32_t& r3) {
    asm volatile("ldmatrix.sync.aligned.m8n8.x4.shared.b16 {%0,%1,%2,%3}, [%4];"
                 : "=r"(r0), "=r"(r1), "=r"(r2), "=r"(r3) : "r"(addr));
}
__device__ __forceinline__ void mma_f16(float* d, const uint32_t* a, const uint32_t* b) {
    asm volatile("mma.sync.aligned.m16n8k16.row.col.f32.f16.f16.f32 "
                 "{%0,%1,%2,%3}, {%4,%5,%6,%7}, {%8,%9}, {%0,%1,%2,%3};"
                 : "+f"(d[0]), "+f"(d[1]), "+f"(d[2]), "+f"(d[3])
                 : "r"(a[0]), "r"(a[1]), "r"(a[2]), "r"(a[3]), "r"(b[0]), "r"(b[1]));
}
// fp32x2 from a half2 word
__device__ __forceinline__ float2 h2f2(uint32_t h) {
    return __half22float2(*(__half2*)&h);
}

// ---------------------------------------------------------------------------
// init: precompute normalized stencil coefficients + clamped neighbor indices
// ---------------------------------------------------------------------------
__global__ void init_tables_kernel() {
    int v = threadIdx.x + blockIdx.x * 256;
    if (v < NN) {
        int r = v / GW, c = v - (v / GW) * GW;
        float dv = dinv_rc(r, c);
        float w = (c > 0)      ? dinv_rc(r, c - 1) : 0.0f;
        float e = (c < GW - 1) ? dinv_rc(r, c + 1) : 0.0f;
        float n = (r > 0)      ? dinv_rc(r - 1, c) : 0.0f;
        float s = (r < GH - 1) ? dinv_rc(r + 1, c) : 0.0f;
        float4* cf = (float4*)(g_coef + v * 8);
        cf[0] = make_float4(dv * dv, dv * w, dv * e, dv * n);
        cf[1] = make_float4(dv * s, 0.0f, 0.0f, 0.0f);
        g_nidx[v] = make_int4((c > 0) ? v - 1 : v, (c < GW - 1) ? v + 1 : v,
                              (r > 0) ? v - GW : v, (r < GH - 1) ? v + GW : v);
    }
}

// ---------------------------------------------------------------------------
// x0 = relu(onehot(color)@Win + pr*Win[10] + pc*Win[11] + bin) -> fp16
// ---------------------------------------------------------------------------
__global__ __launch_bounds__(256) void encode_kernel(
    const int* __restrict__ grids, const float* __restrict__ Win,
    const float* __restrict__ bin)
{
    __shared__ float4 sW[12 * 32];
    __shared__ float4 sB[32];
    const int tid = threadIdx.x;
    for (int i = tid; i < 384; i += 256) sW[i] = ((const float4*)Win)[i];
    if (tid < 32) sB[tid] = ((const float4*)bin)[tid];
    __syncthreads();

    long long idx = (long long)blockIdx.x * 256 + tid;
    int cg = (int)(idx & 31);
    long long bn = idx >> 5;
    int n = (int)(bn % NN);
    int color = grids[bn];
    float pr = (float)(n / GW) * (1.0f / (GH - 1));
    float pc = (float)(n % GW) * (1.0f / (GW - 1));
    float4 wc = sW[color * 32 + cg];
    float4 wr = sW[10 * 32 + cg];
    float4 wp = sW[11 * 32 + cg];
    float4 bb = sB[cg];
    float4 o;
    o.x = fmaxf(fmaf(pc, wp.x, fmaf(pr, wr.x, wc.x + bb.x)), 0.0f);
    o.y = fmaxf(fmaf(pc, wp.y, fmaf(pr, wr.y, wc.y + bb.y)), 0.0f);
    o.z = fmaxf(fmaf(pc, wp.z, fmaf(pr, wr.z, wc.z + bb.z)), 0.0f);
    o.w = fmaxf(fmaf(pc, wp.w, fmaf(pr, wr.w, wc.w + bb.w)), 0.0f);
    __half2 h01 = __floats2half2_rn(o.x, o.y);
    __half2 h23 = __floats2half2_rn(o.z, o.w);
    ((uint2*)g_XH0)[idx] = make_uint2(*(uint32_t*)&h01, *(uint32_t*)&h23);
}

// ---------------------------------------------------------------------------
// Tensor-core (HMMA) GCN layer, single-pass fp16: D = fp16(Ahat@x16) @ fp16(W).
// Activations fp16-resident; LN math + accumulators fp32 in registers.
// CTA = (batch, quarter), 256 threads, 3 CTAs/SM; loops 4 tiles (3x64 + 33).
// Warp tile 32x32 (mw=warp>>2, nw=warp&3); B cols permuted so each thread
// owns 8 consecutive logical cols -> uint4-coalesced fp16 epilogue.
// ---------------------------------------------------------------------------
__global__ __launch_bounds__(256, 3) void layer_mma_kernel(
    int flip,
    const float* __restrict__ Wg, const float* __restrict__ bg,
    const float* __restrict__ gamma, const float* __restrict__ beta)
{
    extern __shared__ char smem[];
    const uint32_t sb = smem_u32(smem);
    float* sPar = (float*)(smem + OFF_PAR);   // bg[128], gamma[128], beta[128]
    float* sS   = (float*)(smem + OFF_RED);   // [64][4] sum partials
    float* sQ   = sS + 256;                   // [64][4] sumsq partials

    const int tid = threadIdx.x, warp = tid >> 5, lane = tid & 31;
    const int mw = warp >> 2, nw = warp & 3;
    const int b = blockIdx.x >> 2, quarter = blockIdx.x & 3;
    const int rowbase0 = quarter * 225;

    const __half* XinH  = flip ? g_XH1 : g_XH0;
    __half*       XoutH = flip ? g_XH0 : g_XH1;
    const __half* XbH  = XinH  + (size_t)b * NN * HID;
    __half*       XobH = XoutH + (size_t)b * NN * HID;

    // --- stage LN params ---
    if (tid < 128) {
        sPar[tid]       = bg[tid];
        sPar[128 + tid] = gamma[tid];
        sPar[256 + tid] = beta[tid];
    }

    // --- stage W transposed+permuted to fp16: B[P(l)][k], 272B rows ---
    {
        const float4* W4 = (const float4*)Wg;
        #pragma unroll
        for (int i = 0; i < 16; i++) {
            int j = tid + 256 * i;          // float4 index over [128k][32]
            int k = j >> 5, n4 = (j & 31) * 4;
            float4 v = W4[j];
            #pragma unroll
            for (int u = 0; u < 4; u++) {
                int l = n4 + u;
                int li = l & 31;
                int P = (l & 96) + ((li & 7) >> 1) * 8 + (li >> 3) * 2 + (l & 1);
                __half h = __float2half_rn(f4get(v, u));
                *(__half*)(smem + OFF_B + (uint32_t)P * PITCHB
                           + (uint32_t)k * 2) = h;
            }
        }
    }
    __syncthreads();

    // lane-dependent ldmatrix base offsets
    const uint32_t aRow = (uint32_t)(mw * 32 + (lane & 15)) * PITCHB
                        + ((lane >> 4) & 1) * 16;
    const uint32_t aB0 = sb + OFF_A + aRow;
    const uint32_t aB1 = aB0 + 16 * PITCHB;
    uint32_t bOff[2];
    #pragma unroll
    for (int p = 0; p < 2; p++) {
        int n = nw * 32 + p * 16 + (lane & 7) + ((lane >> 4) & 1) * 8;
        bOff[p] = sb + OFF_B + (uint32_t)n * PITCHB + ((lane >> 3) & 1) * 16;
    }
    const int g = lane >> 2, tig = lane & 3;
    const int C0 = nw * 32 + tig * 8;   // this thread's 8 logical cols

    for (int t = 0; t < 4; t++) {
        const int base = rowbase0 + t * 64;
        const int nrows = min(64, 225 - t * 64);

        // --- stencil (table-driven, fp16 input) -> fp16 A ---
        #pragma unroll 4
        for (int s = 0; s < 8; s++) {
            int idx = tid + 256 * s;
            int r = idx >> 5, cg = idx & 31;
            uint32_t off = (uint32_t)r * PITCHB + (uint32_t)cg * 8;
            if (r < nrows) {
                int v = base + r;
                float4 cf = *(const float4*)(g_coef + v * 8);      // self,W,E,N
                float cfs = g_coef[v * 8 + 4];                     // S
                int4 ni = g_nidx[v];
                uint2 hs = *(const uint2*)(XbH + (size_t)v    * HID + cg * 4);
                uint2 hw = *(const uint2*)(XbH + (size_t)ni.x * HID + cg * 4);
                uint2 he = *(const uint2*)(XbH + (size_t)ni.y * HID + cg * 4);
                uint2 hn = *(const uint2*)(XbH + (size_t)ni.z * HID + cg * 4);
                uint2 ho = *(const uint2*)(XbH + (size_t)ni.w * HID + cg * 4);
                float2 s0 = h2f2(hs.x), s1 = h2f2(hs.y);
                float2 w0 = h2f2(hw.x), w1 = h2f2(hw.y);
                float2 e0 = h2f2(he.x), e1 = h2f2(he.y);
                float2 n0 = h2f2(hn.x), n1 = h2f2(hn.y);
                float2 o0 = h2f2(ho.x), o1 = h2f2(ho.y);
                float ax = cf.x * s0.x, ay = cf.x * s0.y;
                float az = cf.x * s1.x, aw = cf.x * s1.y;
                ax = fmaf(cf.y, w0.x, ax); ay = fmaf(cf.y, w0.y, ay);
                az = fmaf(cf.y, w1.x, az); aw = fmaf(cf.y, w1.y, aw);
                ax = fmaf(cf.z, e0.x, ax); ay = fmaf(cf.z, e0.y, ay);
                az = fmaf(cf.z, e1.x, az); aw = fmaf(cf.z, e1.y, aw);
                ax = fmaf(cf.w, n0.x, ax); ay = fmaf(cf.w, n0.y, ay);
                az = fmaf(cf.w, n1.x, az); aw = fmaf(cf.w, n1.y, aw);
                ax = fmaf(cfs, o0.x, ax); ay = fmaf(cfs, o0.y, ay);
                az = fmaf(cfs, o1.x, az); aw = fmaf(cfs, o1.y, aw);
                __half2 h01 = __floats2half2_rn(ax, ay);
                __half2 h23 = __floats2half2_rn(az, aw);
                *(uint2*)(smem + OFF_A + off) =
                    make_uint2(*(uint32_t*)&h01, *(uint32_t*)&h23);
            } else {
                *(uint2*)(smem + OFF_A + off) = make_uint2(0u, 0u);
            }
        }
        __syncthreads();

        // --- MMA mainloop: D = A @ B' (single fp16 pass, 32x32 warp tile) ---
        float acc[2][4][4];
        #pragma unroll
        for (int i = 0; i < 2; i++)
            #pragma unroll
            for (int nb = 0; nb < 4; nb++)
                #pragma unroll
                for (int j = 0; j < 4; j++) acc[i][nb][j] = 0.0f;

        #pragma unroll
        for (int ks = 0; ks < 8; ks++) {
            const uint32_t kb = (uint32_t)ks * 32;
            uint32_t a0[4], a1[4];
            ldsm4(aB0 + kb, a0[0], a0[1], a0[2], a0[3]);
            ldsm4(aB1 + kb, a1[0], a1[1], a1[2], a1[3]);
            uint32_t bh[4][2];
            #pragma unroll
            for (int p = 0; p < 2; p++) {
                ldsm4(bOff[p] + kb,
                      bh[2*p][0], bh[2*p][1], bh[2*p+1][0], bh[2*p+1][1]);
            }
            #pragma unroll
            for (int nb = 0; nb < 4; nb++) {
                mma_f16(acc[0][nb], a0, bh[nb]);
                mma_f16(acc[1][nb], a1, bh[nb]);
            }
        }

        // --- epilogue: bias add, LN partials (32 cols/warp), 4-way reduce ---
        float4 bi0 = *(float4*)(sPar + C0);
        float4 bi1 = *(float4*)(sPar + C0 + 4);
        #pragma unroll
        for (int i = 0; i < 2; i++) {
            #pragma unroll
            for (int h = 0; h < 2; h++) {
                int row = mw * 32 + i * 16 + g + 8 * h;
                float v0 = acc[i][0][2*h]   + bi0.x;
                float v1 = acc[i][0][2*h+1] + bi0.y;
                float v2 = acc[i][1][2*h]   + bi0.z;
                float v3 = acc[i][1][2*h+1] + bi0.w;
                float v4 = acc[i][2][2*h]   + bi1.x;
                float v5 = acc[i][2][2*h+1] + bi1.y;
                float v6 = acc[i][3][2*h]   + bi1.z;
                float v7 = acc[i][3][2*h+1] + bi1.w;
                acc[i][0][2*h] = v0; acc[i][0][2*h+1] = v1;
                acc[i][1][2*h] = v2; acc[i][1][2*h+1] = v3;
                acc[i][2][2*h] = v4; acc[i][2][2*h+1] = v5;
                acc[i][3][2*h] = v6; acc[i][3][2*h+1] = v7;
                float s = v0 + v1 + v2 + v3 + v4 + v5 + v6 + v7;
                float q = fmaf(v0, v0, fmaf(v1, v1, fmaf(v2, v2, v3 * v3)));
                q = fmaf(v4, v4, fmaf(v5, v5, fmaf(v6, v6, fmaf(v7, v7, q))));
                s += __shfl_xor_sync(0xffffffffu, s, 1);
                s += __shfl_xor_sync(0xffffffffu, s, 2);
                q += __shfl_xor_sync(0xffffffffu, q, 1);
                q += __shfl_xor_sync(0xffffffffu, q, 2);
                if (tig == 0) { sS[row * 4 + nw] = s; sQ[row * 4 + nw] = q; }
            }
        }
        __syncthreads();

        #pragma unroll
        for (int i = 0; i < 2; i++) {
            #pragma unroll
            for (int h = 0; h < 2; h++) {
                int row = mw * 32 + i * 16 + g + 8 * h;
                float4 sv = *(float4*)(sS + row * 4);
                float4 qv = *(float4*)(sQ + row * 4);
                float s = (sv.x + sv.y) + (sv.z + sv.w);
                float q = (qv.x + qv.y) + (qv.z + qv.w);
                float mean = s * (1.0f / HID);
                float var  = q * (1.0f / HID) - mean * mean;
                float rstd = rsqrtf(var + 1e-5f);
                if (row < nrows) {   // quad-uniform
                    int v = base + row;
                    float4 gm0 = *(float4*)(sPar + 128 + C0);
                    float4 gm1 = *(float4*)(sPar + 128 + C0 + 4);
                    float4 bt0 = *(float4*)(sPar + 256 + C0);
                    float4 bt1 = *(float4*)(sPar + 256 + C0 + 4);
                    // fp16 residual read (8 halves)
                    uint4 xh = *(const uint4*)(XbH + (size_t)v * HID + C0);
                    float2 xa = h2f2(xh.x), xb2 = h2f2(xh.y);
                    float2 xc = h2f2(xh.z), xd = h2f2(xh.w);
                    float o0 = fmaxf((acc[i][0][2*h]   - mean) * rstd * gm0.x + bt0.x, 0.0f) + xa.x;
                    float o1 = fmaxf((acc[i][0][2*h+1] - mean) * rstd * gm0.y + bt0.y, 0.0f) + xa.y;
                    float o2 = fmaxf((acc[i][1][2*h]   - mean) * rstd * gm0.z + bt0.z, 0.0f) + xb2.x;
                    float o3 = fmaxf((acc[i][1][2*h+1] - mean) * rstd * gm0.w + bt0.w, 0.0f) + xb2.y;
                    float o4 = fmaxf((acc[i][2][2*h]   - mean) * rstd * gm1.x + bt1.x, 0.0f) + xc.x;
                    float o5 = fmaxf((acc[i][2][2*h+1] - mean) * rstd * gm1.y + bt1.y, 0.0f) + xc.y;
                    float o6 = fmaxf((acc[i][3][2*h]   - mean) * rstd * gm1.z + bt1.z, 0.0f) + xd.x;
                    float o7 = fmaxf((acc[i][3][2*h+1] - mean) * rstd * gm1.w + bt1.w, 0.0f) + xd.y;
                    __half2 ha = __floats2half2_rn(o0, o1);
                    __half2 hb = __floats2half2_rn(o2, o3);
                    __half2 hc = __floats2half2_rn(o4, o5);
                    __half2 hd = __floats2half2_rn(o6, o7);
                    *(uint4*)(XobH + (size_t)v * HID + C0) =
                        make_uint4(*(uint32_t*)&ha, *(uint32_t*)&hb,
                                   *(uint32_t*)&hc, *(uint32_t*)&hd);
                }
            }
        }
        __syncthreads();
    }
}

// ---------------------------------------------------------------------------
// out = x @ Wout + bout via single-pass fp16 HMMA; reads fp16 x.
// CTA = (batch, half), 256 threads; loops 8 tiles of 64 rows.
// Column permutation: logical l = tig*8 + nb*2 + e per 32-block.
// ---------------------------------------------------------------------------
__global__ __launch_bounds__(256, 4) void out_mma_kernel(
    const float* __restrict__ Wout, const float* __restrict__ bout,
    float* __restrict__ out)
{
    extern __shared__ char smem[];
    const uint32_t sb = smem_u32(smem);
    float* sPar = (float*)(smem + OOFF_PAR);   // bout[64]

    const int tid = threadIdx.x, warp = tid >> 5, lane = tid & 31;
    const int mw = warp >> 1, nw = warp & 1;
    const int b = blockIdx.x >> 1, half = blockIdx.x & 1;
    const int rowbase0 = half * 450;
    const __half* XbH = g_XH0 + (size_t)b * NN * HID;

    if (tid < 64) sPar[tid] = bout[tid];

    // --- stage Wout transposed+permuted to fp16: B[P(l)][k], 272B rows ---
    {
        const float4* W4 = (const float4*)Wout;   // [128k][16]
        #pragma unroll
        for (int i = 0; i < 8; i++) {
            int j = tid + 256 * i;
            int k = j >> 4, n4 = (j & 15) * 4;
            float4 v = W4[j];
            #pragma unroll
            for (int u = 0; u < 4; u++) {
                int l = n4 + u;
                int li = l & 31;
                int P = (l & 32) + ((li & 7) >> 1) * 8 + (li >> 3) * 2 + (l & 1);
                __half h = __float2half_rn(f4get(v, u));
                *(__half*)(smem + OOFF_B + (uint32_t)P * PITCHB
                           + (uint32_t)k * 2) = h;
            }
        }
    }
    __syncthreads();

    const uint32_t aRow = (uint32_t)(mw * 16 + (lane & 15)) * PITCHB
                        + ((lane >> 4) & 1) * 16;
    const uint32_t aB = sb + OOFF_A + aRow;
    uint32_t bOff[2];
    #pragma unroll
    for (int p = 0; p < 2; p++) {
        int n = nw * 32 + p * 16 + (lane & 7) + ((lane >> 4) & 1) * 8;
        bOff[p] = sb + OOFF_B + (uint32_t)n * PITCHB + ((lane >> 3) & 1) * 16;
    }
    const int g = lane >> 2, tig = lane & 3;

    for (int t = 0; t < 8; t++) {
        const int base = rowbase0 + t * 64;
        const int nrows = min(64, 450 - t * 64);

        // --- A = fp16 x (no conversion needed) ---
        #pragma unroll 4
        for (int s = 0; s < 8; s++) {
            int idx = tid + 256 * s;
            int r = idx >> 5, cg = idx & 31;
            uint32_t off = (uint32_t)r * PITCHB + (uint32_t)cg * 8;
            if (r < nrows) {
                *(uint2*)(smem + OOFF_A + off) =
                    *(const uint2*)(XbH + (size_t)(base + r) * HID + cg * 4);
            } else {
                *(uint2*)(smem + OOFF_A + off) = make_uint2(0u, 0u);
            }
        }
        __syncthreads();

        float acc[4][4];
        #pragma unroll
        for (int nb = 0; nb < 4; nb++)
            #pragma unroll
            for (int j = 0; j < 4; j++) acc[nb][j] = 0.0f;

        #pragma unroll
        for (int ks = 0; ks < 8; ks++) {
            const uint32_t kb = (uint32_t)ks * 32;
            uint32_t a[4];
            ldsm4(aB + kb, a[0], a[1], a[2], a[3]);
            uint32_t bh[4][2];
            #pragma unroll
            for (int p = 0; p < 2; p++) {
                ldsm4(bOff[p] + kb,
                      bh[2*p][0], bh[2*p][1], bh[2*p+1][0], bh[2*p+1][1]);
            }
            #pragma unroll
            for (int nb = 0; nb < 4; nb++)
                mma_f16(acc[nb], a, bh[nb]);
        }

        #pragma unroll
        for (int h = 0; h < 2; h++) {
            int row = mw * 16 + g + 8 * h;
            if (row < nrows) {   // quad-uniform
                float* op = out + ((size_t)b * NN + base + row) * OUTD;
                #pragma unroll
                for (int j = 0; j < 2; j++) {
                    int C = nw * 32 + tig * 8 + 4 * j;
                    float4 bo = *(float4*)(sPar + C);
                    float4 o;
                    o.x = acc[2*j][2*h]     + bo.x;
                    o.y = acc[2*j][2*h+1]   + bo.y;
                    o.z = acc[2*j+1][2*h]   + bo.z;
                    o.w = acc[2*j+1][2*h+1] + bo.w;
                    *(float4*)(op + C) = o;
                }
            }
        }
        __syncthreads();
    }
}

// ---------------------------------------------------------------------------
extern "C" void kernel_launch(void* const* d_in, const int* in_sizes, int n_in,
                              void* d_out, int out_size) {
    const int*   grids = (const int*)d_in[0];
    // d_in[1] = edge_index: fixed 30x30 4-connected grid; precomputed tables.
    const float* Win   = (const float*)d_in[2];
    const float* bin   = (const float*)d_in[3];
    const float* Wg    = (const float*)d_in[4];
    const float* bg    = (const float*)d_in[5];
    const float* gamma = (const float*)d_in[6];
    const float* beta  = (const float*)d_in[7];
    const float* Wout  = (const float*)d_in[8];
    const float* bout  = (const float*)d_in[9];
    float* out = (float*)d_out;
    (void)in_sizes; (void)n_in; (void)out_size;

    cudaFuncSetAttribute((const void*)layer_mma_kernel,
                         cudaFuncAttributeMaxDynamicSharedMemorySize, SMEM_MMA);
    cudaFuncSetAttribute((const void*)out_mma_kernel,
                         cudaFuncAttributeMaxDynamicSharedMemorySize, SMEM_OUT);

    init_tables_kernel<<<4, 256>>>();
    encode_kernel<<<(NB * NN * 32) / 256, 256>>>(grids, Win, bin);
    for (int i = 0; i < 4; i++) {
        layer_mma_kernel<<<NB * 4, 256, SMEM_MMA>>>(
            i & 1, Wg + (size_t)i * HID * HID, bg + i * HID,
            gamma + i * HID, beta + i * HID);
    }
    out_mma_kernel<<<NB * 2, 256, SMEM_OUT>>>(Wout, bout, out);
}

// round 13
// speedup vs baseline: 4.9541x; 1.0768x over previous
#include <cuda_runtime.h>
#include <cuda_fp16.h>
#include <cstdint>

#define NB   512
#define GH   30
#define GW   30
#define NN   900
#define HID  128
#define OUTD 64

// Activations live ONLY in fp16 (ping-pong); LN/residual math fp32 in registers.
__device__ __half g_XH0[(size_t)NB * NN * HID];
__device__ __half g_XH1[(size_t)NB * NN * HID];
// Precomputed graph tables (fixed 30x30 4-connected grid + self loops)
__device__ float g_coef[NN * 8];   // [v]: self, W, E, N, S, pad...
__device__ int4  g_nidx[NN];       // [v]: clamped W, E, N, S indices

// smem byte offsets (fp16 matrices, 136-elem = 272B rows)
#define PITCHB 272
#define OFF_B    0
#define OFF_A    34816
#define OFF_PAR  52224
#define OFF_RED  53760
#define SMEM_MMA 55808
// fused-out extras
#define OFF_WO   55808
#define OFF_BOUT 73216
#define SMEM_FUSED 73472

__device__ __forceinline__ uint32_t smem_u32(const void* p) {
    uint32_t a;
    asm("{ .reg .u64 t; cvta.to.shared.u64 t, %1; cvt.u32.u64 %0, t; }" : "=r"(a) : "l"(p));
    return a;
}
__device__ __forceinline__ float dinv_rc(int rp, int cp) {
    int d = 1 + (rp > 0) + (rp < GH - 1) + (cp > 0) + (cp < GW - 1);
    return rsqrtf((float)d);
}
__device__ __forceinline__ float f4get(const float4& v, int i) {
    return i == 0 ? v.x : i == 1 ? v.y : i == 2 ? v.z : v.w;
}
__device__ __forceinline__ void ldsm4(uint32_t addr, uint32_t& r0, uint32_t& r1,
                                      uint32_t& r2, uint32_t& r3) {
    asm volatile("ldmatrix.sync.aligned.m8n8.x4.shared.b16 {%0,%1,%2,%3}, [%4];"
                 : "=r"(r0), "=r"(r1), "=r"(r2), "=r"(r3) : "r"(addr));
}
__device__ __forceinline__ void mma_f16(float* d, const uint32_t* a, const uint32_t* b) {
    asm volatile("mma.sync.aligned.m16n8k16.row.col.f32.f16.f16.f32 "
                 "{%0,%1,%2,%3}, {%4,%5,%6,%7}, {%8,%9}, {%0,%1,%2,%3};"
                 : "+f"(d[0]), "+f"(d[1]), "+f"(d[2]), "+f"(d[3])
                 : "r"(a[0]), "r"(a[1]), "r"(a[2]), "r"(a[3]), "r"(b[0]), "r"(b[1]));
}
__device__ __forceinline__ float2 h2f2(uint32_t h) {
    return __half22float2(*(__half2*)&h);
}

// ---------------------------------------------------------------------------
// init: precompute normalized stencil coefficients + clamped neighbor indices
// ---------------------------------------------------------------------------
__global__ void init_tables_kernel() {
    int v = threadIdx.x + blockIdx.x * 256;
    if (v < NN) {
        int r = v / GW, c = v - (v / GW) * GW;
        float dv = dinv_rc(r, c);
        float w = (c > 0)      ? dinv_rc(r, c - 1) : 0.0f;
        float e = (c < GW - 1) ? dinv_rc(r, c + 1) : 0.0f;
        float n = (r > 0)      ? dinv_rc(r - 1, c) : 0.0f;
        float s = (r < GH - 1) ? dinv_rc(r + 1, c) : 0.0f;
        float4* cf = (float4*)(g_coef + v * 8);
        cf[0] = make_float4(dv * dv, dv * w, dv * e, dv * n);
        cf[1] = make_float4(dv * s, 0.0f, 0.0f, 0.0f);
        g_nidx[v] = make_int4((c > 0) ? v - 1 : v, (c < GW - 1) ? v + 1 : v,
                              (r > 0) ? v - GW : v, (r < GH - 1) ? v + GW : v);
    }
}

// ---------------------------------------------------------------------------
// x0 = relu(onehot(color)@Win + pr*Win[10] + pc*Win[11] + bin) -> fp16
// ---------------------------------------------------------------------------
__global__ __launch_bounds__(256) void encode_kernel(
    const int* __restrict__ grids, const float* __restrict__ Win,
    const float* __restrict__ bin)
{
    __shared__ float4 sW[12 * 32];
    __shared__ float4 sB[32];
    const int tid = threadIdx.x;
    for (int i = tid; i < 384; i += 256) sW[i] = ((const float4*)Win)[i];
    if (tid < 32) sB[tid] = ((const float4*)bin)[tid];
    __syncthreads();

    long long idx = (long long)blockIdx.x * 256 + tid;
    int cg = (int)(idx & 31);
    long long bn = idx >> 5;
    int n = (int)(bn % NN);
    int color = grids[bn];
    float pr = (float)(n / GW) * (1.0f / (GH - 1));
    float pc = (float)(n % GW) * (1.0f / (GW - 1));
    float4 wc = sW[color * 32 + cg];
    float4 wr = sW[10 * 32 + cg];
    float4 wp = sW[11 * 32 + cg];
    float4 bb = sB[cg];
    float4 o;
    o.x = fmaxf(fmaf(pc, wp.x, fmaf(pr, wr.x, wc.x + bb.x)), 0.0f);
    o.y = fmaxf(fmaf(pc, wp.y, fmaf(pr, wr.y, wc.y + bb.y)), 0.0f);
    o.z = fmaxf(fmaf(pc, wp.z, fmaf(pr, wr.z, wc.z + bb.z)), 0.0f);
    o.w = fmaxf(fmaf(pc, wp.w, fmaf(pr, wr.w, wc.w + bb.w)), 0.0f);
    __half2 h01 = __floats2half2_rn(o.x, o.y);
    __half2 h23 = __floats2half2_rn(o.z, o.w);
    ((uint2*)g_XH0)[idx] = make_uint2(*(uint32_t*)&h01, *(uint32_t*)&h23);
}

// ---------------------------------------------------------------------------
// Tensor-core GCN layer (single-pass fp16). CTA = (batch, quarter), 256 thr,
// 3 CTAs/SM, 4 tiles of 64 rows. Warp tile 32x32; B cols permuted so each
// thread owns 8 consecutive logical cols. FUSE_OUT: x_new staged to smem A
// buffer and the out GEMM (x @ Wout + bout) runs per tile; no global x write.
// ---------------------------------------------------------------------------
template<bool FUSE_OUT>
__global__ __launch_bounds__(256, 3) void layer_mma_kernel(
    int flip,
    const float* __restrict__ Wg, const float* __restrict__ bg,
    const float* __restrict__ gamma, const float* __restrict__ beta,
    const float* __restrict__ Wout, const float* __restrict__ bout,
    float* __restrict__ out)
{
    extern __shared__ char smem[];
    const uint32_t sb = smem_u32(smem);
    float* sPar = (float*)(smem + OFF_PAR);   // bg[128], gamma[128], beta[128]
    float* sS   = (float*)(smem + OFF_RED);   // [64][4] sum partials
    float* sQ   = sS + 256;                   // [64][4] sumsq partials

    const int tid = threadIdx.x, warp = tid >> 5, lane = tid & 31;
    const int mw = warp >> 2, nw = warp & 3;
    const int b = blockIdx.x >> 2, quarter = blockIdx.x & 3;
    const int rowbase0 = quarter * 225;

    const __half* XinH  = flip ? g_XH1 : g_XH0;
    __half*       XoutH = flip ? g_XH0 : g_XH1;
    const __half* XbH  = XinH  + (size_t)b * NN * HID;
    __half*       XobH = XoutH + (size_t)b * NN * HID;

    // --- stage LN params ---
    if (tid < 128) {
        sPar[tid]       = bg[tid];
        sPar[128 + tid] = gamma[tid];
        sPar[256 + tid] = beta[tid];
    }

    // --- stage W transposed+permuted to fp16, k-paired half2 stores ---
    {
        const float4* W4 = (const float4*)Wg;
        #pragma unroll
        for (int i = 0; i < 8; i++) {
            int j = tid + 256 * i;          // [64 kpairs][32 ngroups]
            int kp = j >> 5, grp = j & 31;
            float4 va = W4[(2 * kp) * 32 + grp];
            float4 vb = W4[(2 * kp + 1) * 32 + grp];
            #pragma unroll
            for (int u = 0; u < 4; u++) {
                int l = grp * 4 + u;
                int li = l & 31;
                int P = (l & 96) + ((li & 7) >> 1) * 8 + (li >> 3) * 2 + (l & 1);
                __half2 h = __floats2half2_rn(f4get(va, u), f4get(vb, u));
                *(uint32_t*)(smem + OFF_B + (uint32_t)P * PITCHB
                             + (uint32_t)kp * 4) = *(uint32_t*)&h;
            }
        }
    }
    // --- FUSE_OUT: stage Wout (k-paired) + bout ---
    if constexpr (FUSE_OUT) {
        const float4* WO4 = (const float4*)Wout;   // [128k][16 groups]
        #pragma unroll
        for (int i = 0; i < 4; i++) {
            int j = tid + 256 * i;          // [64 kpairs][16 ngroups]
            int kp = j >> 4, grp = j & 15;
            float4 va = WO4[(2 * kp) * 16 + grp];
            float4 vb = WO4[(2 * kp + 1) * 16 + grp];
            #pragma unroll
            for (int u = 0; u < 4; u++) {
                int l = grp * 4 + u;
                int li = l & 31;
                int P = (l & 32) + ((li & 7) >> 1) * 8 + (li >> 3) * 2 + (l & 1);
                __half2 h = __floats2half2_rn(f4get(va, u), f4get(vb, u));
                *(uint32_t*)(smem + OFF_WO + (uint32_t)P * PITCHB
                             + (uint32_t)kp * 4) = *(uint32_t*)&h;
            }
        }
        if (tid < 64) ((float*)(smem + OFF_BOUT))[tid] = bout[tid];
    }
    __syncthreads();

    // lane-dependent ldmatrix base offsets (GCN GEMM)
    const uint32_t aRow = (uint32_t)(mw * 32 + (lane & 15)) * PITCHB
                        + ((lane >> 4) & 1) * 16;
    const uint32_t aB0 = sb + OFF_A + aRow;
    const uint32_t aB1 = aB0 + 16 * PITCHB;
    uint32_t bOff[2];
    #pragma unroll
    for (int p = 0; p < 2; p++) {
        int n = nw * 32 + p * 16 + (lane & 7) + ((lane >> 4) & 1) * 8;
        bOff[p] = sb + OFF_B + (uint32_t)n * PITCHB + ((lane >> 3) & 1) * 16;
    }
    const int g = lane >> 2, tig = lane & 3;
    const int C0 = nw * 32 + tig * 8;   // this thread's 8 logical cols

    // out-phase offsets (FUSE_OUT only)
    uint32_t aB2 = 0, bOff2[2] = {0, 0};
    int mwO = 0, nwO = 0;
    if constexpr (FUSE_OUT) {
        mwO = warp >> 1; nwO = warp & 1;
        aB2 = sb + OFF_A + (uint32_t)(mwO * 16 + (lane & 15)) * PITCHB
            + ((lane >> 4) & 1) * 16;
        #pragma unroll
        for (int p = 0; p < 2; p++) {
            int n = nwO * 32 + p * 16 + (lane & 7) + ((lane >> 4) & 1) * 8;
            bOff2[p] = sb + OFF_WO + (uint32_t)n * PITCHB + ((lane >> 3) & 1) * 16;
        }
    }

    for (int t = 0; t < 4; t++) {
        const int base = rowbase0 + t * 64;
        const int nrows = min(64, 225 - t * 64);

        // --- stencil (table-driven, fp16 input) -> fp16 A ---
        #pragma unroll 4
        for (int s = 0; s < 8; s++) {
            int idx = tid + 256 * s;
            int r = idx >> 5, cg = idx & 31;
            uint32_t off = (uint32_t)r * PITCHB + (uint32_t)cg * 8;
            if (r < nrows) {
                int v = base + r;
                float4 cf = *(const float4*)(g_coef + v * 8);      // self,W,E,N
                float cfs = g_coef[v * 8 + 4];                     // S
                int4 ni = g_nidx[v];
                uint2 hs = *(const uint2*)(XbH + (size_t)v    * HID + cg * 4);
                uint2 hw = *(const uint2*)(XbH + (size_t)ni.x * HID + cg * 4);
                uint2 he = *(const uint2*)(XbH + (size_t)ni.y * HID + cg * 4);
                uint2 hn = *(const uint2*)(XbH + (size_t)ni.z * HID + cg * 4);
                uint2 ho = *(const uint2*)(XbH + (size_t)ni.w * HID + cg * 4);
                float2 s0 = h2f2(hs.x), s1 = h2f2(hs.y);
                float2 w0 = h2f2(hw.x), w1 = h2f2(hw.y);
                float2 e0 = h2f2(he.x), e1 = h2f2(he.y);
                float2 n0 = h2f2(hn.x), n1 = h2f2(hn.y);
                float2 o0 = h2f2(ho.x), o1 = h2f2(ho.y);
                float ax = cf.x * s0.x, ay = cf.x * s0.y;
                float az = cf.x * s1.x, aw = cf.x * s1.y;
                ax = fmaf(cf.y, w0.x, ax); ay = fmaf(cf.y, w0.y, ay);
                az = fmaf(cf.y, w1.x, az); aw = fmaf(cf.y, w1.y, aw);
                ax = fmaf(cf.z, e0.x, ax); ay = fmaf(cf.z, e0.y, ay);
                az = fmaf(cf.z, e1.x, az); aw = fmaf(cf.z, e1.y, aw);
                ax = fmaf(cf.w, n0.x, ax); ay = fmaf(cf.w, n0.y, ay);
                az = fmaf(cf.w, n1.x, az); aw = fmaf(cf.w, n1.y, aw);
                ax = fmaf(cfs, o0.x, ax); ay = fmaf(cfs, o0.y, ay);
                az = fmaf(cfs, o1.x, az); aw = fmaf(cfs, o1.y, aw);
                __half2 h01 = __floats2half2_rn(ax, ay);
                __half2 h23 = __floats2half2_rn(az, aw);
                *(uint2*)(smem + OFF_A + off) =
                    make_uint2(*(uint32_t*)&h01, *(uint32_t*)&h23);
            } else {
                *(uint2*)(smem + OFF_A + off) = make_uint2(0u, 0u);
            }
        }
        __syncthreads();

        // --- MMA mainloop: D = A @ B' (single fp16 pass, 32x32 warp tile) ---
        float acc[2][4][4];
        #pragma unroll
        for (int i = 0; i < 2; i++)
            #pragma unroll
            for (int nb = 0; nb < 4; nb++)
                #pragma unroll
                for (int j = 0; j < 4; j++) acc[i][nb][j] = 0.0f;

        #pragma unroll
        for (int ks = 0; ks < 8; ks++) {
            const uint32_t kb = (uint32_t)ks * 32;
            uint32_t a0[4], a1[4];
            ldsm4(aB0 + kb, a0[0], a0[1], a0[2], a0[3]);
            ldsm4(aB1 + kb, a1[0], a1[1], a1[2], a1[3]);
            uint32_t bh[4][2];
            #pragma unroll
            for (int p = 0; p < 2; p++) {
                ldsm4(bOff[p] + kb,
                      bh[2*p][0], bh[2*p][1], bh[2*p+1][0], bh[2*p+1][1]);
            }
            #pragma unroll
            for (int nb = 0; nb < 4; nb++) {
                mma_f16(acc[0][nb], a0, bh[nb]);
                mma_f16(acc[1][nb], a1, bh[nb]);
            }
        }

        // --- epilogue: bias add, LN partials (32 cols/warp), 4-way reduce ---
        float4 bi0 = *(float4*)(sPar + C0);
        float4 bi1 = *(float4*)(sPar + C0 + 4);
        #pragma unroll
        for (int i = 0; i < 2; i++) {
            #pragma unroll
            for (int h = 0; h < 2; h++) {
                int row = mw * 32 + i * 16 + g + 8 * h;
                float v0 = acc[i][0][2*h]   + bi0.x;
                float v1 = acc[i][0][2*h+1] + bi0.y;
                float v2 = acc[i][1][2*h]   + bi0.z;
                float v3 = acc[i][1][2*h+1] + bi0.w;
                float v4 = acc[i][2][2*h]   + bi1.x;
                float v5 = acc[i][2][2*h+1] + bi1.y;
                float v6 = acc[i][3][2*h]   + bi1.z;
                float v7 = acc[i][3][2*h+1] + bi1.w;
                acc[i][0][2*h] = v0; acc[i][0][2*h+1] = v1;
                acc[i][1][2*h] = v2; acc[i][1][2*h+1] = v3;
                acc[i][2][2*h] = v4; acc[i][2][2*h+1] = v5;
                acc[i][3][2*h] = v6; acc[i][3][2*h+1] = v7;
                float s = v0 + v1 + v2 + v3 + v4 + v5 + v6 + v7;
                float q = fmaf(v0, v0, fmaf(v1, v1, fmaf(v2, v2, v3 * v3)));
                q = fmaf(v4, v4, fmaf(v5, v5, fmaf(v6, v6, fmaf(v7, v7, q))));
                s += __shfl_xor_sync(0xffffffffu, s, 1);
                s += __shfl_xor_sync(0xffffffffu, s, 2);
                q += __shfl_xor_sync(0xffffffffu, q, 1);
                q += __shfl_xor_sync(0xffffffffu, q, 2);
                if (tig == 0) { sS[row * 4 + nw] = s; sQ[row * 4 + nw] = q; }
            }
        }
        __syncthreads();

        // --- LN + relu + residual; dest = global fp16 x (or smem A if fused) ---
        #pragma unroll
        for (int i = 0; i < 2; i++) {
            #pragma unroll
            for (int h = 0; h < 2; h++) {
                int row = mw * 32 + i * 16 + g + 8 * h;
                float4 sv = *(float4*)(sS + row * 4);
                float4 qv = *(float4*)(sQ + row * 4);
                float s = (sv.x + sv.y) + (sv.z + sv.w);
                float q = (qv.x + qv.y) + (qv.z + qv.w);
                float mean = s * (1.0f / HID);
                float var  = q * (1.0f / HID) - mean * mean;
                float rstd = rsqrtf(var + 1e-5f);
                if (row < nrows) {   // quad-uniform
                    int v = base + row;
                    float4 gm0 = *(float4*)(sPar + 128 + C0);
                    float4 gm1 = *(float4*)(sPar + 128 + C0 + 4);
                    float4 bt0 = *(float4*)(sPar + 256 + C0);
                    float4 bt1 = *(float4*)(sPar + 256 + C0 + 4);
                    uint4 xh = *(const uint4*)(XbH + (size_t)v * HID + C0);
                    float2 xa = h2f2(xh.x), xb2 = h2f2(xh.y);
                    float2 xc = h2f2(xh.z), xd = h2f2(xh.w);
                    float o0 = fmaxf((acc[i][0][2*h]   - mean) * rstd * gm0.x + bt0.x, 0.0f) + xa.x;
                    float o1 = fmaxf((acc[i][0][2*h+1] - mean) * rstd * gm0.y + bt0.y, 0.0f) + xa.y;
                    float o2 = fmaxf((acc[i][1][2*h]   - mean) * rstd * gm0.z + bt0.z, 0.0f) + xb2.x;
                    float o3 = fmaxf((acc[i][1][2*h+1] - mean) * rstd * gm0.w + bt0.w, 0.0f) + xb2.y;
                    float o4 = fmaxf((acc[i][2][2*h]   - mean) * rstd * gm1.x + bt1.x, 0.0f) + xc.x;
                    float o5 = fmaxf((acc[i][2][2*h+1] - mean) * rstd * gm1.y + bt1.y, 0.0f) + xc.y;
                    float o6 = fmaxf((acc[i][3][2*h]   - mean) * rstd * gm1.z + bt1.z, 0.0f) + xd.x;
                    float o7 = fmaxf((acc[i][3][2*h+1] - mean) * rstd * gm1.w + bt1.w, 0.0f) + xd.y;
                    __half2 ha = __floats2half2_rn(o0, o1);
                    __half2 hb = __floats2half2_rn(o2, o3);
                    __half2 hc = __floats2half2_rn(o4, o5);
                    __half2 hd = __floats2half2_rn(o6, o7);
                    uint4 pk = make_uint4(*(uint32_t*)&ha, *(uint32_t*)&hb,
                                          *(uint32_t*)&hc, *(uint32_t*)&hd);
                    if constexpr (FUSE_OUT) {
                        *(uint4*)(smem + OFF_A + (uint32_t)row * PITCHB
                                  + (uint32_t)C0 * 2) = pk;
                    } else {
                        *(uint4*)(XobH + (size_t)v * HID + C0) = pk;
                    }
                } else {
                    if constexpr (FUSE_OUT) {
                        *(uint4*)(smem + OFF_A + (uint32_t)row * PITCHB
                                  + (uint32_t)C0 * 2) = make_uint4(0u, 0u, 0u, 0u);
                    }
                }
            }
        }
        __syncthreads();

        // --- fused out GEMM: out[tile] = x_new @ Wout + bout ---
        if constexpr (FUSE_OUT) {
            float acc2[4][4];
            #pragma unroll
            for (int nb = 0; nb < 4; nb++)
                #pragma unroll
                for (int j = 0; j < 4; j++) acc2[nb][j] = 0.0f;

            #pragma unroll
            for (int ks = 0; ks < 8; ks++) {
                const uint32_t kb = (uint32_t)ks * 32;
                uint32_t a[4];
                ldsm4(aB2 + kb, a[0], a[1], a[2], a[3]);
                uint32_t bh[4][2];
                #pragma unroll
                for (int p = 0; p < 2; p++) {
                    ldsm4(bOff2[p] + kb,
                          bh[2*p][0], bh[2*p][1], bh[2*p+1][0], bh[2*p+1][1]);
                }
                #pragma unroll
                for (int nb = 0; nb < 4; nb++)
                    mma_f16(acc2[nb], a, bh[nb]);
            }

            const float* sBout = (const float*)(smem + OFF_BOUT);
            #pragma unroll
            for (int h = 0; h < 2; h++) {
                int row = mwO * 16 + g + 8 * h;
                if (row < nrows) {   // quad-uniform
                    float* op = out + ((size_t)b * NN + base + row) * OUTD;
                    #pragma unroll
                    for (int j = 0; j < 2; j++) {
                        int C = nwO * 32 + tig * 8 + 4 * j;
                        float4 bo = *(const float4*)(sBout + C);
                        float4 o;
                        o.x = acc2[2*j][2*h]     + bo.x;
                        o.y = acc2[2*j][2*h+1]   + bo.y;
                        o.z = acc2[2*j+1][2*h]   + bo.z;
                        o.w = acc2[2*j+1][2*h+1] + bo.w;
                        *(float4*)(op + C) = o;
                    }
                }
            }
            __syncthreads();   // OFF_A reads done before next tile's stencil
        }
    }
}

// ---------------------------------------------------------------------------
extern "C" void kernel_launch(void* const* d_in, const int* in_sizes, int n_in,
                              void* d_out, int out_size) {
    const int*   grids = (const int*)d_in[0];
    // d_in[1] = edge_index: fixed 30x30 4-connected grid; precomputed tables.
    const float* Win   = (const float*)d_in[2];
    const float* bin   = (const float*)d_in[3];
    const float* Wg    = (const float*)d_in[4];
    const float* bg    = (const float*)d_in[5];
    const float* gamma = (const float*)d_in[6];
    const float* beta  = (const float*)d_in[7];
    const float* Wout  = (const float*)d_in[8];
    const float* bout  = (const float*)d_in[9];
    float* out = (float*)d_out;
    (void)in_sizes; (void)n_in; (void)out_size;

    cudaFuncSetAttribute((const void*)layer_mma_kernel<false>,
                         cudaFuncAttributeMaxDynamicSharedMemorySize, SMEM_MMA);
    cudaFuncSetAttribute((const void*)layer_mma_kernel<true>,
                         cudaFuncAttributeMaxDynamicSharedMemorySize, SMEM_FUSED);

    init_tables_kernel<<<4, 256>>>();
    encode_kernel<<<(NB * NN * 32) / 256, 256>>>(grids, Win, bin);
    for (int i = 0; i < 3; i++) {
        layer_mma_kernel<false><<<NB * 4, 256, SMEM_MMA>>>(
            i & 1, Wg + (size_t)i * HID * HID, bg + i * HID,
            gamma + i * HID, beta + i * HID, nullptr, nullptr, nullptr);
    }
    layer_mma_kernel<true><<<NB * 4, 256, SMEM_FUSED>>>(
        1, Wg + (size_t)3 * HID * HID, bg + 3 * HID,
        gamma + 3 * HID, beta + 3 * HID, Wout, bout, out);
}

// round 15
// speedup vs baseline: 5.2806x; 1.0659x over previous
#include <cuda_runtime.h>
#include <cuda_fp16.h>
#include <cstdint>

#define NB   512
#define GH   30
#define GW   30
#define NN   900
#define HID  128
#define OUTD 64

// Activations live ONLY in fp16 (ping-pong); LN/residual math fp32 in registers.
__device__ __half g_XH0[(size_t)NB * NN * HID];
__device__ __half g_XH1[(size_t)NB * NN * HID];
// Pre-permuted fp16 weights in the exact smem layout ([P][136] halves, 272B pitch)
// 16B-aligned: staged with uint4 copies.
__device__ __align__(16) __half g_Wg16[4][128 * 136];   // 2176 uint4 each
__device__ __align__(16) __half g_Wout16[64 * 136];     // 1088 uint4
// Precomputed graph tables (fixed 30x30 4-connected grid + self loops)
__device__ float g_coef[NN * 8];   // [v]: self, W, E, N, S, pad...
__device__ int4  g_nidx[NN];       // [v]: clamped W, E, N, S indices

// smem byte offsets (fp16 matrices, 136-elem = 272B rows)
#define PITCHB 272
#define OFF_B    0
#define OFF_A    34816
#define OFF_PAR  52224
#define OFF_RED  53760
#define SMEM_MMA 55808
// fused-out extras (Wout: 64 rows x 272B = 17408B)
#define OFF_WO   55808
#define OFF_BOUT 73216
#define SMEM_FUSED 73472

__device__ __forceinline__ uint32_t smem_u32(const void* p) {
    uint32_t a;
    asm("{ .reg .u64 t; cvta.to.shared.u64 t, %1; cvt.u32.u64 %0, t; }" : "=r"(a) : "l"(p));
    return a;
}
__device__ __forceinline__ float dinv_rc(int rp, int cp) {
    int d = 1 + (rp > 0) + (rp < GH - 1) + (cp > 0) + (cp < GW - 1);
    return rsqrtf((float)d);
}
__device__ __forceinline__ float f4get(const float4& v, int i) {
    return i == 0 ? v.x : i == 1 ? v.y : i == 2 ? v.z : v.w;
}
__device__ __forceinline__ void ldsm4(uint32_t addr, uint32_t& r0, uint32_t& r1,
                                      uint32_t& r2, uint32_t& r3) {
    asm volatile("ldmatrix.sync.aligned.m8n8.x4.shared.b16 {%0,%1,%2,%3}, [%4];"
                 : "=r"(r0), "=r"(r1), "=r"(r2), "=r"(r3) : "r"(addr));
}
__device__ __forceinline__ void mma_f16(float* d, const uint32_t* a, const uint32_t* b) {
    asm volatile("mma.sync.aligned.m16n8k16.row.col.f32.f16.f16.f32 "
                 "{%0,%1,%2,%3}, {%4,%5,%6,%7}, {%8,%9}, {%0,%1,%2,%3};"
                 : "+f"(d[0]), "+f"(d[1]), "+f"(d[2]), "+f"(d[3])
                 : "r"(a[0]), "r"(a[1]), "r"(a[2]), "r"(a[3]), "r"(b[0]), "r"(b[1]));
}
__device__ __forceinline__ float2 h2f2(uint32_t h) {
    return __half22float2(*(__half2*)&h);
}

// ---------------------------------------------------------------------------
// init: stencil coef/nidx tables
// ---------------------------------------------------------------------------
__global__ void init_tables_kernel() {
    int v = threadIdx.x + blockIdx.x * 256;
    if (v < NN) {
        int r = v / GW, c = v - (v / GW) * GW;
        float dv = dinv_rc(r, c);
        float w = (c > 0)      ? dinv_rc(r, c - 1) : 0.0f;
        float e = (c < GW - 1) ? dinv_rc(r, c + 1) : 0.0f;
        float n = (r > 0)      ? dinv_rc(r - 1, c) : 0.0f;
        float s = (r < GH - 1) ? dinv_rc(r + 1, c) : 0.0f;
        float4* cf = (float4*)(g_coef + v * 8);
        cf[0] = make_float4(dv * dv, dv * w, dv * e, dv * n);
        cf[1] = make_float4(dv * s, 0.0f, 0.0f, 0.0f);
        g_nidx[v] = make_int4((c > 0) ? v - 1 : v, (c < GW - 1) ? v + 1 : v,
                              (r > 0) ? v - GW : v, (r < GH - 1) ? v + GW : v);
    }
}

// ---------------------------------------------------------------------------
// prep: transpose+permute+fp16-convert all weights ONCE into global arrays
// (exact smem layout; layer staging becomes a straight uint4 copy)
// ---------------------------------------------------------------------------
__global__ void prep_weights_kernel(const float* __restrict__ Wg,
                                    const float* __restrict__ Wout) {
    int idx = threadIdx.x + blockIdx.x * 256;
    if (idx < 4 * HID * HID) {                 // Wg: [layer][k][l]
        int layer = idx >> 14;
        int k = (idx >> 7) & 127, l = idx & 127;
        int li = l & 31;
        int P = (l & 96) + ((li & 7) >> 1) * 8 + (li >> 3) * 2 + (l & 1);
        g_Wg16[layer][P * 136 + k] = __float2half_rn(Wg[idx]);
    } else if (idx < 4 * HID * HID + HID * OUTD) {   // Wout: [k][l]
        int j = idx - 4 * HID * HID;
        int k = j >> 6, l = j & 63;
        int li = l & 31;
        int P = (l & 32) + ((li & 7) >> 1) * 8 + (li >> 3) * 2 + (l & 1);
        g_Wout16[P * 136 + k] = __float2half_rn(Wout[j]);
    }
}

// ---------------------------------------------------------------------------
// x0 = relu(onehot(color)@Win + pr*Win[10] + pc*Win[11] + bin) -> fp16
// ---------------------------------------------------------------------------
__global__ __launch_bounds__(256) void encode_kernel(
    const int* __restrict__ grids, const float* __restrict__ Win,
    const float* __restrict__ bin)
{
    __shared__ float4 sW[12 * 32];
    __shared__ float4 sB[32];
    const int tid = threadIdx.x;
    for (int i = tid; i < 384; i += 256) sW[i] = ((const float4*)Win)[i];
    if (tid < 32) sB[tid] = ((const float4*)bin)[tid];
    __syncthreads();

    long long idx = (long long)blockIdx.x * 256 + tid;
    int cg = (int)(idx & 31);
    long long bn = idx >> 5;
    int n = (int)(bn % NN);
    int color = grids[bn];
    float pr = (float)(n / GW) * (1.0f / (GH - 1));
    float pc = (float)(n % GW) * (1.0f / (GW - 1));
    float4 wc = sW[color * 32 + cg];
    float4 wr = sW[10 * 32 + cg];
    float4 wp = sW[11 * 32 + cg];
    float4 bb = sB[cg];
    float4 o;
    o.x = fmaxf(fmaf(pc, wp.x, fmaf(pr, wr.x, wc.x + bb.x)), 0.0f);
    o.y = fmaxf(fmaf(pc, wp.y, fmaf(pr, wr.y, wc.y + bb.y)), 0.0f);
    o.z = fmaxf(fmaf(pc, wp.z, fmaf(pr, wr.z, wc.z + bb.z)), 0.0f);
    o.w = fmaxf(fmaf(pc, wp.w, fmaf(pr, wr.w, wc.w + bb.w)), 0.0f);
    __half2 h01 = __floats2half2_rn(o.x, o.y);
    __half2 h23 = __floats2half2_rn(o.z, o.w);
    ((uint2*)g_XH0)[idx] = make_uint2(*(uint32_t*)&h01, *(uint32_t*)&h23);
}

// ---------------------------------------------------------------------------
// Tensor-core GCN layer (single-pass fp16). CTA = (batch, quarter), 256 thr,
// 3 CTAs/SM, 4 tiles of 64 rows. Warp tile 32x32; B staged by plain uint4
// copy from pre-permuted global fp16. FUSE_OUT fuses the out GEMM.
// ---------------------------------------------------------------------------
template<bool FUSE_OUT>
__global__ __launch_bounds__(256, 3) void layer_mma_kernel(
    int layer, int flip,
    const float* __restrict__ bg,
    const float* __restrict__ gamma, const float* __restrict__ beta,
    const float* __restrict__ bout,
    float* __restrict__ out)
{
    extern __shared__ char smem[];
    const uint32_t sb = smem_u32(smem);
    float* sPar = (float*)(smem + OFF_PAR);   // bg[128], gamma[128], beta[128]
    float* sS   = (float*)(smem + OFF_RED);   // [64][4] sum partials
    float* sQ   = sS + 256;                   // [64][4] sumsq partials

    const int tid = threadIdx.x, warp = tid >> 5, lane = tid & 31;
    const int mw = warp >> 2, nw = warp & 3;
    const int b = blockIdx.x >> 2, quarter = blockIdx.x & 3;
    const int rowbase0 = quarter * 225;

    const __half* XinH  = flip ? g_XH1 : g_XH0;
    __half*       XoutH = flip ? g_XH0 : g_XH1;
    const __half* XbH  = XinH  + (size_t)b * NN * HID;
    __half*       XobH = XoutH + (size_t)b * NN * HID;

    // --- stage LN params ---
    if (tid < 128) {
        sPar[tid]       = bg[tid];
        sPar[128 + tid] = gamma[tid];
        sPar[256 + tid] = beta[tid];
    }

    // --- stage W: straight uint4 copy of pre-permuted fp16 (conflict-free) ---
    {
        const uint4* src = (const uint4*)g_Wg16[layer];
        uint4* dst = (uint4*)(smem + OFF_B);
        #pragma unroll
        for (int i = tid; i < 2176; i += 256) dst[i] = src[i];   // 128 rows
    }
    if constexpr (FUSE_OUT) {
        const uint4* src = (const uint4*)g_Wout16;
        uint4* dst = (uint4*)(smem + OFF_WO);
        #pragma unroll
        for (int i = tid; i < 1088; i += 256) dst[i] = src[i];   // 64 rows
        if (tid < 64) ((float*)(smem + OFF_BOUT))[tid] = bout[tid];
    }
    __syncthreads();

    // lane-dependent ldmatrix base offsets (GCN GEMM)
    const uint32_t aRow = (uint32_t)(mw * 32 + (lane & 15)) * PITCHB
                        + ((lane >> 4) & 1) * 16;
    const uint32_t aB0 = sb + OFF_A + aRow;
    const uint32_t aB1 = aB0 + 16 * PITCHB;
    uint32_t bOff[2];
    #pragma unroll
    for (int p = 0; p < 2; p++) {
        int n = nw * 32 + p * 16 + (lane & 7) + ((lane >> 4) & 1) * 8;
        bOff[p] = sb + OFF_B + (uint32_t)n * PITCHB + ((lane >> 3) & 1) * 16;
    }
    const int g = lane >> 2, tig = lane & 3;
    const int C0 = nw * 32 + tig * 8;   // this thread's 8 logical cols

    // out-phase offsets (FUSE_OUT only)
    uint32_t aB2 = 0, bOff2[2] = {0, 0};
    int mwO = 0, nwO = 0;
    if constexpr (FUSE_OUT) {
        mwO = warp >> 1; nwO = warp & 1;
        aB2 = sb + OFF_A + (uint32_t)(mwO * 16 + (lane & 15)) * PITCHB
            + ((lane >> 4) & 1) * 16;
        #pragma unroll
        for (int p = 0; p < 2; p++) {
            int n = nwO * 32 + p * 16 + (lane & 7) + ((lane >> 4) & 1) * 8;
            bOff2[p] = sb + OFF_WO + (uint32_t)n * PITCHB + ((lane >> 3) & 1) * 16;
        }
    }

    for (int t = 0; t < 4; t++) {
        const int base = rowbase0 + t * 64;
        const int nrows = min(64, 225 - t * 64);

        // --- stencil (table-driven, fp16 input) -> fp16 A ---
        #pragma unroll 4
        for (int s = 0; s < 8; s++) {
            int idx = tid + 256 * s;
            int r = idx >> 5, cg = idx & 31;
            uint32_t off = (uint32_t)r * PITCHB + (uint32_t)cg * 8;
            if (r < nrows) {
                int v = base + r;
                float4 cf = *(const float4*)(g_coef + v * 8);      // self,W,E,N
                float cfs = g_coef[v * 8 + 4];                     // S
                int4 ni = g_nidx[v];
                uint2 hs = *(const uint2*)(XbH + (size_t)v    * HID + cg * 4);
                uint2 hw = *(const uint2*)(XbH + (size_t)ni.x * HID + cg * 4);
                uint2 he = *(const uint2*)(XbH + (size_t)ni.y * HID + cg * 4);
                uint2 hn = *(const uint2*)(XbH + (size_t)ni.z * HID + cg * 4);
                uint2 ho = *(const uint2*)(XbH + (size_t)ni.w * HID + cg * 4);
                float2 s0 = h2f2(hs.x), s1 = h2f2(hs.y);
                float2 w0 = h2f2(hw.x), w1 = h2f2(hw.y);
                float2 e0 = h2f2(he.x), e1 = h2f2(he.y);
                float2 n0 = h2f2(hn.x), n1 = h2f2(hn.y);
                float2 o0 = h2f2(ho.x), o1 = h2f2(ho.y);
                float ax = cf.x * s0.x, ay = cf.x * s0.y;
                float az = cf.x * s1.x, aw = cf.x * s1.y;
                ax = fmaf(cf.y, w0.x, ax); ay = fmaf(cf.y, w0.y, ay);
                az = fmaf(cf.y, w1.x, az); aw = fmaf(cf.y, w1.y, aw);
                ax = fmaf(cf.z, e0.x, ax); ay = fmaf(cf.z, e0.y, ay);
                az = fmaf(cf.z, e1.x, az); aw = fmaf(cf.z, e1.y, aw);
                ax = fmaf(cf.w, n0.x, ax); ay = fmaf(cf.w, n0.y, ay);
                az = fmaf(cf.w, n1.x, az); aw = fmaf(cf.w, n1.y, aw);
                ax = fmaf(cfs, o0.x, ax); ay = fmaf(cfs, o0.y, ay);
                az = fmaf(cfs, o1.x, az); aw = fmaf(cfs, o1.y, aw);
                __half2 h01 = __floats2half2_rn(ax, ay);
                __half2 h23 = __floats2half2_rn(az, aw);
                *(uint2*)(smem + OFF_A + off) =
                    make_uint2(*(uint32_t*)&h01, *(uint32_t*)&h23);
            } else {
                *(uint2*)(smem + OFF_A + off) = make_uint2(0u, 0u);
            }
        }
        __syncthreads();

        // --- MMA mainloop: D = A @ B' (single fp16 pass, 32x32 warp tile) ---
        float acc[2][4][4];
        #pragma unroll
        for (int i = 0; i < 2; i++)
            #pragma unroll
            for (int nb = 0; nb < 4; nb++)
                #pragma unroll
                for (int j = 0; j < 4; j++) acc[i][nb][j] = 0.0f;

        #pragma unroll
        for (int ks = 0; ks < 8; ks++) {
            const uint32_t kb = (uint32_t)ks * 32;
            uint32_t a0[4], a1[4];
            ldsm4(aB0 + kb, a0[0], a0[1], a0[2], a0[3]);
            ldsm4(aB1 + kb, a1[0], a1[1], a1[2], a1[3]);
            uint32_t bh[4][2];
            #pragma unroll
            for (int p = 0; p < 2; p++) {
                ldsm4(bOff[p] + kb,
                      bh[2*p][0], bh[2*p][1], bh[2*p+1][0], bh[2*p+1][1]);
            }
            #pragma unroll
            for (int nb = 0; nb < 4; nb++) {
                mma_f16(acc[0][nb], a0, bh[nb]);
                mma_f16(acc[1][nb], a1, bh[nb]);
            }
        }

        // --- epilogue: bias add, LN partials (32 cols/warp), 4-way reduce ---
        float4 bi0 = *(float4*)(sPar + C0);
        float4 bi1 = *(float4*)(sPar + C0 + 4);
        #pragma unroll
        for (int i = 0; i < 2; i++) {
            #pragma unroll
            for (int h = 0; h < 2; h++) {
                int row = mw * 32 + i * 16 + g + 8 * h;
                float v0 = acc[i][0][2*h]   + bi0.x;
                float v1 = acc[i][0][2*h+1] + bi0.y;
                float v2 = acc[i][1][2*h]   + bi0.z;
                float v3 = acc[i][1][2*h+1] + bi0.w;
                float v4 = acc[i][2][2*h]   + bi1.x;
                float v5 = acc[i][2][2*h+1] + bi1.y;
                float v6 = acc[i][3][2*h]   + bi1.z;
                float v7 = acc[i][3][2*h+1] + bi1.w;
                acc[i][0][2*h] = v0; acc[i][0][2*h+1] = v1;
                acc[i][1][2*h] = v2; acc[i][1][2*h+1] = v3;
                acc[i][2][2*h] = v4; acc[i][2][2*h+1] = v5;
                acc[i][3][2*h] = v6; acc[i][3][2*h+1] = v7;
                float s = v0 + v1 + v2 + v3 + v4 + v5 + v6 + v7;
                float q = fmaf(v0, v0, fmaf(v1, v1, fmaf(v2, v2, v3 * v3)));
                q = fmaf(v4, v4, fmaf(v5, v5, fmaf(v6, v6, fmaf(v7, v7, q))));
                s += __shfl_xor_sync(0xffffffffu, s, 1);
                s += __shfl_xor_sync(0xffffffffu, s, 2);
                q += __shfl_xor_sync(0xffffffffu, q, 1);
                q += __shfl_xor_sync(0xffffffffu, q, 2);
                if (tig == 0) { sS[row * 4 + nw] = s; sQ[row * 4 + nw] = q; }
            }
        }
        __syncthreads();

        // --- LN + relu + residual; dest = global fp16 x (or smem A if fused) ---
        #pragma unroll
        for (int i = 0; i < 2; i++) {
            #pragma unroll
            for (int h = 0; h < 2; h++) {
                int row = mw * 32 + i * 16 + g + 8 * h;
                float4 sv = *(float4*)(sS + row * 4);
                float4 qv = *(float4*)(sQ + row * 4);
                float s = (sv.x + sv.y) + (sv.z + sv.w);
                float q = (qv.x + qv.y) + (qv.z + qv.w);
                float mean = s * (1.0f / HID);
                float var  = q * (1.0f / HID) - mean * mean;
                float rstd = rsqrtf(var + 1e-5f);
                if (row < nrows) {   // quad-uniform
                    int v = base + row;
                    float4 gm0 = *(float4*)(sPar + 128 + C0);
                    float4 gm1 = *(float4*)(sPar + 128 + C0 + 4);
                    float4 bt0 = *(float4*)(sPar + 256 + C0);
                    float4 bt1 = *(float4*)(sPar + 256 + C0 + 4);
                    uint4 xh = *(const uint4*)(XbH + (size_t)v * HID + C0);
                    float2 xa = h2f2(xh.x), xb2 = h2f2(xh.y);
                    float2 xc = h2f2(xh.z), xd = h2f2(xh.w);
                    float o0 = fmaxf((acc[i][0][2*h]   - mean) * rstd * gm0.x + bt0.x, 0.0f) + xa.x;
                    float o1 = fmaxf((acc[i][0][2*h+1] - mean) * rstd * gm0.y + bt0.y, 0.0f) + xa.y;
                    float o2 = fmaxf((acc[i][1][2*h]   - mean) * rstd * gm0.z + bt0.z, 0.0f) + xb2.x;
                    float o3 = fmaxf((acc[i][1][2*h+1] - mean) * rstd * gm0.w + bt0.w, 0.0f) + xb2.y;
                    float o4 = fmaxf((acc[i][2][2*h]   - mean) * rstd * gm1.x + bt1.x, 0.0f) + xc.x;
                    float o5 = fmaxf((acc[i][2][2*h+1] - mean) * rstd * gm1.y + bt1.y, 0.0f) + xc.y;
                    float o6 = fmaxf((acc[i][3][2*h]   - mean) * rstd * gm1.z + bt1.z, 0.0f) + xd.x;
                    float o7 = fmaxf((acc[i][3][2*h+1] - mean) * rstd * gm1.w + bt1.w, 0.0f) + xd.y;
                    __half2 ha = __floats2half2_rn(o0, o1);
                    __half2 hb = __floats2half2_rn(o2, o3);
                    __half2 hc = __floats2half2_rn(o4, o5);
                    __half2 hd = __floats2half2_rn(o6, o7);
                    uint4 pk = make_uint4(*(uint32_t*)&ha, *(uint32_t*)&hb,
                                          *(uint32_t*)&hc, *(uint32_t*)&hd);
                    if constexpr (FUSE_OUT) {
                        *(uint4*)(smem + OFF_A + (uint32_t)row * PITCHB
                                  + (uint32_t)C0 * 2) = pk;
                    } else {
                        *(uint4*)(XobH + (size_t)v * HID + C0) = pk;
                    }
                } else {
                    if constexpr (FUSE_OUT) {
                        *(uint4*)(smem + OFF_A + (uint32_t)row * PITCHB
                                  + (uint32_t)C0 * 2) = make_uint4(0u, 0u, 0u, 0u);
                    }
                }
            }
        }
        __syncthreads();

        // --- fused out GEMM: out[tile] = x_new @ Wout + bout ---
        if constexpr (FUSE_OUT) {
            float acc2[4][4];
            #pragma unroll
            for (int nb = 0; nb < 4; nb++)
                #pragma unroll
                for (int j = 0; j < 4; j++) acc2[nb][j] = 0.0f;

            #pragma unroll
            for (int ks = 0; ks < 8; ks++) {
                const uint32_t kb = (uint32_t)ks * 32;
                uint32_t a[4];
                ldsm4(aB2 + kb, a[0], a[1], a[2], a[3]);
                uint32_t bh[4][2];
                #pragma unroll
                for (int p = 0; p < 2; p++) {
                    ldsm4(bOff2[p] + kb,
                          bh[2*p][0], bh[2*p][1], bh[2*p+1][0], bh[2*p+1][1]);
                }
                #pragma unroll
                for (int nb = 0; nb < 4; nb++)
                    mma_f16(acc2[nb], a, bh[nb]);
            }

            const float* sBout = (const float*)(smem + OFF_BOUT);
            #pragma unroll
            for (int h = 0; h < 2; h++) {
                int row = mwO * 16 + g + 8 * h;
                if (row < nrows) {   // quad-uniform
                    float* op = out + ((size_t)b * NN + base + row) * OUTD;
                    #pragma unroll
                    for (int j = 0; j < 2; j++) {
                        int C = nwO * 32 + tig * 8 + 4 * j;
                        float4 bo = *(const float4*)(sBout + C);
                        float4 o;
                        o.x = acc2[2*j][2*h]     + bo.x;
                        o.y = acc2[2*j][2*h+1]   + bo.y;
                        o.z = acc2[2*j+1][2*h]   + bo.z;
                        o.w = acc2[2*j+1][2*h+1] + bo.w;
                        *(float4*)(op + C) = o;
                    }
                }
            }
            __syncthreads();   // OFF_A reads done before next tile's stencil
        }
    }
}

// ---------------------------------------------------------------------------
extern "C" void kernel_launch(void* const* d_in, const int* in_sizes, int n_in,
                              void* d_out, int out_size) {
    const int*   grids = (const int*)d_in[0];
    // d_in[1] = edge_index: fixed 30x30 4-connected grid; precomputed tables.
    const float* Win   = (const float*)d_in[2];
    const float* bin   = (const float*)d_in[3];
    const float* Wg    = (const float*)d_in[4];
    const float* bg    = (const float*)d_in[5];
    const float* gamma = (const float*)d_in[6];
    const float* beta  = (const float*)d_in[7];
    const float* Wout  = (const float*)d_in[8];
    const float* bout  = (const float*)d_in[9];
    float* out = (float*)d_out;
    (void)in_sizes; (void)n_in; (void)out_size;

    cudaFuncSetAttribute((const void*)layer_mma_kernel<false>,
                         cudaFuncAttributeMaxDynamicSharedMemorySize, SMEM_MMA);
    cudaFuncSetAttribute((const void*)layer_mma_kernel<true>,
                         cudaFuncAttributeMaxDynamicSharedMemorySize, SMEM_FUSED);

    init_tables_kernel<<<4, 256>>>();
    prep_weights_kernel<<<(4 * HID * HID + HID * OUTD + 255) / 256, 256>>>(Wg, Wout);
    encode_kernel<<<(NB * NN * 32) / 256, 256>>>(grids, Win, bin);
    for (int i = 0; i < 3; i++) {
        layer_mma_kernel<false><<<NB * 4, 256, SMEM_MMA>>>(
            i, i & 1, bg + i * HID, gamma + i * HID, beta + i * HID,
            nullptr, nullptr);
    }
    layer_mma_kernel<true><<<NB * 4, 256, SMEM_FUSED>>>(
        3, 1, bg + 3 * HID, gamma + 3 * HID, beta + 3 * HID, bout, out);
}

// round 16
// speedup vs baseline: 5.6854x; 1.0766x over previous
#include <cuda_runtime.h>
#include <cuda_fp16.h>
#include <cstdint>

#define NB   512
#define GH   30
#define GW   30
#define NN   900
#define HID  128
#define OUTD 64

// Activations live ONLY in fp16 (ping-pong); LN/residual math fp32 in registers.
__device__ __half g_XH0[(size_t)NB * NN * HID];
__device__ __half g_XH1[(size_t)NB * NN * HID];
// Pre-permuted fp16 weights in the exact smem layout ([P][136] halves, 272B pitch)
// 16B-aligned: staged with uint4 copies.
__device__ __align__(16) __half g_Wg16[4][128 * 136];   // 2176 uint4 each
__device__ __align__(16) __half g_Wout16[64 * 136];     // 1088 uint4
// Precomputed graph tables (fixed 30x30 4-connected grid + self loops)
__device__ float g_coef[NN * 8];   // [v]: self, W, E, N, S, pad...
__device__ int4  g_nidx[NN];       // [v]: clamped W, E, N, S indices

// smem byte offsets (fp16 matrices, 136-elem = 272B rows)
#define PITCHB 272
#define OFF_B    0
#define OFF_A    34816
#define OFF_PAR  52224
#define OFF_RED  53760
#define SMEM_MMA 55808
// fused-out extras (Wout: 64 rows x 272B = 17408B)
#define OFF_WO   55808
#define OFF_BOUT 73216
#define SMEM_FUSED 73472

__device__ __forceinline__ uint32_t smem_u32(const void* p) {
    uint32_t a;
    asm("{ .reg .u64 t; cvta.to.shared.u64 t, %1; cvt.u32.u64 %0, t; }" : "=r"(a) : "l"(p));
    return a;
}
__device__ __forceinline__ float dinv_rc(int rp, int cp) {
    int d = 1 + (rp > 0) + (rp < GH - 1) + (cp > 0) + (cp < GW - 1);
    return rsqrtf((float)d);
}
__device__ __forceinline__ float f4get(const float4& v, int i) {
    return i == 0 ? v.x : i == 1 ? v.y : i == 2 ? v.z : v.w;
}
__device__ __forceinline__ void ldsm4(uint32_t addr, uint32_t& r0, uint32_t& r1,
                                      uint32_t& r2, uint32_t& r3) {
    asm volatile("ldmatrix.sync.aligned.m8n8.x4.shared.b16 {%0,%1,%2,%3}, [%4];"
                 : "=r"(r0), "=r"(r1), "=r"(r2), "=r"(r3) : "r"(addr));
}
__device__ __forceinline__ void mma_f16(float* d, const uint32_t* a, const uint32_t* b) {
    asm volatile("mma.sync.aligned.m16n8k16.row.col.f32.f16.f16.f32 "
                 "{%0,%1,%2,%3}, {%4,%5,%6,%7}, {%8,%9}, {%0,%1,%2,%3};"
                 : "+f"(d[0]), "+f"(d[1]), "+f"(d[2]), "+f"(d[3])
                 : "r"(a[0]), "r"(a[1]), "r"(a[2]), "r"(a[3]), "r"(b[0]), "r"(b[1]));
}
__device__ __forceinline__ float2 h2f2(uint32_t h) {
    return __half22float2(*(__half2*)&h);
}

// ---------------------------------------------------------------------------
// init: stencil coef/nidx tables
// ---------------------------------------------------------------------------
__global__ void init_tables_kernel() {
    int v = threadIdx.x + blockIdx.x * 256;
    if (v < NN) {
        int r = v / GW, c = v - (v / GW) * GW;
        float dv = dinv_rc(r, c);
        float w = (c > 0)      ? dinv_rc(r, c - 1) : 0.0f;
        float e = (c < GW - 1) ? dinv_rc(r, c + 1) : 0.0f;
        float n = (r > 0)      ? dinv_rc(r - 1, c) : 0.0f;
        float s = (r < GH - 1) ? dinv_rc(r + 1, c) : 0.0f;
        float4* cf = (float4*)(g_coef + v * 8);
        cf[0] = make_float4(dv * dv, dv * w, dv * e, dv * n);
        cf[1] = make_float4(dv * s, 0.0f, 0.0f, 0.0f);
        g_nidx[v] = make_int4((c > 0) ? v - 1 : v, (c < GW - 1) ? v + 1 : v,
                              (r > 0) ? v - GW : v, (r < GH - 1) ? v + GW : v);
    }
}

// ---------------------------------------------------------------------------
// prep: transpose+permute+fp16-convert all weights ONCE into global arrays
// ---------------------------------------------------------------------------
__global__ void prep_weights_kernel(const float* __restrict__ Wg,
                                    const float* __restrict__ Wout) {
    int idx = threadIdx.x + blockIdx.x * 256;
    if (idx < 4 * HID * HID) {                 // Wg: [layer][k][l]
        int layer = idx >> 14;
        int k = (idx >> 7) & 127, l = idx & 127;
        int li = l & 31;
        int P = (l & 96) + ((li & 7) >> 1) * 8 + (li >> 3) * 2 + (l & 1);
        g_Wg16[layer][P * 136 + k] = __float2half_rn(Wg[idx]);
    } else if (idx < 4 * HID * HID + HID * OUTD) {   // Wout: [k][l]
        int j = idx - 4 * HID * HID;
        int k = j >> 6, l = j & 63;
        int li = l & 31;
        int P = (l & 32) + ((li & 7) >> 1) * 8 + (li >> 3) * 2 + (l & 1);
        g_Wout16[P * 136 + k] = __float2half_rn(Wout[j]);
    }
}

// ---------------------------------------------------------------------------
// x0 = relu(onehot(color)@Win + pr*Win[10] + pc*Win[11] + bin) -> fp16
// ---------------------------------------------------------------------------
__global__ __launch_bounds__(256) void encode_kernel(
    const int* __restrict__ grids, const float* __restrict__ Win,
    const float* __restrict__ bin)
{
    __shared__ float4 sW[12 * 32];
    __shared__ float4 sB[32];
    const int tid = threadIdx.x;
    for (int i = tid; i < 384; i += 256) sW[i] = ((const float4*)Win)[i];
    if (tid < 32) sB[tid] = ((const float4*)bin)[tid];
    __syncthreads();

    long long idx = (long long)blockIdx.x * 256 + tid;
    int cg = (int)(idx & 31);
    long long bn = idx >> 5;
    int n = (int)(bn % NN);
    int color = grids[bn];
    float pr = (float)(n / GW) * (1.0f / (GH - 1));
    float pc = (float)(n % GW) * (1.0f / (GW - 1));
    float4 wc = sW[color * 32 + cg];
    float4 wr = sW[10 * 32 + cg];
    float4 wp = sW[11 * 32 + cg];
    float4 bb = sB[cg];
    float4 o;
    o.x = fmaxf(fmaf(pc, wp.x, fmaf(pr, wr.x, wc.x + bb.x)), 0.0f);
    o.y = fmaxf(fmaf(pc, wp.y, fmaf(pr, wr.y, wc.y + bb.y)), 0.0f);
    o.z = fmaxf(fmaf(pc, wp.z, fmaf(pr, wr.z, wc.z + bb.z)), 0.0f);
    o.w = fmaxf(fmaf(pc, wp.w, fmaf(pr, wr.w, wc.w + bb.w)), 0.0f);
    __half2 h01 = __floats2half2_rn(o.x, o.y);
    __half2 h23 = __floats2half2_rn(o.z, o.w);
    ((uint2*)g_XH0)[idx] = make_uint2(*(uint32_t*)&h01, *(uint32_t*)&h23);
}

// ---------------------------------------------------------------------------
// Tensor-core GCN layer (single-pass fp16). CTA = (batch, quarter), 256 thr.
// Non-fused: 4 CTAs/SM (<=64 regs target); fused: 3 CTAs/SM (smem-capped).
// Warp tile 32x32; B staged by uint4 copy from pre-permuted global fp16.
// ---------------------------------------------------------------------------
template<bool FUSE_OUT>
__global__ __launch_bounds__(256, FUSE_OUT ? 3 : 4) void layer_mma_kernel(
    int layer, int flip,
    const float* __restrict__ bg,
    const float* __restrict__ gamma, const float* __restrict__ beta,
    const float* __restrict__ bout,
    float* __restrict__ out)
{
    extern __shared__ char smem[];
    const uint32_t sb = smem_u32(smem);
    float* sPar = (float*)(smem + OFF_PAR);   // bg[128], gamma[128], beta[128]
    float* sS   = (float*)(smem + OFF_RED);   // [64][4] sum partials
    float* sQ   = sS + 256;                   // [64][4] sumsq partials

    const int tid = threadIdx.x, warp = tid >> 5, lane = tid & 31;
    const int mw = warp >> 2, nw = warp & 3;
    const int b = blockIdx.x >> 2, quarter = blockIdx.x & 3;
    const int rowbase0 = quarter * 225;

    const __half* XinH  = flip ? g_XH1 : g_XH0;
    __half*       XoutH = flip ? g_XH0 : g_XH1;
    const __half* XbH  = XinH  + (size_t)b * NN * HID;
    __half*       XobH = XoutH + (size_t)b * NN * HID;

    // --- stage LN params ---
    if (tid < 128) {
        sPar[tid]       = bg[tid];
        sPar[128 + tid] = gamma[tid];
        sPar[256 + tid] = beta[tid];
    }

    // --- stage W: straight uint4 copy of pre-permuted fp16 (conflict-free) ---
    {
        const uint4* src = (const uint4*)g_Wg16[layer];
        uint4* dst = (uint4*)(smem + OFF_B);
        #pragma unroll
        for (int i = tid; i < 2176; i += 256) dst[i] = src[i];   // 128 rows
    }
    if constexpr (FUSE_OUT) {
        const uint4* src = (const uint4*)g_Wout16;
        uint4* dst = (uint4*)(smem + OFF_WO);
        #pragma unroll
        for (int i = tid; i < 1088; i += 256) dst[i] = src[i];   // 64 rows
        if (tid < 64) ((float*)(smem + OFF_BOUT))[tid] = bout[tid];
    }
    __syncthreads();

    // lane-dependent ldmatrix base offsets (GCN GEMM)
    const uint32_t aRow = (uint32_t)(mw * 32 + (lane & 15)) * PITCHB
                        + ((lane >> 4) & 1) * 16;
    const uint32_t aB0 = sb + OFF_A + aRow;
    const uint32_t aB1 = aB0 + 16 * PITCHB;
    uint32_t bOff[2];
    #pragma unroll
    for (int p = 0; p < 2; p++) {
        int n = nw * 32 + p * 16 + (lane & 7) + ((lane >> 4) & 1) * 8;
        bOff[p] = sb + OFF_B + (uint32_t)n * PITCHB + ((lane >> 3) & 1) * 16;
    }
    const int g = lane >> 2, tig = lane & 3;
    const int C0 = nw * 32 + tig * 8;   // this thread's 8 logical cols

    // out-phase offsets (FUSE_OUT only)
    uint32_t aB2 = 0, bOff2[2] = {0, 0};
    int mwO = 0, nwO = 0;
    if constexpr (FUSE_OUT) {
        mwO = warp >> 1; nwO = warp & 1;
        aB2 = sb + OFF_A + (uint32_t)(mwO * 16 + (lane & 15)) * PITCHB
            + ((lane >> 4) & 1) * 16;
        #pragma unroll
        for (int p = 0; p < 2; p++) {
            int n = nwO * 32 + p * 16 + (lane & 7) + ((lane >> 4) & 1) * 8;
            bOff2[p] = sb + OFF_WO + (uint32_t)n * PITCHB + ((lane >> 3) & 1) * 16;
        }
    }

    for (int t = 0; t < 4; t++) {
        const int base = rowbase0 + t * 64;
        const int nrows = min(64, 225 - t * 64);

        // --- stencil (table-driven, fp16 input) -> fp16 A ---
        #pragma unroll 4
        for (int s = 0; s < 8; s++) {
            int idx = tid + 256 * s;
            int r = idx >> 5, cg = idx & 31;
            uint32_t off = (uint32_t)r * PITCHB + (uint32_t)cg * 8;
            if (r < nrows) {
                int v = base + r;
                float4 cf = *(const float4*)(g_coef + v * 8);      // self,W,E,N
                float cfs = g_coef[v * 8 + 4];                     // S
                int4 ni = g_nidx[v];
                uint2 hs = *(const uint2*)(XbH + (size_t)v    * HID + cg * 4);
                uint2 hw = *(const uint2*)(XbH + (size_t)ni.x * HID + cg * 4);
                uint2 he = *(const uint2*)(XbH + (size_t)ni.y * HID + cg * 4);
                uint2 hn = *(const uint2*)(XbH + (size_t)ni.z * HID + cg * 4);
                uint2 ho = *(const uint2*)(XbH + (size_t)ni.w * HID + cg * 4);
                float2 s0 = h2f2(hs.x), s1 = h2f2(hs.y);
                float2 w0 = h2f2(hw.x), w1 = h2f2(hw.y);
                float2 e0 = h2f2(he.x), e1 = h2f2(he.y);
                float2 n0 = h2f2(hn.x), n1 = h2f2(hn.y);
                float2 o0 = h2f2(ho.x), o1 = h2f2(ho.y);
                float ax = cf.x * s0.x, ay = cf.x * s0.y;
                float az = cf.x * s1.x, aw = cf.x * s1.y;
                ax = fmaf(cf.y, w0.x, ax); ay = fmaf(cf.y, w0.y, ay);
                az = fmaf(cf.y, w1.x, az); aw = fmaf(cf.y, w1.y, aw);
                ax = fmaf(cf.z, e0.x, ax); ay = fmaf(cf.z, e0.y, ay);
                az = fmaf(cf.z, e1.x, az); aw = fmaf(cf.z, e1.y, aw);
                ax = fmaf(cf.w, n0.x, ax); ay = fmaf(cf.w, n0.y, ay);
                az = fmaf(cf.w, n1.x, az); aw = fmaf(cf.w, n1.y, aw);
                ax = fmaf(cfs, o0.x, ax); ay = fmaf(cfs, o0.y, ay);
                az = fmaf(cfs, o1.x, az); aw = fmaf(cfs, o1.y, aw);
                __half2 h01 = __floats2half2_rn(ax, ay);
                __half2 h23 = __floats2half2_rn(az, aw);
                *(uint2*)(smem + OFF_A + off) =
                    make_uint2(*(uint32_t*)&h01, *(uint32_t*)&h23);
            } else {
                *(uint2*)(smem + OFF_A + off) = make_uint2(0u, 0u);
            }
        }
        __syncthreads();

        // --- MMA mainloop: D = A @ B' (single fp16 pass, 32x32 warp tile) ---
        float acc[2][4][4];
        #pragma unroll
        for (int i = 0; i < 2; i++)
            #pragma unroll
            for (int nb = 0; nb < 4; nb++)
                #pragma unroll
                for (int j = 0; j < 4; j++) acc[i][nb][j] = 0.0f;

        #pragma unroll
        for (int ks = 0; ks < 8; ks++) {
            const uint32_t kb = (uint32_t)ks * 32;
            uint32_t a0[4], a1[4];
            ldsm4(aB0 + kb, a0[0], a0[1], a0[2], a0[3]);
            ldsm4(aB1 + kb, a1[0], a1[1], a1[2], a1[3]);
            uint32_t bh[4][2];
            #pragma unroll
            for (int p = 0; p < 2; p++) {
                ldsm4(bOff[p] + kb,
                      bh[2*p][0], bh[2*p][1], bh[2*p+1][0], bh[2*p+1][1]);
            }
            #pragma unroll
            for (int nb = 0; nb < 4; nb++) {
                mma_f16(acc[0][nb], a0, bh[nb]);
                mma_f16(acc[1][nb], a1, bh[nb]);
            }
        }

        // --- epilogue: bias add, LN partials (32 cols/warp), 4-way reduce ---
        float4 bi0 = *(float4*)(sPar + C0);
        float4 bi1 = *(float4*)(sPar + C0 + 4);
        #pragma unroll
        for (int i = 0; i < 2; i++) {
            #pragma unroll
            for (int h = 0; h < 2; h++) {
                int row = mw * 32 + i * 16 + g + 8 * h;
                float v0 = acc[i][0][2*h]   + bi0.x;
                float v1 = acc[i][0][2*h+1] + bi0.y;
                float v2 = acc[i][1][2*h]   + bi0.z;
                float v3 = acc[i][1][2*h+1] + bi0.w;
                float v4 = acc[i][2][2*h]   + bi1.x;
                float v5 = acc[i][2][2*h+1] + bi1.y;
                float v6 = acc[i][3][2*h]   + bi1.z;
                float v7 = acc[i][3][2*h+1] + bi1.w;
                acc[i][0][2*h] = v0; acc[i][0][2*h+1] = v1;
                acc[i][1][2*h] = v2; acc[i][1][2*h+1] = v3;
                acc[i][2][2*h] = v4; acc[i][2][2*h+1] = v5;
                acc[i][3][2*h] = v6; acc[i][3][2*h+1] = v7;
                float s = v0 + v1 + v2 + v3 + v4 + v5 + v6 + v7;
                float q = fmaf(v0, v0, fmaf(v1, v1, fmaf(v2, v2, v3 * v3)));
                q = fmaf(v4, v4, fmaf(v5, v5, fmaf(v6, v6, fmaf(v7, v7, q))));
                s += __shfl_xor_sync(0xffffffffu, s, 1);
                s += __shfl_xor_sync(0xffffffffu, s, 2);
                q += __shfl_xor_sync(0xffffffffu, q, 1);
                q += __shfl_xor_sync(0xffffffffu, q, 2);
                if (tig == 0) { sS[row * 4 + nw] = s; sQ[row * 4 + nw] = q; }
            }
        }
        __syncthreads();

        // --- LN + relu + residual; dest = global fp16 x (or smem A if fused) ---
        #pragma unroll
        for (int i = 0; i < 2; i++) {
            #pragma unroll
            for (int h = 0; h < 2; h++) {
                int row = mw * 32 + i * 16 + g + 8 * h;
                float4 sv = *(float4*)(sS + row * 4);
                float4 qv = *(float4*)(sQ + row * 4);
                float s = (sv.x + sv.y) + (sv.z + sv.w);
                float q = (qv.x + qv.y) + (qv.z + qv.w);
                float mean = s * (1.0f / HID);
                float var  = q * (1.0f / HID) - mean * mean;
                float rstd = rsqrtf(var + 1e-5f);
                if (row < nrows) {   // quad-uniform
                    int v = base + row;
                    float4 gm0 = *(float4*)(sPar + 128 + C0);
                    float4 gm1 = *(float4*)(sPar + 128 + C0 + 4);
                    float4 bt0 = *(float4*)(sPar + 256 + C0);
                    float4 bt1 = *(float4*)(sPar + 256 + C0 + 4);
                    uint4 xh = *(const uint4*)(XbH + (size_t)v * HID + C0);
                    float2 xa = h2f2(xh.x), xb2 = h2f2(xh.y);
                    float2 xc = h2f2(xh.z), xd = h2f2(xh.w);
                    float o0 = fmaxf((acc[i][0][2*h]   - mean) * rstd * gm0.x + bt0.x, 0.0f) + xa.x;
                    float o1 = fmaxf((acc[i][0][2*h+1] - mean) * rstd * gm0.y + bt0.y, 0.0f) + xa.y;
                    float o2 = fmaxf((acc[i][1][2*h]   - mean) * rstd * gm0.z + bt0.z, 0.0f) + xb2.x;
                    float o3 = fmaxf((acc[i][1][2*h+1] - mean) * rstd * gm0.w + bt0.w, 0.0f) + xb2.y;
                    float o4 = fmaxf((acc[i][2][2*h]   - mean) * rstd * gm1.x + bt1.x, 0.0f) + xc.x;
                    float o5 = fmaxf((acc[i][2][2*h+1] - mean) * rstd * gm1.y + bt1.y, 0.0f) + xc.y;
                    float o6 = fmaxf((acc[i][3][2*h]   - mean) * rstd * gm1.z + bt1.z, 0.0f) + xd.x;
                    float o7 = fmaxf((acc[i][3][2*h+1] - mean) * rstd * gm1.w + bt1.w, 0.0f) + xd.y;
                    __half2 ha = __floats2half2_rn(o0, o1);
                    __half2 hb = __floats2half2_rn(o2, o3);
                    __half2 hc = __floats2half2_rn(o4, o5);
                    __half2 hd = __floats2half2_rn(o6, o7);
                    uint4 pk = make_uint4(*(uint32_t*)&ha, *(uint32_t*)&hb,
                                          *(uint32_t*)&hc, *(uint32_t*)&hd);
                    if constexpr (FUSE_OUT) {
                        *(uint4*)(smem + OFF_A + (uint32_t)row * PITCHB
                                  + (uint32_t)C0 * 2) = pk;
                    } else {
                        *(uint4*)(XobH + (size_t)v * HID + C0) = pk;
                    }
                } else {
                    if constexpr (FUSE_OUT) {
                        *(uint4*)(smem + OFF_A + (uint32_t)row * PITCHB
                                  + (uint32_t)C0 * 2) = make_uint4(0u, 0u, 0u, 0u);
                    }
                }
            }
        }
        __syncthreads();

        // --- fused out GEMM: out[tile] = x_new @ Wout + bout ---
        if constexpr (FUSE_OUT) {
            float acc2[4][4];
            #pragma unroll
            for (int nb = 0; nb < 4; nb++)
                #pragma unroll
                for (int j = 0; j < 4; j++) acc2[nb][j] = 0.0f;

            #pragma unroll
            for (int ks = 0; ks < 8; ks++) {
                const uint32_t kb = (uint32_t)ks * 32;
                uint32_t a[4];
                ldsm4(aB2 + kb, a[0], a[1], a[2], a[3]);
                uint32_t bh[4][2];
                #pragma unroll
                for (int p = 0; p < 2; p++) {
                    ldsm4(bOff2[p] + kb,
                          bh[2*p][0], bh[2*p][1], bh[2*p+1][0], bh[2*p+1][1]);
                }
                #pragma unroll
                for (int nb = 0; nb < 4; nb++)
                    mma_f16(acc2[nb], a, bh[nb]);
            }

            const float* sBout = (const float*)(smem + OFF_BOUT);
            #pragma unroll
            for (int h = 0; h < 2; h++) {
                int row = mwO * 16 + g + 8 * h;
                if (row < nrows) {   // quad-uniform
                    float* op = out + ((size_t)b * NN + base + row) * OUTD;
                    #pragma unroll
                    for (int j = 0; j < 2; j++) {
                        int C = nwO * 32 + tig * 8 + 4 * j;
                        float4 bo = *(const float4*)(sBout + C);
                        float4 o;
                        o.x = acc2[2*j][2*h]     + bo.x;
                        o.y = acc2[2*j][2*h+1]   + bo.y;
                        o.z = acc2[2*j+1][2*h]   + bo.z;
                        o.w = acc2[2*j+1][2*h+1] + bo.w;
                        *(float4*)(op + C) = o;
                    }
                }
            }
            __syncthreads();   // OFF_A reads done before next tile's stencil
        }
    }
}

// ---------------------------------------------------------------------------
extern "C" void kernel_launch(void* const* d_in, const int* in_sizes, int n_in,
                              void* d_out, int out_size) {
    const int*   grids = (const int*)d_in[0];
    // d_in[1] = edge_index: fixed 30x30 4-connected grid; precomputed tables.
    const float* Win   = (const float*)d_in[2];
    const float* bin   = (const float*)d_in[3];
    const float* Wg    = (const float*)d_in[4];
    const float* bg    = (const float*)d_in[5];
    const float* gamma = (const float*)d_in[6];
    const float* beta  = (const float*)d_in[7];
    const float* Wout  = (const float*)d_in[8];
    const float* bout  = (const float*)d_in[9];
    float* out = (float*)d_out;
    (void)in_sizes; (void)n_in; (void)out_size;

    cudaFuncSetAttribute((const void*)layer_mma_kernel<false>,
                         cudaFuncAttributeMaxDynamicSharedMemorySize, SMEM_MMA);
    cudaFuncSetAttribute((const void*)layer_mma_kernel<true>,
                         cudaFuncAttributeMaxDynamicSharedMemorySize, SMEM_FUSED);

    init_tables_kernel<<<4, 256>>>();
    prep_weights_kernel<<<(4 * HID * HID + HID * OUTD + 255) / 256, 256>>>(Wg, Wout);
    encode_kernel<<<(NB * NN * 32) / 256, 256>>>(grids, Win, bin);
    for (int i = 0; i < 3; i++) {
        layer_mma_kernel<false><<<NB * 4, 256, SMEM_MMA>>>(
            i, i & 1, bg + i * HID, gamma + i * HID, beta + i * HID,
            nullptr, nullptr);
    }
    layer_mma_kernel<true><<<NB * 4, 256, SMEM_FUSED>>>(
        3, 1, bg + 3 * HID, gamma + 3 * HID, beta + 3 * HID, bout, out);
}

// round 17
// speedup vs baseline: 6.4667x; 1.1374x over previous
#include <cuda_runtime.h>
#include <cuda_fp16.h>
#include <cstdint>

#define NB   512
#define GH   30
#define GW   30
#define NN   900
#define HID  128
#define OUTD 64
#define TROWS 60                 // 900 = 15 * 60, uniform tiles
#define TILES 15
#define ITEMS (NB * TILES)       // 7680
#define GRID_L  592              // 148 SMs x 4 CTAs (all-resident)
#define IPC_L   ((ITEMS + GRID_L - 1) / GRID_L)    // 13
#define GRID_F  444              // 148 SMs x 3 CTAs (fused, smem-capped)
#define IPC_F   ((ITEMS + GRID_F - 1) / GRID_F)    // 18

// Activations live ONLY in fp16 (ping-pong); LN/residual math fp32 in registers.
__device__ __half g_XH0[(size_t)NB * NN * HID];
__device__ __half g_XH1[(size_t)NB * NN * HID];
// Pre-permuted fp16 weights in the exact smem layout ([P][136] halves, 272B pitch)
__device__ __align__(16) __half g_Wg16[4][128 * 136];   // 2176 uint4 each
__device__ __align__(16) __half g_Wout16[64 * 136];     // 1088 uint4
// Precomputed graph tables (fixed 30x30 4-connected grid + self loops)
__device__ float g_coef[NN * 8];   // [v]: self, W, E, N, S, pad...
__device__ int4  g_nidx[NN];       // [v]: clamped W, E, N, S indices

// smem byte offsets (fp16 matrices, 136-elem = 272B rows)
#define PITCHB 272
#define OFF_B    0
#define OFF_A    34816
#define OFF_PAR  52224
#define OFF_RED  53760
#define SMEM_MMA 55808
// fused-out extras (Wout: 64 rows x 272B = 17408B)
#define OFF_WO   55808
#define OFF_BOUT 73216
#define SMEM_FUSED 73472

__device__ __forceinline__ uint32_t smem_u32(const void* p) {
    uint32_t a;
    asm("{ .reg .u64 t; cvta.to.shared.u64 t, %1; cvt.u32.u64 %0, t; }" : "=r"(a) : "l"(p));
    return a;
}
__device__ __forceinline__ float dinv_rc(int rp, int cp) {
    int d = 1 + (rp > 0) + (rp < GH - 1) + (cp > 0) + (cp < GW - 1);
    return rsqrtf((float)d);
}
__device__ __forceinline__ float f4get(const float4& v, int i) {
    return i == 0 ? v.x : i == 1 ? v.y : i == 2 ? v.z : v.w;
}
__device__ __forceinline__ void ldsm4(uint32_t addr, uint32_t& r0, uint32_t& r1,
                                      uint32_t& r2, uint32_t& r3) {
    asm volatile("ldmatrix.sync.aligned.m8n8.x4.shared.b16 {%0,%1,%2,%3}, [%4];"
                 : "=r"(r0), "=r"(r1), "=r"(r2), "=r"(r3) : "r"(addr));
}
__device__ __forceinline__ void mma_f16(float* d, const uint32_t* a, const uint32_t* b) {
    asm volatile("mma.sync.aligned.m16n8k16.row.col.f32.f16.f16.f32 "
                 "{%0,%1,%2,%3}, {%4,%5,%6,%7}, {%8,%9}, {%0,%1,%2,%3};"
                 : "+f"(d[0]), "+f"(d[1]), "+f"(d[2]), "+f"(d[3])
                 : "r"(a[0]), "r"(a[1]), "r"(a[2]), "r"(a[3]), "r"(b[0]), "r"(b[1]));
}
__device__ __forceinline__ float2 h2f2(uint32_t h) {
    return __half22float2(*(__half2*)&h);
}

// ---------------------------------------------------------------------------
// init: stencil coef/nidx tables
// ---------------------------------------------------------------------------
__global__ void init_tables_kernel() {
    int v = threadIdx.x + blockIdx.x * 256;
    if (v < NN) {
        int r = v / GW, c = v - (v / GW) * GW;
        float dv = dinv_rc(r, c);
        float w = (c > 0)      ? dinv_rc(r, c - 1) : 0.0f;
        float e = (c < GW - 1) ? dinv_rc(r, c + 1) : 0.0f;
        float n = (r > 0)      ? dinv_rc(r - 1, c) : 0.0f;
        float s = (r < GH - 1) ? dinv_rc(r + 1, c) : 0.0f;
        float4* cf = (float4*)(g_coef + v * 8);
        cf[0] = make_float4(dv * dv, dv * w, dv * e, dv * n);
        cf[1] = make_float4(dv * s, 0.0f, 0.0f, 0.0f);
        g_nidx[v] = make_int4((c > 0) ? v - 1 : v, (c < GW - 1) ? v + 1 : v,
                              (r > 0) ? v - GW : v, (r < GH - 1) ? v + GW : v);
    }
}

// ---------------------------------------------------------------------------
// prep: transpose+permute+fp16-convert all weights ONCE into global arrays
// ---------------------------------------------------------------------------
__global__ void prep_weights_kernel(const float* __restrict__ Wg,
                                    const float* __restrict__ Wout) {
    int idx = threadIdx.x + blockIdx.x * 256;
    if (idx < 4 * HID * HID) {                 // Wg: [layer][k][l]
        int layer = idx >> 14;
        int k = (idx >> 7) & 127, l = idx & 127;
        int li = l & 31;
        int P = (l & 96) + ((li & 7) >> 1) * 8 + (li >> 3) * 2 + (l & 1);
        g_Wg16[layer][P * 136 + k] = __float2half_rn(Wg[idx]);
    } else if (idx < 4 * HID * HID + HID * OUTD) {   // Wout: [k][l]
        int j = idx - 4 * HID * HID;
        int k = j >> 6, l = j & 63;
        int li = l & 31;
        int P = (l & 32) + ((li & 7) >> 1) * 8 + (li >> 3) * 2 + (l & 1);
        g_Wout16[P * 136 + k] = __float2half_rn(Wout[j]);
    }
}

// ---------------------------------------------------------------------------
// x0 = relu(onehot(color)@Win + pr*Win[10] + pc*Win[11] + bin) -> fp16
// ---------------------------------------------------------------------------
__global__ __launch_bounds__(256) void encode_kernel(
    const int* __restrict__ grids, const float* __restrict__ Win,
    const float* __restrict__ bin)
{
    __shared__ float4 sW[12 * 32];
    __shared__ float4 sB[32];
    const int tid = threadIdx.x;
    for (int i = tid; i < 384; i += 256) sW[i] = ((const float4*)Win)[i];
    if (tid < 32) sB[tid] = ((const float4*)bin)[tid];
    __syncthreads();

    long long idx = (long long)blockIdx.x * 256 + tid;
    int cg = (int)(idx & 31);
    long long bn = idx >> 5;
    int n = (int)(bn % NN);
    int color = grids[bn];
    float pr = (float)(n / GW) * (1.0f / (GH - 1));
    float pc = (float)(n % GW) * (1.0f / (GW - 1));
    float4 wc = sW[color * 32 + cg];
    float4 wr = sW[10 * 32 + cg];
    float4 wp = sW[11 * 32 + cg];
    float4 bb = sB[cg];
    float4 o;
    o.x = fmaxf(fmaf(pc, wp.x, fmaf(pr, wr.x, wc.x + bb.x)), 0.0f);
    o.y = fmaxf(fmaf(pc, wp.y, fmaf(pr, wr.y, wc.y + bb.y)), 0.0f);
    o.z = fmaxf(fmaf(pc, wp.z, fmaf(pr, wr.z, wc.z + bb.z)), 0.0f);
    o.w = fmaxf(fmaf(pc, wp.w, fmaf(pr, wr.w, wc.w + bb.w)), 0.0f);
    __half2 h01 = __floats2half2_rn(o.x, o.y);
    __half2 h23 = __floats2half2_rn(o.z, o.w);
    ((uint2*)g_XH0)[idx] = make_uint2(*(uint32_t*)&h01, *(uint32_t*)&h23);
}

// ---------------------------------------------------------------------------
// Persistent tensor-core GCN layer (single-pass fp16).
// grid = GRID_L/GRID_F persistent CTAs; each stages W once, then loops over
// blocked-contiguous work items. Item = (batch, 60-row tile); 900 = 15*60 so
// all tiles are uniform (rows 60..63 zero-padded in smem A).
// Warp tile 32x32; FUSE_OUT fuses the out GEMM.
// ---------------------------------------------------------------------------
template<bool FUSE_OUT>
__global__ __launch_bounds__(256, FUSE_OUT ? 3 : 4) void layer_mma_kernel(
    int layer, int flip,
    const float* __restrict__ bg,
    const float* __restrict__ gamma, const float* __restrict__ beta,
    const float* __restrict__ bout,
    float* __restrict__ out)
{
    extern __shared__ char smem[];
    const uint32_t sb = smem_u32(smem);
    float* sPar = (float*)(smem + OFF_PAR);   // bg[128], gamma[128], beta[128]
    float* sS   = (float*)(smem + OFF_RED);   // [64][4] sum partials
    float* sQ   = sS + 256;                   // [64][4] sumsq partials

    const int tid = threadIdx.x, warp = tid >> 5, lane = tid & 31;
    const int mw = warp >> 2, nw = warp & 3;

    const __half* XinH  = flip ? g_XH1 : g_XH0;
    __half*       XoutH = flip ? g_XH0 : g_XH1;

    // --- stage LN params ---
    if (tid < 128) {
        sPar[tid]       = bg[tid];
        sPar[128 + tid] = gamma[tid];
        sPar[256 + tid] = beta[tid];
    }

    // --- stage W once: uint4 copy of pre-permuted fp16 (conflict-free) ---
    {
        const uint4* src = (const uint4*)g_Wg16[layer];
        uint4* dst = (uint4*)(smem + OFF_B);
        #pragma unroll
        for (int i = tid; i < 2176; i += 256) dst[i] = src[i];   // 128 rows
    }
    if constexpr (FUSE_OUT) {
        const uint4* src = (const uint4*)g_Wout16;
        uint4* dst = (uint4*)(smem + OFF_WO);
        #pragma unroll
        for (int i = tid; i < 1088; i += 256) dst[i] = src[i];   // 64 rows
        if (tid < 64) ((float*)(smem + OFF_BOUT))[tid] = bout[tid];
    }
    __syncthreads();

    // lane-dependent ldmatrix base offsets (GCN GEMM)
    const uint32_t aRow = (uint32_t)(mw * 32 + (lane & 15)) * PITCHB
                        + ((lane >> 4) & 1) * 16;
    const uint32_t aB0 = sb + OFF_A + aRow;
    const uint32_t aB1 = aB0 + 16 * PITCHB;
    uint32_t bOff[2];
    #pragma unroll
    for (int p = 0; p < 2; p++) {
        int n = nw * 32 + p * 16 + (lane & 7) + ((lane >> 4) & 1) * 8;
        bOff[p] = sb + OFF_B + (uint32_t)n * PITCHB + ((lane >> 3) & 1) * 16;
    }
    const int g = lane >> 2, tig = lane & 3;
    const int C0 = nw * 32 + tig * 8;   // this thread's 8 logical cols

    // out-phase offsets (FUSE_OUT only)
    uint32_t aB2 = 0, bOff2[2] = {0, 0};
    int mwO = 0, nwO = 0;
    if constexpr (FUSE_OUT) {
        mwO = warp >> 1; nwO = warp & 1;
        aB2 = sb + OFF_A + (uint32_t)(mwO * 16 + (lane & 15)) * PITCHB
            + ((lane >> 4) & 1) * 16;
        #pragma unroll
        for (int p = 0; p < 2; p++) {
            int n = nwO * 32 + p * 16 + (lane & 7) + ((lane >> 4) & 1) * 8;
            bOff2[p] = sb + OFF_WO + (uint32_t)n * PITCHB + ((lane >> 3) & 1) * 16;
        }
    }

    const int IPC = FUSE_OUT ? IPC_F : IPC_L;
    const int it0 = blockIdx.x * IPC;
    const int it1 = min(it0 + IPC, ITEMS);

    for (int item = it0; item < it1; item++) {
        const int b = item / TILES;
        const int base = (item - b * TILES) * TROWS;
        const __half* XbH  = XinH  + (size_t)b * NN * HID;
        __half*       XobH = XoutH + (size_t)b * NN * HID;

        // --- stencil (table-driven, fp16 input) -> fp16 A (pad rows 60-63) ---
        #pragma unroll 4
        for (int s = 0; s < 8; s++) {
            int idx = tid + 256 * s;
            int r = idx >> 5, cg = idx & 31;
            uint32_t off = (uint32_t)r * PITCHB + (uint32_t)cg * 8;
            if (r < TROWS) {
                int v = base + r;
                float4 cf = *(const float4*)(g_coef + v * 8);      // self,W,E,N
                float cfs = g_coef[v * 8 + 4];                     // S
                int4 ni = g_nidx[v];
                uint2 hs = *(const uint2*)(XbH + (size_t)v    * HID + cg * 4);
                uint2 hw = *(const uint2*)(XbH + (size_t)ni.x * HID + cg * 4);
                uint2 he = *(const uint2*)(XbH + (size_t)ni.y * HID + cg * 4);
                uint2 hn = *(const uint2*)(XbH + (size_t)ni.z * HID + cg * 4);
                uint2 ho = *(const uint2*)(XbH + (size_t)ni.w * HID + cg * 4);
                float2 s0 = h2f2(hs.x), s1 = h2f2(hs.y);
                float2 w0 = h2f2(hw.x), w1 = h2f2(hw.y);
                float2 e0 = h2f2(he.x), e1 = h2f2(he.y);
                float2 n0 = h2f2(hn.x), n1 = h2f2(hn.y);
                float2 o0 = h2f2(ho.x), o1 = h2f2(ho.y);
                float ax = cf.x * s0.x, ay = cf.x * s0.y;
                float az = cf.x * s1.x, aw = cf.x * s1.y;
                ax = fmaf(cf.y, w0.x, ax); ay = fmaf(cf.y, w0.y, ay);
                az = fmaf(cf.y, w1.x, az); aw = fmaf(cf.y, w1.y, aw);
                ax = fmaf(cf.z, e0.x, ax); ay = fmaf(cf.z, e0.y, ay);
                az = fmaf(cf.z, e1.x, az); aw = fmaf(cf.z, e1.y, aw);
                ax = fmaf(cf.w, n0.x, ax); ay = fmaf(cf.w, n0.y, ay);
                az = fmaf(cf.w, n1.x, az); aw = fmaf(cf.w, n1.y, aw);
                ax = fmaf(cfs, o0.x, ax); ay = fmaf(cfs, o0.y, ay);
                az = fmaf(cfs, o1.x, az); aw = fmaf(cfs, o1.y, aw);
                __half2 h01 = __floats2half2_rn(ax, ay);
                __half2 h23 = __floats2half2_rn(az, aw);
                *(uint2*)(smem + OFF_A + off) =
                    make_uint2(*(uint32_t*)&h01, *(uint32_t*)&h23);
            } else {
                *(uint2*)(smem + OFF_A + off) = make_uint2(0u, 0u);
            }
        }
        __syncthreads();

        // --- MMA mainloop: D = A @ B' (single fp16 pass, 32x32 warp tile) ---
        float acc[2][4][4];
        #pragma unroll
        for (int i = 0; i < 2; i++)
            #pragma unroll
            for (int nb = 0; nb < 4; nb++)
                #pragma unroll
                for (int j = 0; j < 4; j++) acc[i][nb][j] = 0.0f;

        #pragma unroll
        for (int ks = 0; ks < 8; ks++) {
            const uint32_t kb = (uint32_t)ks * 32;
            uint32_t a0[4], a1[4];
            ldsm4(aB0 + kb, a0[0], a0[1], a0[2], a0[3]);
            ldsm4(aB1 + kb, a1[0], a1[1], a1[2], a1[3]);
            uint32_t bh[4][2];
            #pragma unroll
            for (int p = 0; p < 2; p++) {
                ldsm4(bOff[p] + kb,
                      bh[2*p][0], bh[2*p][1], bh[2*p+1][0], bh[2*p+1][1]);
            }
            #pragma unroll
            for (int nb = 0; nb < 4; nb++) {
                mma_f16(acc[0][nb], a0, bh[nb]);
                mma_f16(acc[1][nb], a1, bh[nb]);
            }
        }

        // --- epilogue: bias add, LN partials (32 cols/warp), 4-way reduce ---
        float4 bi0 = *(float4*)(sPar + C0);
        float4 bi1 = *(float4*)(sPar + C0 + 4);
        #pragma unroll
        for (int i = 0; i < 2; i++) {
            #pragma unroll
            for (int h = 0; h < 2; h++) {
                int row = mw * 32 + i * 16 + g + 8 * h;
                float v0 = acc[i][0][2*h]   + bi0.x;
                float v1 = acc[i][0][2*h+1] + bi0.y;
                float v2 = acc[i][1][2*h]   + bi0.z;
                float v3 = acc[i][1][2*h+1] + bi0.w;
                float v4 = acc[i][2][2*h]   + bi1.x;
                float v5 = acc[i][2][2*h+1] + bi1.y;
                float v6 = acc[i][3][2*h]   + bi1.z;
                float v7 = acc[i][3][2*h+1] + bi1.w;
                acc[i][0][2*h] = v0; acc[i][0][2*h+1] = v1;
                acc[i][1][2*h] = v2; acc[i][1][2*h+1] = v3;
                acc[i][2][2*h] = v4; acc[i][2][2*h+1] = v5;
                acc[i][3][2*h] = v6; acc[i][3][2*h+1] = v7;
                float s = v0 + v1 + v2 + v3 + v4 + v5 + v6 + v7;
                float q = fmaf(v0, v0, fmaf(v1, v1, fmaf(v2, v2, v3 * v3)));
                q = fmaf(v4, v4, fmaf(v5, v5, fmaf(v6, v6, fmaf(v7, v7, q))));
                s += __shfl_xor_sync(0xffffffffu, s, 1);
                s += __shfl_xor_sync(0xffffffffu, s, 2);
                q += __shfl_xor_sync(0xffffffffu, q, 1);
                q += __shfl_xor_sync(0xffffffffu, q, 2);
                if (tig == 0) { sS[row * 4 + nw] = s; sQ[row * 4 + nw] = q; }
            }
        }
        __syncthreads();

        // --- LN + relu + residual; dest = global fp16 x (or smem A if fused) ---
        #pragma unroll
        for (int i = 0; i < 2; i++) {
            #pragma unroll
            for (int h = 0; h < 2; h++) {
                int row = mw * 32 + i * 16 + g + 8 * h;
                float4 sv = *(float4*)(sS + row * 4);
                float4 qv = *(float4*)(sQ + row * 4);
                float s = (sv.x + sv.y) + (sv.z + sv.w);
                float q = (qv.x + qv.y) + (qv.z + qv.w);
                float mean = s * (1.0f / HID);
                float var  = q * (1.0f / HID) - mean * mean;
                float rstd = rsqrtf(var + 1e-5f);
                if (row < TROWS) {   // quad-uniform
                    int v = base + row;
                    float4 gm0 = *(float4*)(sPar + 128 + C0);
                    float4 gm1 = *(float4*)(sPar + 128 + C0 + 4);
                    float4 bt0 = *(float4*)(sPar + 256 + C0);
                    float4 bt1 = *(float4*)(sPar + 256 + C0 + 4);
                    uint4 xh = *(const uint4*)(XbH + (size_t)v * HID + C0);
                    float2 xa = h2f2(xh.x), xb2 = h2f2(xh.y);
                    float2 xc = h2f2(xh.z), xd = h2f2(xh.w);
                    float o0 = fmaxf((acc[i][0][2*h]   - mean) * rstd * gm0.x + bt0.x, 0.0f) + xa.x;
                    float o1 = fmaxf((acc[i][0][2*h+1] - mean) * rstd * gm0.y + bt0.y, 0.0f) + xa.y;
                    float o2 = fmaxf((acc[i][1][2*h]   - mean) * rstd * gm0.z + bt0.z, 0.0f) + xb2.x;
                    float o3 = fmaxf((acc[i][1][2*h+1] - mean) * rstd * gm0.w + bt0.w, 0.0f) + xb2.y;
                    float o4 = fmaxf((acc[i][2][2*h]   - mean) * rstd * gm1.x + bt1.x, 0.0f) + xc.x;
                    float o5 = fmaxf((acc[i][2][2*h+1] - mean) * rstd * gm1.y + bt1.y, 0.0f) + xc.y;
                    float o6 = fmaxf((acc[i][3][2*h]   - mean) * rstd * gm1.z + bt1.z, 0.0f) + xd.x;
                    float o7 = fmaxf((acc[i][3][2*h+1] - mean) * rstd * gm1.w + bt1.w, 0.0f) + xd.y;
                    __half2 ha = __floats2half2_rn(o0, o1);
                    __half2 hb = __floats2half2_rn(o2, o3);
                    __half2 hc = __floats2half2_rn(o4, o5);
                    __half2 hd = __floats2half2_rn(o6, o7);
                    uint4 pk = make_uint4(*(uint32_t*)&ha, *(uint32_t*)&hb,
                                          *(uint32_t*)&hc, *(uint32_t*)&hd);
                    if constexpr (FUSE_OUT) {
                        *(uint4*)(smem + OFF_A + (uint32_t)row * PITCHB
                                  + (uint32_t)C0 * 2) = pk;
                    } else {
                        *(uint4*)(XobH + (size_t)v * HID + C0) = pk;
                    }
                } else {
                    if constexpr (FUSE_OUT) {
                        *(uint4*)(smem + OFF_A + (uint32_t)row * PITCHB
                                  + (uint32_t)C0 * 2) = make_uint4(0u, 0u, 0u, 0u);
                    }
                }
            }
        }
        __syncthreads();

        // --- fused out GEMM: out[tile] = x_new @ Wout + bout ---
        if constexpr (FUSE_OUT) {
            float acc2[4][4];
            #pragma unroll
            for (int nb = 0; nb < 4; nb++)
                #pragma unroll
                for (int j = 0; j < 4; j++) acc2[nb][j] = 0.0f;

            #pragma unroll
            for (int ks = 0; ks < 8; ks++) {
                const uint32_t kb = (uint32_t)ks * 32;
                uint32_t a[4];
                ldsm4(aB2 + kb, a[0], a[1], a[2], a[3]);
                uint32_t bh[4][2];
                #pragma unroll
                for (int p = 0; p < 2; p++) {
                    ldsm4(bOff2[p] + kb,
                          bh[2*p][0], bh[2*p][1], bh[2*p+1][0], bh[2*p+1][1]);
                }
                #pragma unroll
                for (int nb = 0; nb < 4; nb++)
                    mma_f16(acc2[nb], a, bh[nb]);
            }

            const float* sBout = (const float*)(smem + OFF_BOUT);
            #pragma unroll
            for (int h = 0; h < 2; h++) {
                int row = mwO * 16 + g + 8 * h;
                if (row < TROWS) {   // quad-uniform
                    float* op = out + ((size_t)b * NN + base + row) * OUTD;
                    #pragma unroll
                    for (int j = 0; j < 2; j++) {
                        int C = nwO * 32 + tig * 8 + 4 * j;
                        float4 bo = *(const float4*)(sBout + C);
                        float4 o;
                        o.x = acc2[2*j][2*h]     + bo.x;
                        o.y = acc2[2*j][2*h+1]   + bo.y;
                        o.z = acc2[2*j+1][2*h]   + bo.z;
                        o.w = acc2[2*j+1][2*h+1] + bo.w;
                        *(float4*)(op + C) = o;
                    }
                }
            }
            __syncthreads();   // OFF_A reads done before next item's stencil
        }
    }
}

// ---------------------------------------------------------------------------
extern "C" void kernel_launch(void* const* d_in, const int* in_sizes, int n_in,
                              void* d_out, int out_size) {
    const int*   grids = (const int*)d_in[0];
    // d_in[1] = edge_index: fixed 30x30 4-connected grid; precomputed tables.
    const float* Win   = (const float*)d_in[2];
    const float* bin   = (const float*)d_in[3];
    const float* Wg    = (const float*)d_in[4];
    const float* bg    = (const float*)d_in[5];
    const float* gamma = (const float*)d_in[6];
    const float* beta  = (const float*)d_in[7];
    const float* Wout  = (const float*)d_in[8];
    const float* bout  = (const float*)d_in[9];
    float* out = (float*)d_out;
    (void)in_sizes; (void)n_in; (void)out_size;

    cudaFuncSetAttribute((const void*)layer_mma_kernel<false>,
                         cudaFuncAttributeMaxDynamicSharedMemorySize, SMEM_MMA);
    cudaFuncSetAttribute((const void*)layer_mma_kernel<true>,
                         cudaFuncAttributeMaxDynamicSharedMemorySize, SMEM_FUSED);

    init_tables_kernel<<<4, 256>>>();
    prep_weights_kernel<<<(4 * HID * HID + HID * OUTD + 255) / 256, 256>>>(Wg, Wout);
    encode_kernel<<<(NB * NN * 32) / 256, 256>>>(grids, Win, bin);
    for (int i = 0; i < 3; i++) {
        layer_mma_kernel<false><<<GRID_L, 256, SMEM_MMA>>>(
            i, i & 1, bg + i * HID, gamma + i * HID, beta + i * HID,
            nullptr, nullptr);
    }
    layer_mma_kernel<true><<<GRID_F, 256, SMEM_FUSED>>>(
        3, 1, bg + 3 * HID, gamma + 3 * HID, beta + 3 * HID, bout, out);
}